// round 1
// baseline (speedup 1.0000x reference)
#include <cuda_runtime.h>
#include <math.h>

#define Bdim 2
#define NHdim 4
#define Tdim 1024
#define Ndim 8192
#define Ddim 256
#define BHdim (Bdim * NHdim)

// Scratch (no cudaMalloc allowed)
static __device__ float g_QR[67108864];   // [BH, T, N] RoPE'd Q, 256 MB
static __device__ float g_gate[BHdim * Tdim];
static __device__ float g_S_fallback[8388608]; // scores scratch if d_out too small

// ---------------------------------------------------------------------------
// RoPE: QR = rope(Q). One thread per (even,odd) pair.
// ---------------------------------------------------------------------------
__global__ void rope_kernel(const float* __restrict__ Q) {
    size_t idx = (size_t)blockIdx.x * blockDim.x + threadIdx.x;
    const size_t NP = (size_t)BHdim * Tdim * (Ndim / 2);
    if (idx >= NP) return;
    int p = (int)(idx % (Ndim / 2));
    int t = (int)((idx / (Ndim / 2)) % Tdim);
    // freq = THETA^(-q/N) / (2*pi), THETA = 2^16, q = 2p
    float q = 2.0f * (float)p;
    float freq = exp2f(-16.0f * q * (1.0f / (float)Ndim)) * 0.15915494309189535f;
    float ph = (float)t * freq;
    ph = (ph - floorf(ph)) * 6.283185307179586f;
    float s, c;
    sincosf(ph, &s, &c);
    float2 v = ((const float2*)Q)[idx];
    float2 r;
    r.x = v.x * c - v.y * s;
    r.y = v.y * c + v.x * s;
    ((float2*)g_QR)[idx] = r;
}

// ---------------------------------------------------------------------------
// Gate: g = 0.5 + 0.5*sigmoid(mean(traces, axis=-1)). One warp per row.
// ---------------------------------------------------------------------------
__global__ void gate_kernel(const float* __restrict__ traces) {
    int row = blockIdx.x;
    const float* pr = traces + (size_t)row * Ddim;
    float sum = 0.f;
    for (int i = threadIdx.x; i < Ddim; i += 32) sum += pr[i];
#pragma unroll
    for (int o = 16; o; o >>= 1) sum += __shfl_xor_sync(0xffffffffu, sum, o);
    if (threadIdx.x == 0) {
        float m = sum * (1.0f / (float)Ddim);
        float sig = 1.0f / (1.0f + expf(-m));
        g_gate[row] = 0.5f + 0.5f * sig;
    }
}

// ---------------------------------------------------------------------------
// GEMM1: scores = tril(QR @ QR^T, -1) * (1 + stdp) * gate[t]
// 128x128 tile, BK=8, 256 threads, 8x8 microtile. Upper blocks: zero-fill only.
// ---------------------------------------------------------------------------
__global__ __launch_bounds__(256) void scores_kernel(
    float* __restrict__ Sc, const float* __restrict__ stdp_scale) {
    const int bh = blockIdx.z;
    const int bt = blockIdx.y;  // t block
    const int bs = blockIdx.x;  // s block
    float* Sbase = Sc + (size_t)bh * Tdim * Tdim;

    if (bs > bt) {  // strictly upper block: all zero
        const int r0 = bt * 128, c0 = bs * 128;
        float4 z = make_float4(0.f, 0.f, 0.f, 0.f);
        for (int i = threadIdx.x; i < 128 * 32; i += 256) {
            int r = i >> 5;
            int c = (i & 31) << 2;
            *(float4*)(Sbase + (size_t)(r0 + r) * Tdim + c0 + c) = z;
        }
        return;
    }

    __shared__ float As[8][128];
    __shared__ float Bs[8][128];
    const float* Abase = g_QR + ((size_t)bh * Tdim + bt * 128) * Ndim;
    const float* Bbase = g_QR + ((size_t)bh * Tdim + bs * 128) * Ndim;

    const int tid = threadIdx.x;
    const int tx = tid & 15;   // s-tile group
    const int ty = tid >> 4;   // t-tile group
    const int lr = tid >> 1;   // load row 0..127
    const int lc = (tid & 1) << 2;  // load col {0,4}

    float acc[8][8];
#pragma unroll
    for (int i = 0; i < 8; i++)
#pragma unroll
        for (int j = 0; j < 8; j++) acc[i][j] = 0.f;

    const float* Aptr = Abase + (size_t)lr * Ndim + lc;
    const float* Bptr = Bbase + (size_t)lr * Ndim + lc;

    for (int k0 = 0; k0 < Ndim; k0 += 8) {
        float4 a = *(const float4*)(Aptr + k0);
        float4 b = *(const float4*)(Bptr + k0);
        __syncthreads();
        As[lc + 0][lr] = a.x; As[lc + 1][lr] = a.y;
        As[lc + 2][lr] = a.z; As[lc + 3][lr] = a.w;
        Bs[lc + 0][lr] = b.x; Bs[lc + 1][lr] = b.y;
        Bs[lc + 2][lr] = b.z; Bs[lc + 3][lr] = b.w;
        __syncthreads();
#pragma unroll
        for (int kk = 0; kk < 8; kk++) {
            float ar[8], br[8];
            *(float4*)(ar)     = *(const float4*)(&As[kk][ty * 8]);
            *(float4*)(ar + 4) = *(const float4*)(&As[kk][ty * 8 + 4]);
            *(float4*)(br)     = *(const float4*)(&Bs[kk][tx * 8]);
            *(float4*)(br + 4) = *(const float4*)(&Bs[kk][tx * 8 + 4]);
#pragma unroll
            for (int i = 0; i < 8; i++)
#pragma unroll
                for (int j = 0; j < 8; j++)
                    acc[i][j] = fmaf(ar[i], br[j], acc[i][j]);
        }
    }

    // Epilogue: (t>s) ? acc * (1 + scale*A_PLUS*exp(-(t-s)/20)) * gate[t] : 0
    const float ss = stdp_scale[0] * 0.01f;
    const int t0 = bt * 128 + ty * 8;
    const int s0 = bs * 128 + tx * 8;
#pragma unroll
    for (int i = 0; i < 8; i++) {
        int t = t0 + i;
        float gatef = g_gate[bh * Tdim + t];
        float out[8];
#pragma unroll
        for (int j = 0; j < 8; j++) {
            int s = s0 + j;
            float v = 0.f;
            if (t > s)
                v = acc[i][j] * (1.0f + ss * expf((float)(s - t) * 0.05f)) * gatef;
            out[j] = v;
        }
        float* rowp = Sbase + (size_t)t * Tdim + s0;
        *(float4*)(rowp)     = *(float4*)(out);
        *(float4*)(rowp + 4) = *(float4*)(out + 4);
    }
}

// ---------------------------------------------------------------------------
// GEMM2: output[bh,t,d] = sum_s scores[bh,t,s] * V[b,s,d]
// 64x64 tile, BK=16, 256 threads, 4x4 microtile. K-loop capped causally.
// ---------------------------------------------------------------------------
__global__ __launch_bounds__(256) void out_kernel(
    float* __restrict__ Out, const float* __restrict__ Sc,
    const float* __restrict__ V) {
    const int bh = blockIdx.z;
    const int b = bh / NHdim;
    const int bt = blockIdx.y;
    const int bd = blockIdx.x;
    const float* Srow = Sc + ((size_t)bh * Tdim + bt * 64) * Tdim;
    const float* Vb = V + (size_t)b * Tdim * Ddim + bd * 64;

    __shared__ float Ss[16][64];  // [k][t]
    __shared__ float Vs[16][64];  // [k][d]

    const int tid = threadIdx.x;
    const int tx = tid & 15;
    const int ty = tid >> 4;
    const int rs = tid >> 2;          // score load row 0..63
    const int cs = (tid & 3) << 2;    // score load col {0,4,8,12}
    const int rv = tid >> 4;          // V load row 0..15
    const int cv = (tid & 15) << 2;   // V load col

    float acc[4][4];
#pragma unroll
    for (int i = 0; i < 4; i++)
#pragma unroll
        for (int j = 0; j < 4; j++) acc[i][j] = 0.f;

    const int kend = (bt + 1) * 64;  // s < t <= bt*64+63, scores are zeroed above diag
    for (int k0 = 0; k0 < kend; k0 += 16) {
        float4 sv = *(const float4*)(Srow + (size_t)rs * Tdim + k0 + cs);
        float4 vv = *(const float4*)(Vb + (size_t)(k0 + rv) * Ddim + cv);
        __syncthreads();
        Ss[cs + 0][rs] = sv.x; Ss[cs + 1][rs] = sv.y;
        Ss[cs + 2][rs] = sv.z; Ss[cs + 3][rs] = sv.w;
        *(float4*)(&Vs[rv][cv]) = vv;
        __syncthreads();
#pragma unroll
        for (int kk = 0; kk < 16; kk++) {
            float a[4], bb[4];
            *(float4*)a  = *(const float4*)(&Ss[kk][ty * 4]);
            *(float4*)bb = *(const float4*)(&Vs[kk][tx * 4]);
#pragma unroll
            for (int i = 0; i < 4; i++)
#pragma unroll
                for (int j = 0; j < 4; j++)
                    acc[i][j] = fmaf(a[i], bb[j], acc[i][j]);
        }
    }
#pragma unroll
    for (int i = 0; i < 4; i++) {
        float* op = Out + ((size_t)bh * Tdim + bt * 64 + ty * 4 + i) * Ddim +
                    bd * 64 + tx * 4;
        *(float4*)op = make_float4(acc[i][0], acc[i][1], acc[i][2], acc[i][3]);
    }
}

// ---------------------------------------------------------------------------
extern "C" void kernel_launch(void* const* d_in, const int* in_sizes, int n_in,
                              void* d_out, int out_size) {
    const float* Q      = (const float*)d_in[0];
    const float* V      = (const float*)d_in[1];
    const float* traces = (const float*)d_in[2];
    const float* scale  = (const float*)d_in[3];
    float* out = (float*)d_out;

    const size_t OUT_ELEMS = (size_t)BHdim * Tdim * Ddim;        // 2,097,152
    const size_t SC_ELEMS  = (size_t)BHdim * Tdim * Tdim;        // 8,388,608

    // Output layout assumption: [output | scores] concatenated (tuple order).
    float* scores;
    if ((size_t)out_size >= OUT_ELEMS + SC_ELEMS) {
        scores = out + OUT_ELEMS;
    } else {
        void* p = nullptr;
        cudaGetSymbolAddress(&p, g_S_fallback);
        scores = (float*)p;
    }

    const size_t np = (size_t)BHdim * Tdim * (Ndim / 2);
    rope_kernel<<<(unsigned)((np + 255) / 256), 256>>>(Q);
    gate_kernel<<<BHdim * Tdim, 32>>>(traces);

    dim3 g1(Tdim / 128, Tdim / 128, BHdim);
    scores_kernel<<<g1, 256>>>(scores, scale);

    dim3 g2(Ddim / 64, Tdim / 64, BHdim);
    out_kernel<<<g2, 256>>>(out, scores, V);
}

// round 3
// speedup vs baseline: 2.6973x; 2.6973x over previous
#include <cuda_runtime.h>
#include <cuda_bf16.h>
#include <math.h>
#include <stdint.h>

#define Bdim 2
#define NHdim 4
#define Tdim 1024
#define Ndim 8192
#define Ddim 256
#define BHdim (Bdim * NHdim)

// Scratch (no cudaMalloc allowed)
static __device__ __nv_bfloat16 g_Qh[67108864];  // [BH, T, N] hi part, 128 MB
static __device__ __nv_bfloat16 g_Ql[67108864];  // [BH, T, N] lo part, 128 MB
static __device__ float g_gate[BHdim * Tdim];
static __device__ float g_S_fallback[8388608];

// ---------------------------------------------------------------------------
// PTX helpers (baseline sm_80+ ISA only: cp.async, ldmatrix, mma.sync)
// ---------------------------------------------------------------------------
__device__ __forceinline__ uint32_t smem_u32(const void* p) {
    uint32_t a;
    asm("{ .reg .u64 t; cvta.to.shared.u64 t, %1; cvt.u32.u64 %0, t; }"
        : "=r"(a) : "l"(p));
    return a;
}
__device__ __forceinline__ void cp16(uint32_t s, const void* g) {
    asm volatile("cp.async.cg.shared.global [%0], [%1], 16;" :: "r"(s), "l"(g)
                 : "memory");
}
__device__ __forceinline__ void ldm_x4(uint32_t& r0, uint32_t& r1,
                                       uint32_t& r2, uint32_t& r3,
                                       uint32_t addr) {
    asm volatile(
        "ldmatrix.sync.aligned.m8n8.x4.shared.b16 {%0,%1,%2,%3}, [%4];"
        : "=r"(r0), "=r"(r1), "=r"(r2), "=r"(r3) : "r"(addr));
}
__device__ __forceinline__ void mma16816(float* c, const uint32_t* a,
                                         uint32_t b0, uint32_t b1) {
    asm volatile(
        "mma.sync.aligned.m16n8k16.row.col.f32.bf16.bf16.f32 "
        "{%0,%1,%2,%3}, {%4,%5,%6,%7}, {%8,%9}, {%0,%1,%2,%3};"
        : "+f"(c[0]), "+f"(c[1]), "+f"(c[2]), "+f"(c[3])
        : "r"(a[0]), "r"(a[1]), "r"(a[2]), "r"(a[3]), "r"(b0), "r"(b1));
}
__device__ __forceinline__ uint32_t swz(uint32_t off) {
    return off ^ ((off >> 3) & 0x70);  // SW128 (Swizzle<3,4,3>)
}

// ---------------------------------------------------------------------------
// RoPE + bf16x3 split: Qh = bf16(rope(Q)), Ql = bf16(rope(Q) - Qh)
// ---------------------------------------------------------------------------
__global__ void rope_kernel(const float* __restrict__ Q) {
    size_t idx = (size_t)blockIdx.x * blockDim.x + threadIdx.x;
    const size_t NP = (size_t)BHdim * Tdim * (Ndim / 2);
    if (idx >= NP) return;
    int p = (int)(idx % (Ndim / 2));
    int t = (int)((idx / (Ndim / 2)) % Tdim);
    float q = 2.0f * (float)p;
    float freq = exp2f(-16.0f * q * (1.0f / (float)Ndim)) * 0.15915494309189535f;
    float ph = (float)t * freq;
    ph = (ph - floorf(ph)) * 6.283185307179586f;
    float s, c;
    sincosf(ph, &s, &c);
    float2 v = ((const float2*)Q)[idx];
    float rx = v.x * c - v.y * s;
    float ry = v.y * c + v.x * s;
    __nv_bfloat16 hx = __float2bfloat16(rx);
    __nv_bfloat16 hy = __float2bfloat16(ry);
    __nv_bfloat16 lx = __float2bfloat16(rx - __bfloat162float(hx));
    __nv_bfloat16 ly = __float2bfloat16(ry - __bfloat162float(hy));
    __nv_bfloat162 h; h.x = hx; h.y = hy;
    __nv_bfloat162 l; l.x = lx; l.y = ly;
    ((__nv_bfloat162*)g_Qh)[idx] = h;
    ((__nv_bfloat162*)g_Ql)[idx] = l;
}

// ---------------------------------------------------------------------------
// Gate
// ---------------------------------------------------------------------------
__global__ void gate_kernel(const float* __restrict__ traces) {
    int row = blockIdx.x;
    const float* pr = traces + (size_t)row * Ddim;
    float sum = 0.f;
    for (int i = threadIdx.x; i < Ddim; i += 32) sum += pr[i];
#pragma unroll
    for (int o = 16; o; o >>= 1) sum += __shfl_xor_sync(0xffffffffu, sum, o);
    if (threadIdx.x == 0) {
        float m = sum * (1.0f / (float)Ddim);
        float sig = 1.0f / (1.0f + expf(-m));
        g_gate[row] = 0.5f + 0.5f * sig;
    }
}

// ---------------------------------------------------------------------------
// GEMM1 via HMMA mma.sync bf16x3.
// 128x128 tile, BK=64, 8 warps (2x4), warp tile 64x32, 4-stage cp.async.
// 3 passes over K: hi*hi, hi*lo, lo*hi accumulated in fp32 registers.
// ---------------------------------------------------------------------------
#define NITER 384          // 3 passes * 128 k-iters (BK=64)
#define STG_BYTES 32768    // A 16KB + B 16KB per stage
#define SMEM_TOTAL (4 * STG_BYTES)

__global__ __launch_bounds__(256) void scores_tc_kernel(
    float* __restrict__ Sc, const float* __restrict__ stdp_scale) {
    extern __shared__ char smem[];
    const int bh = blockIdx.z;
    const int bt = blockIdx.y;
    const int bs = blockIdx.x;
    float* Sbase = Sc + (size_t)bh * Tdim * Tdim;

    if (bs > bt) {  // strictly-upper tile: zeros
        const int r0 = bt * 128, c0 = bs * 128;
        float4 z = make_float4(0.f, 0.f, 0.f, 0.f);
        for (int i = threadIdx.x; i < 128 * 32; i += 256) {
            int r = i >> 5, c = (i & 31) << 2;
            *(float4*)(Sbase + (size_t)(r0 + r) * Tdim + c0 + c) = z;
        }
        return;
    }

    const uint32_t sbase = smem_u32(smem);
    const int tid = threadIdx.x;
    const int wid = tid >> 5;
    const int lid = tid & 31;
    const int wr = wid >> 2;   // warp row (0-1): rows wr*64..+63
    const int wc = wid & 3;    // warp col (0-3): cols wc*32..+31

    const char* Ah = (const char*)(g_Qh + ((size_t)bh * Tdim + bt * 128) * Ndim);
    const char* Al = (const char*)(g_Ql + ((size_t)bh * Tdim + bt * 128) * Ndim);
    const char* Bh = (const char*)(g_Qh + ((size_t)bh * Tdim + bs * 128) * Ndim);
    const char* Bl = (const char*)(g_Ql + ((size_t)bh * Tdim + bs * 128) * Ndim);

    // cp.async geometry: per stage each thread loads 4x16B for A and for B.
    const int rbase = tid >> 3;        // row 0..31 (+32*j)
    const int colb = (tid & 7) * 16;   // byte col within 128B row
    const uint32_t sw0 = swz((rbase + 0) * 128 + colb);
    const uint32_t sw1 = swz((rbase + 32) * 128 + colb);
    const uint32_t sw2 = swz((rbase + 64) * 128 + colb);
    const uint32_t sw3 = swz((rbase + 96) * 128 + colb);
    const size_t go0 = (size_t)(rbase + 0) * (Ndim * 2) + colb;
    const size_t go1 = (size_t)(rbase + 32) * (Ndim * 2) + colb;
    const size_t go2 = (size_t)(rbase + 64) * (Ndim * 2) + colb;
    const size_t go3 = (size_t)(rbase + 96) * (Ndim * 2) + colb;

    auto issue_loads = [&](int j, int stage) {
        if (j < NITER) {
            int pass = j >> 7;
            size_t kb = (size_t)(j & 127) * 128;  // 64 bf16 = 128B along K
            const char* Asrc = (pass == 2) ? Al : Ah;
            const char* Bsrc = (pass == 1) ? Bl : Bh;
            uint32_t sA = sbase + stage * STG_BYTES;
            uint32_t sB = sA + 16384;
            cp16(sA + sw0, Asrc + go0 + kb);
            cp16(sA + sw1, Asrc + go1 + kb);
            cp16(sA + sw2, Asrc + go2 + kb);
            cp16(sA + sw3, Asrc + go3 + kb);
            cp16(sB + sw0, Bsrc + go0 + kb);
            cp16(sB + sw1, Bsrc + go1 + kb);
            cp16(sB + sw2, Bsrc + go2 + kb);
            cp16(sB + sw3, Bsrc + go3 + kb);
        }
        asm volatile("cp.async.commit_group;" ::: "memory");
    };

    // ldmatrix address precompute (within a stage's A / B tile).
    // A frag (m16k16): lanes 0-7 rows0-7@k, 8-15 rows8-15@k, 16-23 rows0-7@k+8,
    // 24-31 rows8-15@k+8.
    const int a_row = wr * 64 + (lid & 15);
    const int a_kb = (lid >> 4) * 16;  // +16B for hi-k half
    uint32_t a_off[4];
#pragma unroll
    for (int mi = 0; mi < 4; mi++)
        a_off[mi] = swz((a_row + mi * 16) * 128 + a_kb);
    // B frag (n8k16 pairs): lanes0-7 n0-7@k, 8-15 n0-7@k+8, 16-23 n8-15@k,
    // 24-31 n8-15@k+8.
    const int b_row = wc * 32 + (lid & 7) + ((lid >> 4) << 3);
    const int b_kb = ((lid >> 3) & 1) * 16;
    uint32_t b_off[2];
#pragma unroll
    for (int nb = 0; nb < 2; nb++)
        b_off[nb] = swz((b_row + nb * 16) * 128 + b_kb);

    float acc[4][4][4];
#pragma unroll
    for (int i = 0; i < 4; i++)
#pragma unroll
        for (int j = 0; j < 4; j++)
#pragma unroll
            for (int k = 0; k < 4; k++) acc[i][j][k] = 0.f;

    // Prologue
    issue_loads(0, 0);
    issue_loads(1, 1);
    issue_loads(2, 2);

    for (int i = 0; i < NITER; i++) {
        const int stage = i & 3;
        __syncthreads();              // all warps done reading stage (i-1)&3
        issue_loads(i + 3, (i + 3) & 3);
        asm volatile("cp.async.wait_group 3;" ::: "memory");
        __syncthreads();              // stage i data visible to all warps

        const uint32_t sA = sbase + stage * STG_BYTES;
        const uint32_t sB = sA + 16384;
#pragma unroll
        for (int ks = 0; ks < 4; ks++) {
            const uint32_t kadd = ks * 32;  // 16 bf16 = 32B per k-step
            uint32_t a[4][4];
#pragma unroll
            for (int mi = 0; mi < 4; mi++)
                ldm_x4(a[mi][0], a[mi][1], a[mi][2], a[mi][3],
                       sA + (a_off[mi] ^ swz(kadd)));
            uint32_t b[2][4];
#pragma unroll
            for (int nb = 0; nb < 2; nb++)
                ldm_x4(b[nb][0], b[nb][1], b[nb][2], b[nb][3],
                       sB + (b_off[nb] ^ swz(kadd)));
#pragma unroll
            for (int mi = 0; mi < 4; mi++) {
                mma16816(acc[mi][0], a[mi], b[0][0], b[0][1]);
                mma16816(acc[mi][1], a[mi], b[0][2], b[0][3]);
                mma16816(acc[mi][2], a[mi], b[1][0], b[1][1]);
                mma16816(acc[mi][3], a[mi], b[1][2], b[1][3]);
            }
        }
    }

    // Epilogue: apply (t>s) * (1 + ss*exp(0.05*(s-t))) * gate[t], store fp32.
    const float ssc = stdp_scale[0] * 0.01f;
    const int g0 = lid >> 2;        // fragment row group 0..7
    const int tg = lid & 3;         // fragment col group
#pragma unroll
    for (int mi = 0; mi < 4; mi++) {
#pragma unroll
        for (int half = 0; half < 2; half++) {
            const int t = bt * 128 + wr * 64 + mi * 16 + g0 + half * 8;
            const float g = g_gate[bh * Tdim + t];
            const float bco = g * ssc * __expf(-0.05f * (float)t);
            float* rowp = Sbase + (size_t)t * Tdim;
#pragma unroll
            for (int ni = 0; ni < 4; ni++) {
                const int s = bs * 128 + wc * 32 + ni * 8 + tg * 2;
                const float e0 = __expf(0.05f * (float)s);
                float v0 = acc[mi][ni][half * 2 + 0];
                float v1 = acc[mi][ni][half * 2 + 1];
                float2 o;
                o.x = (t > s)     ? v0 * fmaf(bco, e0, g) : 0.f;
                o.y = (t > s + 1) ? v1 * fmaf(bco, e0 * 1.0512710963760241f, g)
                                  : 0.f;
                *(float2*)(rowp + s) = o;
            }
        }
    }
}

// ---------------------------------------------------------------------------
// GEMM2: output = scores @ V
// ---------------------------------------------------------------------------
__global__ __launch_bounds__(256) void out_kernel(
    float* __restrict__ Out, const float* __restrict__ Sc,
    const float* __restrict__ V) {
    const int bh = blockIdx.z;
    const int b = bh / NHdim;
    const int bt = blockIdx.y;
    const int bd = blockIdx.x;
    const float* Srow = Sc + ((size_t)bh * Tdim + bt * 64) * Tdim;
    const float* Vb = V + (size_t)b * Tdim * Ddim + bd * 64;

    __shared__ float Ss[16][64];
    __shared__ float Vs[16][64];

    const int tid = threadIdx.x;
    const int tx = tid & 15;
    const int ty = tid >> 4;
    const int rs = tid >> 2;
    const int cs = (tid & 3) << 2;
    const int rv = tid >> 4;
    const int cv = (tid & 15) << 2;

    float acc[4][4];
#pragma unroll
    for (int i = 0; i < 4; i++)
#pragma unroll
        for (int j = 0; j < 4; j++) acc[i][j] = 0.f;

    const int kend = (bt + 1) * 64;
    for (int k0 = 0; k0 < kend; k0 += 16) {
        float4 sv = *(const float4*)(Srow + (size_t)rs * Tdim + k0 + cs);
        float4 vv = *(const float4*)(Vb + (size_t)(k0 + rv) * Ddim + cv);
        __syncthreads();
        Ss[cs + 0][rs] = sv.x; Ss[cs + 1][rs] = sv.y;
        Ss[cs + 2][rs] = sv.z; Ss[cs + 3][rs] = sv.w;
        *(float4*)(&Vs[rv][cv]) = vv;
        __syncthreads();
#pragma unroll
        for (int kk = 0; kk < 16; kk++) {
            float a[4], bb[4];
            *(float4*)a = *(const float4*)(&Ss[kk][ty * 4]);
            *(float4*)bb = *(const float4*)(&Vs[kk][tx * 4]);
#pragma unroll
            for (int i = 0; i < 4; i++)
#pragma unroll
                for (int j = 0; j < 4; j++)
                    acc[i][j] = fmaf(a[i], bb[j], acc[i][j]);
        }
    }
#pragma unroll
    for (int i = 0; i < 4; i++) {
        float* op = Out + ((size_t)bh * Tdim + bt * 64 + ty * 4 + i) * Ddim +
                    bd * 64 + tx * 4;
        *(float4*)op = make_float4(acc[i][0], acc[i][1], acc[i][2], acc[i][3]);
    }
}

// ---------------------------------------------------------------------------
extern "C" void kernel_launch(void* const* d_in, const int* in_sizes, int n_in,
                              void* d_out, int out_size) {
    const float* Q      = (const float*)d_in[0];
    const float* V      = (const float*)d_in[1];
    const float* traces = (const float*)d_in[2];
    const float* scale  = (const float*)d_in[3];
    float* out = (float*)d_out;

    const size_t OUT_ELEMS = (size_t)BHdim * Tdim * Ddim;
    const size_t SC_ELEMS  = (size_t)BHdim * Tdim * Tdim;

    float* scores;
    if ((size_t)out_size >= OUT_ELEMS + SC_ELEMS) {
        scores = out + OUT_ELEMS;
    } else {
        void* p = nullptr;
        cudaGetSymbolAddress(&p, g_S_fallback);
        scores = (float*)p;
    }

    const size_t np = (size_t)BHdim * Tdim * (Ndim / 2);
    rope_kernel<<<(unsigned)((np + 255) / 256), 256>>>(Q);
    gate_kernel<<<BHdim * Tdim, 32>>>(traces);

    static bool attr_set = false;
    if (!attr_set) {
        cudaFuncSetAttribute(scores_tc_kernel,
                             cudaFuncAttributeMaxDynamicSharedMemorySize,
                             SMEM_TOTAL);
        attr_set = true;
    }
    dim3 g1(Tdim / 128, Tdim / 128, BHdim);
    scores_tc_kernel<<<g1, 256, SMEM_TOTAL>>>(scores, scale);

    dim3 g2(Ddim / 64, Tdim / 64, BHdim);
    out_kernel<<<g2, 256>>>(out, scores, V);
}

// round 5
// speedup vs baseline: 3.2011x; 1.1868x over previous
#include <cuda_runtime.h>
#include <cuda_bf16.h>
#include <math.h>
#include <stdint.h>

#define Bdim 2
#define NHdim 4
#define Tdim 1024
#define Ndim 8192
#define Ddim 256
#define BHdim (Bdim * NHdim)

// Scratch (no cudaMalloc allowed)
static __device__ __nv_bfloat16 g_Qh[67108864];  // [BH, T, N] hi, 128 MB
static __device__ __nv_bfloat16 g_Ql[67108864];  // [BH, T, N] lo, 128 MB
static __device__ __nv_bfloat16 g_Sh[8388608];   // [BH, T, T] scores hi bf16
static __device__ __nv_bfloat16 g_Sl[8388608];   // [BH, T, T] scores lo bf16
static __device__ __nv_bfloat16 g_VTh[Bdim * Ddim * Tdim];  // [B, D, T]
static __device__ __nv_bfloat16 g_VTl[Bdim * Ddim * Tdim];
static __device__ float g_gate[BHdim * Tdim];
static __device__ float g_S_fallback[8388608];

// ---------------------------------------------------------------------------
// PTX helpers (baseline sm_80+ ISA: cp.async, ldmatrix, mma.sync)
// ---------------------------------------------------------------------------
__device__ __forceinline__ uint32_t smem_u32(const void* p) {
    uint32_t a;
    asm("{ .reg .u64 t; cvta.to.shared.u64 t, %1; cvt.u32.u64 %0, t; }"
        : "=r"(a) : "l"(p));
    return a;
}
__device__ __forceinline__ void cp16(uint32_t s, const void* g) {
    asm volatile("cp.async.cg.shared.global [%0], [%1], 16;" :: "r"(s), "l"(g)
                 : "memory");
}
__device__ __forceinline__ void ldm_x4(uint32_t* r, uint32_t addr) {
    asm volatile(
        "ldmatrix.sync.aligned.m8n8.x4.shared.b16 {%0,%1,%2,%3}, [%4];"
        : "=r"(r[0]), "=r"(r[1]), "=r"(r[2]), "=r"(r[3]) : "r"(addr));
}
__device__ __forceinline__ void mma16816(float* c, const uint32_t* a,
                                         uint32_t b0, uint32_t b1) {
    asm volatile(
        "mma.sync.aligned.m16n8k16.row.col.f32.bf16.bf16.f32 "
        "{%0,%1,%2,%3}, {%4,%5,%6,%7}, {%8,%9}, {%0,%1,%2,%3};"
        : "+f"(c[0]), "+f"(c[1]), "+f"(c[2]), "+f"(c[3])
        : "r"(a[0]), "r"(a[1]), "r"(a[2]), "r"(a[3]), "r"(b0), "r"(b1));
}
__device__ __forceinline__ uint32_t swz(uint32_t off) {
    return off ^ ((off >> 3) & 0x70);  // SW128
}

// ---------------------------------------------------------------------------
// RoPE + bf16x3 split
// ---------------------------------------------------------------------------
__global__ void rope_kernel(const float* __restrict__ Q) {
    size_t idx = (size_t)blockIdx.x * blockDim.x + threadIdx.x;
    const size_t NP = (size_t)BHdim * Tdim * (Ndim / 2);
    if (idx >= NP) return;
    int p = (int)(idx % (Ndim / 2));
    int t = (int)((idx / (Ndim / 2)) % Tdim);
    float q = 2.0f * (float)p;
    float freq = exp2f(-16.0f * q * (1.0f / (float)Ndim)) * 0.15915494309189535f;
    float ph = (float)t * freq;
    ph = (ph - floorf(ph)) * 6.283185307179586f;
    float s, c;
    sincosf(ph, &s, &c);
    float2 v = ((const float2*)Q)[idx];
    float rx = v.x * c - v.y * s;
    float ry = v.y * c + v.x * s;
    __nv_bfloat16 hx = __float2bfloat16(rx);
    __nv_bfloat16 hy = __float2bfloat16(ry);
    __nv_bfloat16 lx = __float2bfloat16(rx - __bfloat162float(hx));
    __nv_bfloat16 ly = __float2bfloat16(ry - __bfloat162float(hy));
    __nv_bfloat162 h; h.x = hx; h.y = hy;
    __nv_bfloat162 l; l.x = lx; l.y = ly;
    ((__nv_bfloat162*)g_Qh)[idx] = h;
    ((__nv_bfloat162*)g_Ql)[idx] = l;
}

// ---------------------------------------------------------------------------
// Gate
// ---------------------------------------------------------------------------
__global__ void gate_kernel(const float* __restrict__ traces) {
    int row = blockIdx.x;
    const float* pr = traces + (size_t)row * Ddim;
    float sum = 0.f;
    for (int i = threadIdx.x; i < Ddim; i += 32) sum += pr[i];
#pragma unroll
    for (int o = 16; o; o >>= 1) sum += __shfl_xor_sync(0xffffffffu, sum, o);
    if (threadIdx.x == 0) {
        float m = sum * (1.0f / (float)Ddim);
        float sig = 1.0f / (1.0f + expf(-m));
        g_gate[row] = 0.5f + 0.5f * sig;
    }
}

// ---------------------------------------------------------------------------
// V transpose + bf16 split: VT[b][d][s] from V[b][s][d]
// ---------------------------------------------------------------------------
__global__ void vt_kernel(const float* __restrict__ V) {
    __shared__ float tile[32][33];
    const int b = blockIdx.z;
    const int s0 = blockIdx.x * 32, d0 = blockIdx.y * 32;
#pragma unroll
    for (int j = 0; j < 4; j++)
        tile[threadIdx.y + 8 * j][threadIdx.x] =
            V[(size_t)b * Tdim * Ddim + (size_t)(s0 + threadIdx.y + 8 * j) * Ddim +
              d0 + threadIdx.x];
    __syncthreads();
#pragma unroll
    for (int j = 0; j < 4; j++) {
        int d = d0 + threadIdx.y + 8 * j;
        int s = s0 + threadIdx.x;
        float v = tile[threadIdx.x][threadIdx.y + 8 * j];
        __nv_bfloat16 h = __float2bfloat16(v);
        __nv_bfloat16 l = __float2bfloat16(v - __bfloat162float(h));
        size_t o = (size_t)b * Ddim * Tdim + (size_t)d * Tdim + s;
        g_VTh[o] = h;
        g_VTl[o] = l;
    }
}

// ---------------------------------------------------------------------------
// Shared mainloop geometry:
// 128x128 tile, 8 warps (2x4), warp tile 64x32, K-chunk 64 bf16 (128B).
// Stage = Ah(16K) + Bh(16K) + Al(16K) + Bl(16K) = 64KB. 3 stages = 192KB.
// ---------------------------------------------------------------------------
#define STG_BYTES 65536
#define SMEM_TOTAL (3 * STG_BYTES)

struct FragCtx {
    uint32_t a_off[4];
    uint32_t b_off[2];
    uint32_t sw[4];
    size_t go[4];
};

__device__ __forceinline__ void frag_setup(FragCtx& f, int tid) {
    const int lid = tid & 31;
    const int wid = tid >> 5;
    const int wr = wid >> 2;
    const int wc = wid & 3;
    const int a_row = wr * 64 + (lid & 15);
    const int a_kb = (lid >> 4) * 16;
#pragma unroll
    for (int mi = 0; mi < 4; mi++)
        f.a_off[mi] = swz((a_row + mi * 16) * 128 + a_kb);
    const int b_row = wc * 32 + (lid & 7) + ((lid >> 4) << 3);
    const int b_kb = ((lid >> 3) & 1) * 16;
#pragma unroll
    for (int nb = 0; nb < 2; nb++)
        f.b_off[nb] = swz((b_row + nb * 16) * 128 + b_kb);
    const int rbase = tid >> 3;
    const int colb = (tid & 7) * 16;
#pragma unroll
    for (int r = 0; r < 4; r++)
        f.sw[r] = swz((rbase + 32 * r) * 128 + colb);
#pragma unroll
    for (int r = 0; r < 4; r++)
        f.go[r] = (size_t)(rbase + 32 * r) * 2048 + colb;  // row stride 2048B
}

// Issue one chunk's 16 cp16 (4 tiles x 4 rows each).
__device__ __forceinline__ void issue_chunk(
    const FragCtx& f, uint32_t sbase, int st, size_t kb,
    const char* Ah, const char* Bh, const char* Al, const char* Bl,
    size_t rowstrideA, size_t rowstrideB) {
    uint32_t s0 = sbase + st * STG_BYTES;
#pragma unroll
    for (int r = 0; r < 4; r++) {
        size_t goA = (f.go[r] / 2048) * rowstrideA + (f.go[r] % 2048);
        size_t goB = (f.go[r] / 2048) * rowstrideB + (f.go[r] % 2048);
        cp16(s0 + f.sw[r],         Ah + goA + kb);
        cp16(s0 + 16384 + f.sw[r], Bh + goB + kb);
        cp16(s0 + 32768 + f.sw[r], Al + goA + kb);
        cp16(s0 + 49152 + f.sw[r], Bl + goB + kb);
    }
}

// Compute one chunk: 4 k-steps, bf16x3 (hh + hl + lh).
__device__ __forceinline__ void compute_chunk(const FragCtx& f, uint32_t sbase,
                                              int st, float acc[4][4][4]) {
    const uint32_t s0 = sbase + st * STG_BYTES;
#pragma unroll
    for (int ks = 0; ks < 4; ks++) {
        const uint32_t kx = ks * 32;
        uint32_t ah[4][4], bh2[2][4];
#pragma unroll
        for (int mi = 0; mi < 4; mi++)
            ldm_x4(ah[mi], s0 + (f.a_off[mi] ^ kx));
#pragma unroll
        for (int nb = 0; nb < 2; nb++)
            ldm_x4(bh2[nb], s0 + 16384 + (f.b_off[nb] ^ kx));
#pragma unroll
        for (int mi = 0; mi < 4; mi++) {
            mma16816(acc[mi][0], ah[mi], bh2[0][0], bh2[0][1]);
            mma16816(acc[mi][1], ah[mi], bh2[0][2], bh2[0][3]);
            mma16816(acc[mi][2], ah[mi], bh2[1][0], bh2[1][1]);
            mma16816(acc[mi][3], ah[mi], bh2[1][2], bh2[1][3]);
        }
        uint32_t bl2[2][4];
#pragma unroll
        for (int nb = 0; nb < 2; nb++)
            ldm_x4(bl2[nb], s0 + 49152 + (f.b_off[nb] ^ kx));
#pragma unroll
        for (int mi = 0; mi < 4; mi++) {
            mma16816(acc[mi][0], ah[mi], bl2[0][0], bl2[0][1]);
            mma16816(acc[mi][1], ah[mi], bl2[0][2], bl2[0][3]);
            mma16816(acc[mi][2], ah[mi], bl2[1][0], bl2[1][1]);
            mma16816(acc[mi][3], ah[mi], bl2[1][2], bl2[1][3]);
        }
        uint32_t al[4][4];
#pragma unroll
        for (int mi = 0; mi < 4; mi++)
            ldm_x4(al[mi], s0 + 32768 + (f.a_off[mi] ^ kx));
#pragma unroll
        for (int mi = 0; mi < 4; mi++) {
            mma16816(acc[mi][0], al[mi], bh2[0][0], bh2[0][1]);
            mma16816(acc[mi][1], al[mi], bh2[0][2], bh2[0][3]);
            mma16816(acc[mi][2], al[mi], bh2[1][0], bh2[1][1]);
            mma16816(acc[mi][3], al[mi], bh2[1][2], bh2[1][3]);
        }
    }
}

// ---------------------------------------------------------------------------
// GEMM1: scores (+ bf16 split copies for GEMM2)
// ---------------------------------------------------------------------------
__global__ __launch_bounds__(256) void scores_tc_kernel(
    float* __restrict__ Sc, const float* __restrict__ stdp_scale) {
    extern __shared__ char smem[];
    const int bh = blockIdx.z;
    const int bt = blockIdx.y;
    const int bs = blockIdx.x;
    float* Sbase = Sc + (size_t)bh * Tdim * Tdim;
    __nv_bfloat16* Shb = g_Sh + (size_t)bh * Tdim * Tdim;
    __nv_bfloat16* Slb = g_Sl + (size_t)bh * Tdim * Tdim;

    if (bs > bt) {  // strictly-upper tile: zeros (fp32 + bf16 copies)
        const int r0 = bt * 128, c0 = bs * 128;
        float4 z = make_float4(0.f, 0.f, 0.f, 0.f);
        for (int i = threadIdx.x; i < 128 * 32; i += 256) {
            int r = i >> 5, c = (i & 31) << 2;
            *(float4*)(Sbase + (size_t)(r0 + r) * Tdim + c0 + c) = z;
        }
        for (int i = threadIdx.x; i < 128 * 16; i += 256) {
            int r = i >> 4, c = (i & 15) << 3;
            size_t o = (size_t)(r0 + r) * Tdim + c0 + c;
            *(uint4*)(Shb + o) = make_uint4(0, 0, 0, 0);
            *(uint4*)(Slb + o) = make_uint4(0, 0, 0, 0);
        }
        return;
    }

    const uint32_t sbase = smem_u32(smem);
    const int tid = threadIdx.x;
    const int wid = tid >> 5;
    const int lid = tid & 31;
    const int wr = wid >> 2;
    const int wc = wid & 3;

    FragCtx f;
    frag_setup(f, tid);

    const char* Ah = (const char*)(g_Qh + ((size_t)bh * Tdim + bt * 128) * Ndim);
    const char* Al = (const char*)(g_Ql + ((size_t)bh * Tdim + bt * 128) * Ndim);
    const char* Bh = (const char*)(g_Qh + ((size_t)bh * Tdim + bs * 128) * Ndim);
    const char* Bl = (const char*)(g_Ql + ((size_t)bh * Tdim + bs * 128) * Ndim);
    const size_t rsQ = (size_t)Ndim * 2;

    float acc[4][4][4];
#pragma unroll
    for (int i = 0; i < 4; i++)
#pragma unroll
        for (int j = 0; j < 4; j++)
#pragma unroll
            for (int k = 0; k < 4; k++) acc[i][j][k] = 0.f;

    const int NCH = 128;
    issue_chunk(f, sbase, 0, 0, Ah, Bh, Al, Bl, rsQ, rsQ);
    asm volatile("cp.async.commit_group;" ::: "memory");
    issue_chunk(f, sbase, 1, 128, Ah, Bh, Al, Bl, rsQ, rsQ);
    asm volatile("cp.async.commit_group;" ::: "memory");

    for (int i = 0; i < NCH; i++) {
        const int st = i % 3;
        __syncthreads();
        if (i + 2 < NCH)
            issue_chunk(f, sbase, (i + 2) % 3, (size_t)(i + 2) * 128,
                        Ah, Bh, Al, Bl, rsQ, rsQ);
        asm volatile("cp.async.commit_group;" ::: "memory");
        asm volatile("cp.async.wait_group 2;" ::: "memory");
        __syncthreads();
        compute_chunk(f, sbase, st, acc);
    }

    // Epilogue: mask/stdp/gate; store fp32 + bf16 hi/lo.
    const float ssc = stdp_scale[0] * 0.01f;
    const int g0 = lid >> 2;
    const int tg = lid & 3;
#pragma unroll
    for (int mi = 0; mi < 4; mi++) {
#pragma unroll
        for (int half = 0; half < 2; half++) {
            const int t = bt * 128 + wr * 64 + mi * 16 + g0 + half * 8;
            const float g = g_gate[bh * Tdim + t];
            const float bco = g * ssc * __expf(-0.05f * (float)t);
            float* rowp = Sbase + (size_t)t * Tdim;
            __nv_bfloat16* hrow = Shb + (size_t)t * Tdim;
            __nv_bfloat16* lrow = Slb + (size_t)t * Tdim;
#pragma unroll
            for (int ni = 0; ni < 4; ni++) {
                const int s = bs * 128 + wc * 32 + ni * 8 + tg * 2;
                const float e0 = __expf(0.05f * (float)s);
                float v0 = acc[mi][ni][half * 2 + 0];
                float v1 = acc[mi][ni][half * 2 + 1];
                float2 o;
                o.x = (t > s)     ? v0 * fmaf(bco, e0, g) : 0.f;
                o.y = (t > s + 1) ? v1 * fmaf(bco, e0 * 1.0512710963760241f, g)
                                  : 0.f;
                *(float2*)(rowp + s) = o;
                __nv_bfloat162 h, l;
                h.x = __float2bfloat16(o.x);
                h.y = __float2bfloat16(o.y);
                l.x = __float2bfloat16(o.x - __bfloat162float(h.x));
                l.y = __float2bfloat16(o.y - __bfloat162float(h.y));
                *(__nv_bfloat162*)(hrow + s) = h;
                *(__nv_bfloat162*)(lrow + s) = l;
            }
        }
    }
}

// ---------------------------------------------------------------------------
// GEMM2 via HMMA bf16x3: Out = S @ V   (A = Sh/Sl [t][s], B = VTh/VTl [d][s])
// ---------------------------------------------------------------------------
__global__ __launch_bounds__(256) void out_tc_kernel(float* __restrict__ Out) {
    extern __shared__ char smem[];
    const int bh = blockIdx.z;
    const int b = bh / NHdim;
    const int bt = blockIdx.y;
    const int bd = blockIdx.x;

    const uint32_t sbase = smem_u32(smem);
    const int tid = threadIdx.x;
    const int wid = tid >> 5;
    const int lid = tid & 31;
    const int wr = wid >> 2;
    const int wc = wid & 3;

    FragCtx f;
    frag_setup(f, tid);

    const char* Ah = (const char*)(g_Sh + ((size_t)bh * Tdim + bt * 128) * Tdim);
    const char* Al = (const char*)(g_Sl + ((size_t)bh * Tdim + bt * 128) * Tdim);
    const char* Bh = (const char*)(g_VTh + ((size_t)b * Ddim + bd * 128) * Tdim);
    const char* Bl = (const char*)(g_VTl + ((size_t)b * Ddim + bd * 128) * Tdim);
    const size_t rs = (size_t)Tdim * 2;

    float acc[4][4][4];
#pragma unroll
    for (int i = 0; i < 4; i++)
#pragma unroll
        for (int j = 0; j < 4; j++)
#pragma unroll
            for (int k = 0; k < 4; k++) acc[i][j][k] = 0.f;

    const int NCH = (bt + 1) * 2;  // causal: k chunks of 64 up to (bt+1)*128
    issue_chunk(f, sbase, 0, 0, Ah, Bh, Al, Bl, rs, rs);
    asm volatile("cp.async.commit_group;" ::: "memory");
    issue_chunk(f, sbase, 1, 128, Ah, Bh, Al, Bl, rs, rs);
    asm volatile("cp.async.commit_group;" ::: "memory");

    for (int i = 0; i < NCH; i++) {
        const int st = i % 3;
        __syncthreads();
        if (i + 2 < NCH)
            issue_chunk(f, sbase, (i + 2) % 3, (size_t)(i + 2) * 128,
                        Ah, Bh, Al, Bl, rs, rs);
        asm volatile("cp.async.commit_group;" ::: "memory");
        asm volatile("cp.async.wait_group 2;" ::: "memory");
        __syncthreads();
        compute_chunk(f, sbase, st, acc);
    }

    const int g0 = lid >> 2;
    const int tg = lid & 3;
#pragma unroll
    for (int mi = 0; mi < 4; mi++) {
#pragma unroll
        for (int half = 0; half < 2; half++) {
            const int t = bt * 128 + wr * 64 + mi * 16 + g0 + half * 8;
            float* rowp = Out + ((size_t)bh * Tdim + t) * Ddim;
#pragma unroll
            for (int ni = 0; ni < 4; ni++) {
                const int d = bd * 128 + wc * 32 + ni * 8 + tg * 2;
                float2 o;
                o.x = acc[mi][ni][half * 2 + 0];
                o.y = acc[mi][ni][half * 2 + 1];
                *(float2*)(rowp + d) = o;
            }
        }
    }
}

// ---------------------------------------------------------------------------
extern "C" void kernel_launch(void* const* d_in, const int* in_sizes, int n_in,
                              void* d_out, int out_size) {
    const float* Q      = (const float*)d_in[0];
    const float* V      = (const float*)d_in[1];
    const float* traces = (const float*)d_in[2];
    const float* scale  = (const float*)d_in[3];
    float* out = (float*)d_out;

    const size_t OUT_ELEMS = (size_t)BHdim * Tdim * Ddim;
    const size_t SC_ELEMS  = (size_t)BHdim * Tdim * Tdim;

    float* scores;
    if ((size_t)out_size >= OUT_ELEMS + SC_ELEMS) {
        scores = out + OUT_ELEMS;
    } else {
        void* p = nullptr;
        cudaGetSymbolAddress(&p, g_S_fallback);
        scores = (float*)p;
    }

    static bool attr_set = false;
    if (!attr_set) {
        cudaFuncSetAttribute(scores_tc_kernel,
                             cudaFuncAttributeMaxDynamicSharedMemorySize,
                             SMEM_TOTAL);
        cudaFuncSetAttribute(out_tc_kernel,
                             cudaFuncAttributeMaxDynamicSharedMemorySize,
                             SMEM_TOTAL);
        attr_set = true;
    }

    const size_t np = (size_t)BHdim * Tdim * (Ndim / 2);
    rope_kernel<<<(unsigned)((np + 255) / 256), 256>>>(Q);
    gate_kernel<<<BHdim * Tdim, 32>>>(traces);
    dim3 gv(Tdim / 32, Ddim / 32, Bdim);
    vt_kernel<<<gv, dim3(32, 8)>>>(V);

    dim3 g1(Tdim / 128, Tdim / 128, BHdim);
    scores_tc_kernel<<<g1, 256, SMEM_TOTAL>>>(scores, scale);

    dim3 g2(Ddim / 128, Tdim / 128, BHdim);
    out_tc_kernel<<<g2, 256, SMEM_TOTAL>>>(out);
}

// round 6
// speedup vs baseline: 4.4124x; 1.3784x over previous
#include <cuda_runtime.h>
#include <cuda_fp16.h>
#include <math.h>
#include <stdint.h>

#define Bdim 2
#define NHdim 4
#define Tdim 1024
#define Ndim 8192
#define Ddim 256
#define BHdim (Bdim * NHdim)

// Scratch (no cudaMalloc allowed)
static __device__ __half g_Qh[67108864];  // [BH, T, N] hi fp16, 128 MB
static __device__ __half g_Ql[67108864];  // [BH, T, N] lo fp16, 128 MB
static __device__ __half g_Sh[8388608];   // [BH, T, T] scores hi fp16
static __device__ __half g_Sl[8388608];   // [BH, T, T] scores lo fp16
static __device__ __half g_VTh[Bdim * Ddim * Tdim];  // [B, D, T]
static __device__ __half g_VTl[Bdim * Ddim * Tdim];
static __device__ float g_gate[BHdim * Tdim];
static __device__ float g_S_fallback[8388608];

// ---------------------------------------------------------------------------
// PTX helpers (baseline sm_80+ ISA: cp.async, ldmatrix, mma.sync)
// ---------------------------------------------------------------------------
__device__ __forceinline__ uint32_t smem_u32(const void* p) {
    uint32_t a;
    asm("{ .reg .u64 t; cvta.to.shared.u64 t, %1; cvt.u32.u64 %0, t; }"
        : "=r"(a) : "l"(p));
    return a;
}
__device__ __forceinline__ void cp16(uint32_t s, const void* g) {
    asm volatile("cp.async.cg.shared.global [%0], [%1], 16;" :: "r"(s), "l"(g)
                 : "memory");
}
__device__ __forceinline__ void ldm_x4(uint32_t* r, uint32_t addr) {
    asm volatile(
        "ldmatrix.sync.aligned.m8n8.x4.shared.b16 {%0,%1,%2,%3}, [%4];"
        : "=r"(r[0]), "=r"(r[1]), "=r"(r[2]), "=r"(r[3]) : "r"(addr));
}
__device__ __forceinline__ void mma16816(float* c, const uint32_t* a,
                                         uint32_t b0, uint32_t b1) {
    asm volatile(
        "mma.sync.aligned.m16n8k16.row.col.f32.f16.f16.f32 "
        "{%0,%1,%2,%3}, {%4,%5,%6,%7}, {%8,%9}, {%0,%1,%2,%3};"
        : "+f"(c[0]), "+f"(c[1]), "+f"(c[2]), "+f"(c[3])
        : "r"(a[0]), "r"(a[1]), "r"(a[2]), "r"(a[3]), "r"(b0), "r"(b1));
}
__device__ __forceinline__ uint32_t swz(uint32_t off) {
    return off ^ ((off >> 3) & 0x70);  // SW128
}

// ---------------------------------------------------------------------------
// RoPE + fp16 split (fast MUFU sincos; phase already in [0, 2pi))
// ---------------------------------------------------------------------------
__global__ void rope_kernel(const float* __restrict__ Q) {
    size_t idx = (size_t)blockIdx.x * blockDim.x + threadIdx.x;
    const size_t NP = (size_t)BHdim * Tdim * (Ndim / 2);
    if (idx >= NP) return;
    int p = (int)(idx % (Ndim / 2));
    int t = (int)((idx / (Ndim / 2)) % Tdim);
    float q = 2.0f * (float)p;
    float freq = exp2f(-16.0f * q * (1.0f / (float)Ndim)) * 0.15915494309189535f;
    float ph = (float)t * freq;
    ph = (ph - floorf(ph)) * 6.283185307179586f;
    float s, c;
    __sincosf(ph, &s, &c);
    float2 v = ((const float2*)Q)[idx];
    float rx = v.x * c - v.y * s;
    float ry = v.y * c + v.x * s;
    __half hx = __float2half(rx);
    __half hy = __float2half(ry);
    __half lx = __float2half(rx - __half2float(hx));
    __half ly = __float2half(ry - __half2float(hy));
    __half2 h; h.x = hx; h.y = hy;
    __half2 l; l.x = lx; l.y = ly;
    ((__half2*)g_Qh)[idx] = h;
    ((__half2*)g_Ql)[idx] = l;
}

// ---------------------------------------------------------------------------
// Gate
// ---------------------------------------------------------------------------
__global__ void gate_kernel(const float* __restrict__ traces) {
    int row = blockIdx.x;
    const float* pr = traces + (size_t)row * Ddim;
    float sum = 0.f;
    for (int i = threadIdx.x; i < Ddim; i += 32) sum += pr[i];
#pragma unroll
    for (int o = 16; o; o >>= 1) sum += __shfl_xor_sync(0xffffffffu, sum, o);
    if (threadIdx.x == 0) {
        float m = sum * (1.0f / (float)Ddim);
        float sig = 1.0f / (1.0f + expf(-m));
        g_gate[row] = 0.5f + 0.5f * sig;
    }
}

// ---------------------------------------------------------------------------
// V transpose + fp16 split
// ---------------------------------------------------------------------------
__global__ void vt_kernel(const float* __restrict__ V) {
    __shared__ float tile[32][33];
    const int b = blockIdx.z;
    const int s0 = blockIdx.x * 32, d0 = blockIdx.y * 32;
#pragma unroll
    for (int j = 0; j < 4; j++)
        tile[threadIdx.y + 8 * j][threadIdx.x] =
            V[(size_t)b * Tdim * Ddim + (size_t)(s0 + threadIdx.y + 8 * j) * Ddim +
              d0 + threadIdx.x];
    __syncthreads();
#pragma unroll
    for (int j = 0; j < 4; j++) {
        int d = d0 + threadIdx.y + 8 * j;
        int s = s0 + threadIdx.x;
        float v = tile[threadIdx.x][threadIdx.y + 8 * j];
        __half h = __float2half(v);
        __half l = __float2half(v - __half2float(h));
        size_t o = (size_t)b * Ddim * Tdim + (size_t)d * Tdim + s;
        g_VTh[o] = h;
        g_VTl[o] = l;
    }
}

// ---------------------------------------------------------------------------
// Common fragment/load geometry: 128x128 tile, 8 warps 2x4, warp 64x32,
// K-chunk 64 halves (128B).
// ---------------------------------------------------------------------------
struct FragCtx {
    uint32_t a_off[4];
    uint32_t b_off[2];
    uint32_t sw[4];
    int row[4];
    int colb;
};

__device__ __forceinline__ void frag_setup(FragCtx& f, int tid) {
    const int lid = tid & 31;
    const int wid = tid >> 5;
    const int wr = wid >> 2;
    const int wc = wid & 3;
    const int a_row = wr * 64 + (lid & 15);
    const int a_kb = (lid >> 4) * 16;
#pragma unroll
    for (int mi = 0; mi < 4; mi++)
        f.a_off[mi] = swz((a_row + mi * 16) * 128 + a_kb);
    const int b_row = wc * 32 + (lid & 7) + ((lid >> 4) << 3);
    const int b_kb = ((lid >> 3) & 1) * 16;
#pragma unroll
    for (int nb = 0; nb < 2; nb++)
        f.b_off[nb] = swz((b_row + nb * 16) * 128 + b_kb);
    const int rbase = tid >> 3;
    f.colb = (tid & 7) * 16;
#pragma unroll
    for (int r = 0; r < 4; r++) {
        f.row[r] = rbase + 32 * r;
        f.sw[r] = swz(f.row[r] * 128 + f.colb);
    }
}

// ---------------------------------------------------------------------------
// GEMM1: scores = tril(QR QR^T, -1) * (1+stdp) * gate.  fp16x2 (hh + hl).
// Stage = Ah(16K)+Bh(16K)+Bl(16K) = 48KB; 2 stages = 96KB -> 2 CTAs/SM.
// ---------------------------------------------------------------------------
#define STG2 49152
#define SMEM_SC (2 * STG2)

__global__ __launch_bounds__(256, 2) void scores_tc_kernel(
    float* __restrict__ Sc, const float* __restrict__ stdp_scale) {
    extern __shared__ char smem[];
    const int bh = blockIdx.z;
    const int bt = blockIdx.y;
    const int bs = blockIdx.x;
    float* Sbase = Sc + (size_t)bh * Tdim * Tdim;
    __half* Shb = g_Sh + (size_t)bh * Tdim * Tdim;
    __half* Slb = g_Sl + (size_t)bh * Tdim * Tdim;

    if (bs > bt) {  // strictly-upper tile: zeros
        const int r0 = bt * 128, c0 = bs * 128;
        float4 z = make_float4(0.f, 0.f, 0.f, 0.f);
        for (int i = threadIdx.x; i < 128 * 32; i += 256) {
            int r = i >> 5, c = (i & 31) << 2;
            *(float4*)(Sbase + (size_t)(r0 + r) * Tdim + c0 + c) = z;
        }
        for (int i = threadIdx.x; i < 128 * 16; i += 256) {
            int r = i >> 4, c = (i & 15) << 3;
            size_t o = (size_t)(r0 + r) * Tdim + c0 + c;
            *(uint4*)(Shb + o) = make_uint4(0, 0, 0, 0);
            *(uint4*)(Slb + o) = make_uint4(0, 0, 0, 0);
        }
        return;
    }

    const uint32_t sbase = smem_u32(smem);
    const int tid = threadIdx.x;
    const int wid = tid >> 5;
    const int lid = tid & 31;
    const int wr = wid >> 2;
    const int wc = wid & 3;

    FragCtx f;
    frag_setup(f, tid);

    const char* Ah = (const char*)(g_Qh + ((size_t)bh * Tdim + bt * 128) * Ndim);
    const char* Bh = (const char*)(g_Qh + ((size_t)bh * Tdim + bs * 128) * Ndim);
    const char* Bl = (const char*)(g_Ql + ((size_t)bh * Tdim + bs * 128) * Ndim);
    const size_t rsQ = (size_t)Ndim * 2;

    size_t goQ[4];
#pragma unroll
    for (int r = 0; r < 4; r++) goQ[r] = (size_t)f.row[r] * rsQ + f.colb;

    float acc[4][4][4];
#pragma unroll
    for (int i = 0; i < 4; i++)
#pragma unroll
        for (int j = 0; j < 4; j++)
#pragma unroll
            for (int k = 0; k < 4; k++) acc[i][j][k] = 0.f;

    auto issue2 = [&](int j, int st) {
        uint32_t s0 = sbase + st * STG2;
        size_t kb = (size_t)j * 128;
#pragma unroll
        for (int r = 0; r < 4; r++) {
            cp16(s0 + f.sw[r],         Ah + goQ[r] + kb);
            cp16(s0 + 16384 + f.sw[r], Bh + goQ[r] + kb);
            cp16(s0 + 32768 + f.sw[r], Bl + goQ[r] + kb);
        }
    };

    const int NCH = 128;
    issue2(0, 0);
    asm volatile("cp.async.commit_group;" ::: "memory");

    for (int i = 0; i < NCH; i++) {
        const int st = i & 1;
        if (i + 1 < NCH) issue2(i + 1, 1 - st);
        asm volatile("cp.async.commit_group;" ::: "memory");
        asm volatile("cp.async.wait_group 1;" ::: "memory");
        __syncthreads();
        const uint32_t s0 = sbase + st * STG2;
#pragma unroll
        for (int ks = 0; ks < 4; ks++) {
            const uint32_t kx = ks * 32;
            uint32_t ah[4][4], bh2[2][4];
#pragma unroll
            for (int mi = 0; mi < 4; mi++)
                ldm_x4(ah[mi], s0 + (f.a_off[mi] ^ kx));
#pragma unroll
            for (int nb = 0; nb < 2; nb++)
                ldm_x4(bh2[nb], s0 + 16384 + (f.b_off[nb] ^ kx));
#pragma unroll
            for (int mi = 0; mi < 4; mi++) {
                mma16816(acc[mi][0], ah[mi], bh2[0][0], bh2[0][1]);
                mma16816(acc[mi][1], ah[mi], bh2[0][2], bh2[0][3]);
                mma16816(acc[mi][2], ah[mi], bh2[1][0], bh2[1][1]);
                mma16816(acc[mi][3], ah[mi], bh2[1][2], bh2[1][3]);
            }
            uint32_t bl2[2][4];
#pragma unroll
            for (int nb = 0; nb < 2; nb++)
                ldm_x4(bl2[nb], s0 + 32768 + (f.b_off[nb] ^ kx));
#pragma unroll
            for (int mi = 0; mi < 4; mi++) {
                mma16816(acc[mi][0], ah[mi], bl2[0][0], bl2[0][1]);
                mma16816(acc[mi][1], ah[mi], bl2[0][2], bl2[0][3]);
                mma16816(acc[mi][2], ah[mi], bl2[1][0], bl2[1][1]);
                mma16816(acc[mi][3], ah[mi], bl2[1][2], bl2[1][3]);
            }
        }
        __syncthreads();
    }

    // Epilogue: mask/stdp/gate; store fp32 + fp16 hi/lo split.
    const float ssc = stdp_scale[0] * 0.01f;
    const int g0 = lid >> 2;
    const int tg = lid & 3;
#pragma unroll
    for (int mi = 0; mi < 4; mi++) {
#pragma unroll
        for (int half = 0; half < 2; half++) {
            const int t = bt * 128 + wr * 64 + mi * 16 + g0 + half * 8;
            const float g = g_gate[bh * Tdim + t];
            const float bco = g * ssc * __expf(-0.05f * (float)t);
            float* rowp = Sbase + (size_t)t * Tdim;
            __half* hrow = Shb + (size_t)t * Tdim;
            __half* lrow = Slb + (size_t)t * Tdim;
#pragma unroll
            for (int ni = 0; ni < 4; ni++) {
                const int s = bs * 128 + wc * 32 + ni * 8 + tg * 2;
                const float e0 = __expf(0.05f * (float)s);
                float v0 = acc[mi][ni][half * 2 + 0];
                float v1 = acc[mi][ni][half * 2 + 1];
                float2 o;
                o.x = (t > s)     ? v0 * fmaf(bco, e0, g) : 0.f;
                o.y = (t > s + 1) ? v1 * fmaf(bco, e0 * 1.0512710963760241f, g)
                                  : 0.f;
                *(float2*)(rowp + s) = o;
                __half2 h, l;
                h.x = __float2half(o.x);
                h.y = __float2half(o.y);
                l.x = __float2half(o.x - __half2float(h.x));
                l.y = __float2half(o.y - __half2float(h.y));
                *(__half2*)(hrow + s) = h;
                *(__half2*)(lrow + s) = l;
            }
        }
    }
}

// ---------------------------------------------------------------------------
// GEMM2: Out = S @ V via fp16x3 (hh + hl + lh).  Stage 64KB, 3 stages.
// ---------------------------------------------------------------------------
#define STG3 65536
#define SMEM_OUT (3 * STG3)

__global__ __launch_bounds__(256) void out_tc_kernel(float* __restrict__ Out) {
    extern __shared__ char smem[];
    const int bh = blockIdx.z;
    const int b = bh / NHdim;
    const int bt = blockIdx.y;
    const int bd = blockIdx.x;

    const uint32_t sbase = smem_u32(smem);
    const int tid = threadIdx.x;
    const int wid = tid >> 5;
    const int lid = tid & 31;
    const int wr = wid >> 2;
    const int wc = wid & 3;

    FragCtx f;
    frag_setup(f, tid);

    const char* Ah = (const char*)(g_Sh + ((size_t)bh * Tdim + bt * 128) * Tdim);
    const char* Al = (const char*)(g_Sl + ((size_t)bh * Tdim + bt * 128) * Tdim);
    const char* Bh = (const char*)(g_VTh + ((size_t)b * Ddim + bd * 128) * Tdim);
    const char* Bl = (const char*)(g_VTl + ((size_t)b * Ddim + bd * 128) * Tdim);
    const size_t rs = (size_t)Tdim * 2;

    size_t go[4];
#pragma unroll
    for (int r = 0; r < 4; r++) go[r] = (size_t)f.row[r] * rs + f.colb;

    float acc[4][4][4];
#pragma unroll
    for (int i = 0; i < 4; i++)
#pragma unroll
        for (int j = 0; j < 4; j++)
#pragma unroll
            for (int k = 0; k < 4; k++) acc[i][j][k] = 0.f;

    auto issue3 = [&](int j, int st) {
        uint32_t s0 = sbase + st * STG3;
        size_t kb = (size_t)j * 128;
#pragma unroll
        for (int r = 0; r < 4; r++) {
            cp16(s0 + f.sw[r],         Ah + go[r] + kb);
            cp16(s0 + 16384 + f.sw[r], Bh + go[r] + kb);
            cp16(s0 + 32768 + f.sw[r], Al + go[r] + kb);
            cp16(s0 + 49152 + f.sw[r], Bl + go[r] + kb);
        }
    };

    const int NCH = (bt + 1) * 2;  // causal K bound
    issue3(0, 0);
    asm volatile("cp.async.commit_group;" ::: "memory");
    if (NCH > 1) issue3(1, 1);
    asm volatile("cp.async.commit_group;" ::: "memory");

    for (int i = 0; i < NCH; i++) {
        const int st = i % 3;
        __syncthreads();
        if (i + 2 < NCH) issue3(i + 2, (i + 2) % 3);
        asm volatile("cp.async.commit_group;" ::: "memory");
        asm volatile("cp.async.wait_group 2;" ::: "memory");
        __syncthreads();
        const uint32_t s0 = sbase + st * STG3;
#pragma unroll
        for (int ks = 0; ks < 4; ks++) {
            const uint32_t kx = ks * 32;
            uint32_t ah[4][4], bh2[2][4];
#pragma unroll
            for (int mi = 0; mi < 4; mi++)
                ldm_x4(ah[mi], s0 + (f.a_off[mi] ^ kx));
#pragma unroll
            for (int nb = 0; nb < 2; nb++)
                ldm_x4(bh2[nb], s0 + 16384 + (f.b_off[nb] ^ kx));
#pragma unroll
            for (int mi = 0; mi < 4; mi++) {
                mma16816(acc[mi][0], ah[mi], bh2[0][0], bh2[0][1]);
                mma16816(acc[mi][1], ah[mi], bh2[0][2], bh2[0][3]);
                mma16816(acc[mi][2], ah[mi], bh2[1][0], bh2[1][1]);
                mma16816(acc[mi][3], ah[mi], bh2[1][2], bh2[1][3]);
            }
            uint32_t bl2[2][4];
#pragma unroll
            for (int nb = 0; nb < 2; nb++)
                ldm_x4(bl2[nb], s0 + 49152 + (f.b_off[nb] ^ kx));
#pragma unroll
            for (int mi = 0; mi < 4; mi++) {
                mma16816(acc[mi][0], ah[mi], bl2[0][0], bl2[0][1]);
                mma16816(acc[mi][1], ah[mi], bl2[0][2], bl2[0][3]);
                mma16816(acc[mi][2], ah[mi], bl2[1][0], bl2[1][1]);
                mma16816(acc[mi][3], ah[mi], bl2[1][2], bl2[1][3]);
            }
            uint32_t al[4][4];
#pragma unroll
            for (int mi = 0; mi < 4; mi++)
                ldm_x4(al[mi], s0 + 32768 + (f.a_off[mi] ^ kx));
#pragma unroll
            for (int mi = 0; mi < 4; mi++) {
                mma16816(acc[mi][0], al[mi], bh2[0][0], bh2[0][1]);
                mma16816(acc[mi][1], al[mi], bh2[0][2], bh2[0][3]);
                mma16816(acc[mi][2], al[mi], bh2[1][0], bh2[1][1]);
                mma16816(acc[mi][3], al[mi], bh2[1][2], bh2[1][3]);
            }
        }
    }

    const int g0 = lid >> 2;
    const int tg = lid & 3;
#pragma unroll
    for (int mi = 0; mi < 4; mi++) {
#pragma unroll
        for (int half = 0; half < 2; half++) {
            const int t = bt * 128 + wr * 64 + mi * 16 + g0 + half * 8;
            float* rowp = Out + ((size_t)bh * Tdim + t) * Ddim;
#pragma unroll
            for (int ni = 0; ni < 4; ni++) {
                const int d = bd * 128 + wc * 32 + ni * 8 + tg * 2;
                float2 o;
                o.x = acc[mi][ni][half * 2 + 0];
                o.y = acc[mi][ni][half * 2 + 1];
                *(float2*)(rowp + d) = o;
            }
        }
    }
}

// ---------------------------------------------------------------------------
extern "C" void kernel_launch(void* const* d_in, const int* in_sizes, int n_in,
                              void* d_out, int out_size) {
    const float* Q      = (const float*)d_in[0];
    const float* V      = (const float*)d_in[1];
    const float* traces = (const float*)d_in[2];
    const float* scale  = (const float*)d_in[3];
    float* out = (float*)d_out;

    const size_t OUT_ELEMS = (size_t)BHdim * Tdim * Ddim;
    const size_t SC_ELEMS  = (size_t)BHdim * Tdim * Tdim;

    float* scores;
    if ((size_t)out_size >= OUT_ELEMS + SC_ELEMS) {
        scores = out + OUT_ELEMS;
    } else {
        void* p = nullptr;
        cudaGetSymbolAddress(&p, g_S_fallback);
        scores = (float*)p;
    }

    static bool attr_set = false;
    if (!attr_set) {
        cudaFuncSetAttribute(scores_tc_kernel,
                             cudaFuncAttributeMaxDynamicSharedMemorySize,
                             SMEM_SC);
        cudaFuncSetAttribute(out_tc_kernel,
                             cudaFuncAttributeMaxDynamicSharedMemorySize,
                             SMEM_OUT);
        attr_set = true;
    }

    const size_t np = (size_t)BHdim * Tdim * (Ndim / 2);
    rope_kernel<<<(unsigned)((np + 255) / 256), 256>>>(Q);
    gate_kernel<<<BHdim * Tdim, 32>>>(traces);
    dim3 gv(Tdim / 32, Ddim / 32, Bdim);
    vt_kernel<<<gv, dim3(32, 8)>>>(V);

    dim3 g1(Tdim / 128, Tdim / 128, BHdim);
    scores_tc_kernel<<<g1, 256, SMEM_SC>>>(scores, scale);

    dim3 g2(Ddim / 128, Tdim / 128, BHdim);
    out_tc_kernel<<<g2, 256, SMEM_OUT>>>(out);
}

// round 9
// speedup vs baseline: 4.7569x; 1.0781x over previous
#include <cuda_runtime.h>
#include <cuda_fp16.h>
#include <math.h>
#include <stdint.h>

#define Bdim 2
#define NHdim 4
#define Tdim 1024
#define Ndim 8192
#define Ddim 256
#define BHdim (Bdim * NHdim)

// Scratch (no cudaMalloc allowed)
static __device__ __half g_Qh[67108864];  // [BH, T, N] rope(Q) fp16, 128 MB
static __device__ __half g_Sh[8388608];   // [BH, T, T] scores hi fp16
static __device__ __half g_Sl[8388608];   // [BH, T, T] scores lo fp16
static __device__ __half g_VTh[Bdim * Ddim * Tdim];  // [B, D, T] V^T fp16
static __device__ float g_gate[BHdim * Tdim];
static __device__ float g_S_fallback[8388608];

// ---------------------------------------------------------------------------
// PTX helpers (baseline sm_80+ ISA: cp.async, ldmatrix, mma.sync)
// ---------------------------------------------------------------------------
__device__ __forceinline__ uint32_t smem_u32(const void* p) {
    uint32_t a;
    asm("{ .reg .u64 t; cvta.to.shared.u64 t, %1; cvt.u32.u64 %0, t; }"
        : "=r"(a) : "l"(p));
    return a;
}
__device__ __forceinline__ void cp16(uint32_t s, const void* g) {
    asm volatile("cp.async.cg.shared.global [%0], [%1], 16;" :: "r"(s), "l"(g)
                 : "memory");
}
__device__ __forceinline__ void ldm_x4(uint32_t* r, uint32_t addr) {
    asm volatile(
        "ldmatrix.sync.aligned.m8n8.x4.shared.b16 {%0,%1,%2,%3}, [%4];"
        : "=r"(r[0]), "=r"(r[1]), "=r"(r[2]), "=r"(r[3]) : "r"(addr));
}
__device__ __forceinline__ void mma16816(float* c, const uint32_t* a,
                                         uint32_t b0, uint32_t b1) {
    asm volatile(
        "mma.sync.aligned.m16n8k16.row.col.f32.f16.f16.f32 "
        "{%0,%1,%2,%3}, {%4,%5,%6,%7}, {%8,%9}, {%0,%1,%2,%3};"
        : "+f"(c[0]), "+f"(c[1]), "+f"(c[2]), "+f"(c[3])
        : "r"(a[0]), "r"(a[1]), "r"(a[2]), "r"(a[3]), "r"(b0), "r"(b1));
}
__device__ __forceinline__ uint32_t swz(uint32_t off) {
    return off ^ ((off >> 3) & 0x70);  // SW128
}

// ---------------------------------------------------------------------------
// RoPE -> fp16 (hi only; single-product scores needs no lo operand)
// ---------------------------------------------------------------------------
__global__ void rope_kernel(const float* __restrict__ Q) {
    size_t idx = (size_t)blockIdx.x * blockDim.x + threadIdx.x;
    const size_t NP = (size_t)BHdim * Tdim * (Ndim / 2);
    if (idx >= NP) return;
    int p = (int)(idx % (Ndim / 2));
    int t = (int)((idx / (Ndim / 2)) % Tdim);
    float q = 2.0f * (float)p;
    float freq = exp2f(-16.0f * q * (1.0f / (float)Ndim)) * 0.15915494309189535f;
    float ph = (float)t * freq;
    ph = (ph - floorf(ph)) * 6.283185307179586f;
    float s, c;
    __sincosf(ph, &s, &c);
    float2 v = ((const float2*)Q)[idx];
    float rx = v.x * c - v.y * s;
    float ry = v.y * c + v.x * s;
    __half2 h;
    h.x = __float2half(rx);
    h.y = __float2half(ry);
    ((__half2*)g_Qh)[idx] = h;
}

// ---------------------------------------------------------------------------
// Gate
// ---------------------------------------------------------------------------
__global__ void gate_kernel(const float* __restrict__ traces) {
    int row = blockIdx.x;
    const float* pr = traces + (size_t)row * Ddim;
    float sum = 0.f;
    for (int i = threadIdx.x; i < Ddim; i += 32) sum += pr[i];
#pragma unroll
    for (int o = 16; o; o >>= 1) sum += __shfl_xor_sync(0xffffffffu, sum, o);
    if (threadIdx.x == 0) {
        float m = sum * (1.0f / (float)Ddim);
        float sig = 1.0f / (1.0f + expf(-m));
        g_gate[row] = 0.5f + 0.5f * sig;
    }
}

// ---------------------------------------------------------------------------
// V transpose -> fp16 hi: VT[b][d][s]
// ---------------------------------------------------------------------------
__global__ void vt_kernel(const float* __restrict__ V) {
    __shared__ float tile[32][33];
    const int b = blockIdx.z;
    const int s0 = blockIdx.x * 32, d0 = blockIdx.y * 32;
#pragma unroll
    for (int j = 0; j < 4; j++)
        tile[threadIdx.y + 8 * j][threadIdx.x] =
            V[(size_t)b * Tdim * Ddim + (size_t)(s0 + threadIdx.y + 8 * j) * Ddim +
              d0 + threadIdx.x];
    __syncthreads();
#pragma unroll
    for (int j = 0; j < 4; j++) {
        int d = d0 + threadIdx.y + 8 * j;
        int s = s0 + threadIdx.x;
        float v = tile[threadIdx.x][threadIdx.y + 8 * j];
        g_VTh[(size_t)b * Ddim * Tdim + (size_t)d * Tdim + s] = __float2half(v);
    }
}

// ---------------------------------------------------------------------------
// Common fragment/load geometry: 128x128 tile, 8 warps 2x4, warp 64x32.
// ---------------------------------------------------------------------------
struct FragCtx {
    uint32_t a_off[4];
    uint32_t b_off[2];
    uint32_t sw[4];
    int row[4];
    int colb;
};

__device__ __forceinline__ void frag_setup(FragCtx& f, int tid) {
    const int lid = tid & 31;
    const int wid = tid >> 5;
    const int wr = wid >> 2;
    const int wc = wid & 3;
    const int a_row = wr * 64 + (lid & 15);
    const int a_kb = (lid >> 4) * 16;
#pragma unroll
    for (int mi = 0; mi < 4; mi++)
        f.a_off[mi] = swz((a_row + mi * 16) * 128 + a_kb);
    const int b_row = wc * 32 + (lid & 7) + ((lid >> 4) << 3);
    const int b_kb = ((lid >> 3) & 1) * 16;
#pragma unroll
    for (int nb = 0; nb < 2; nb++)
        f.b_off[nb] = swz((b_row + nb * 16) * 128 + b_kb);
    const int rbase = tid >> 3;
    f.colb = (tid & 7) * 16;
#pragma unroll
    for (int r = 0; r < 4; r++) {
        f.row[r] = rbase + 32 * r;
        f.sw[r] = swz(f.row[r] * 128 + f.colb);
    }
}

// ---------------------------------------------------------------------------
// GEMM1: scores = tril(QR QR^T, -1) * (1+stdp) * gate.  Single fp16 product.
// Stage = Ah(16K)+Bh(16K) = 32KB; 3 stages = 96KB -> 2 CTAs/SM.
// Single __syncthreads per chunk (3-stage rotation).
// ---------------------------------------------------------------------------
#define STG_SC 32768
#define SMEM_SC (3 * STG_SC)

__global__ __launch_bounds__(256, 2) void scores_tc_kernel(
    float* __restrict__ Sc, const float* __restrict__ stdp_scale) {
    extern __shared__ char smem[];
    const int bh = blockIdx.z;
    const int bt = blockIdx.y;
    const int bs = blockIdx.x;
    float* Sbase = Sc + (size_t)bh * Tdim * Tdim;
    __half* Shb = g_Sh + (size_t)bh * Tdim * Tdim;
    __half* Slb = g_Sl + (size_t)bh * Tdim * Tdim;

    if (bs > bt) {  // strictly-upper tile: zeros
        const int r0 = bt * 128, c0 = bs * 128;
        float4 z = make_float4(0.f, 0.f, 0.f, 0.f);
        for (int i = threadIdx.x; i < 128 * 32; i += 256) {
            int r = i >> 5, c = (i & 31) << 2;
            *(float4*)(Sbase + (size_t)(r0 + r) * Tdim + c0 + c) = z;
        }
        for (int i = threadIdx.x; i < 128 * 16; i += 256) {
            int r = i >> 4, c = (i & 15) << 3;
            size_t o = (size_t)(r0 + r) * Tdim + c0 + c;
            *(uint4*)(Shb + o) = make_uint4(0, 0, 0, 0);
            *(uint4*)(Slb + o) = make_uint4(0, 0, 0, 0);
        }
        return;
    }

    const uint32_t sbase = smem_u32(smem);
    const int tid = threadIdx.x;
    const int wid = tid >> 5;
    const int lid = tid & 31;
    const int wr = wid >> 2;
    const int wc = wid & 3;

    FragCtx f;
    frag_setup(f, tid);

    const char* Ah = (const char*)(g_Qh + ((size_t)bh * Tdim + bt * 128) * Ndim);
    const char* Bh = (const char*)(g_Qh + ((size_t)bh * Tdim + bs * 128) * Ndim);
    const size_t rsQ = (size_t)Ndim * 2;

    size_t goQ[4];
#pragma unroll
    for (int r = 0; r < 4; r++) goQ[r] = (size_t)f.row[r] * rsQ + f.colb;

    float acc[4][4][4];
#pragma unroll
    for (int i = 0; i < 4; i++)
#pragma unroll
        for (int j = 0; j < 4; j++)
#pragma unroll
            for (int k = 0; k < 4; k++) acc[i][j][k] = 0.f;

    auto issue1 = [&](int j, int st) {
        uint32_t s0 = sbase + st * STG_SC;
        size_t kb = (size_t)j * 128;
#pragma unroll
        for (int r = 0; r < 4; r++) {
            cp16(s0 + f.sw[r],         Ah + goQ[r] + kb);
            cp16(s0 + 16384 + f.sw[r], Bh + goQ[r] + kb);
        }
    };

    const int NCH = 128;
    issue1(0, 0);
    asm volatile("cp.async.commit_group;" ::: "memory");
    issue1(1, 1);
    asm volatile("cp.async.commit_group;" ::: "memory");

    for (int i = 0; i < NCH; i++) {
        const int st = i % 3;
        asm volatile("cp.async.wait_group 1;" ::: "memory");
        __syncthreads();  // chunk i visible; all warps done with chunk i-1
        if (i + 2 < NCH) issue1(i + 2, (i + 2) % 3);
        asm volatile("cp.async.commit_group;" ::: "memory");
        const uint32_t s0 = sbase + st * STG_SC;
#pragma unroll
        for (int ks = 0; ks < 4; ks++) {
            const uint32_t kx = ks * 32;
            uint32_t ah[4][4], bh2[2][4];
#pragma unroll
            for (int mi = 0; mi < 4; mi++)
                ldm_x4(ah[mi], s0 + (f.a_off[mi] ^ kx));
#pragma unroll
            for (int nb = 0; nb < 2; nb++)
                ldm_x4(bh2[nb], s0 + 16384 + (f.b_off[nb] ^ kx));
#pragma unroll
            for (int mi = 0; mi < 4; mi++) {
                mma16816(acc[mi][0], ah[mi], bh2[0][0], bh2[0][1]);
                mma16816(acc[mi][1], ah[mi], bh2[0][2], bh2[0][3]);
                mma16816(acc[mi][2], ah[mi], bh2[1][0], bh2[1][1]);
                mma16816(acc[mi][3], ah[mi], bh2[1][2], bh2[1][3]);
            }
        }
    }

    // Epilogue: mask/stdp/gate; store fp32 + fp16 hi/lo split.
    const float ssc = stdp_scale[0] * 0.01f;
    const int g0 = lid >> 2;
    const int tg = lid & 3;
#pragma unroll
    for (int mi = 0; mi < 4; mi++) {
#pragma unroll
        for (int half = 0; half < 2; half++) {
            const int t = bt * 128 + wr * 64 + mi * 16 + g0 + half * 8;
            const float g = g_gate[bh * Tdim + t];
            const float bco = g * ssc * __expf(-0.05f * (float)t);
            float* rowp = Sbase + (size_t)t * Tdim;
            __half* hrow = Shb + (size_t)t * Tdim;
            __half* lrow = Slb + (size_t)t * Tdim;
#pragma unroll
            for (int ni = 0; ni < 4; ni++) {
                const int s = bs * 128 + wc * 32 + ni * 8 + tg * 2;
                const float e0 = __expf(0.05f * (float)s);
                float v0 = acc[mi][ni][half * 2 + 0];
                float v1 = acc[mi][ni][half * 2 + 1];
                float2 o;
                o.x = (t > s)     ? v0 * fmaf(bco, e0, g) : 0.f;
                o.y = (t > s + 1) ? v1 * fmaf(bco, e0 * 1.0512710963760241f, g)
                                  : 0.f;
                *(float2*)(rowp + s) = o;
                __half2 h, l;
                h.x = __float2half(o.x);
                h.y = __float2half(o.y);
                l.x = __float2half(o.x - __half2float(h.x));
                l.y = __float2half(o.y - __half2float(h.y));
                *(__half2*)(hrow + s) = h;
                *(__half2*)(lrow + s) = l;
            }
        }
    }
}

// ---------------------------------------------------------------------------
// GEMM2: Out = S @ Vh  (exact-S via Sh+Sl, V hi only).
// Stage = Sh(16K)+Sl(16K)+VTh(16K) = 48KB; 3 stages = 144KB.
// ---------------------------------------------------------------------------
#define STG_OUT 49152
#define SMEM_OUT (3 * STG_OUT)

__global__ __launch_bounds__(256) void out_tc_kernel(float* __restrict__ Out) {
    extern __shared__ char smem[];
    const int bh = blockIdx.z;
    const int b = bh / NHdim;
    const int bt = blockIdx.y;
    const int bd = blockIdx.x;

    const uint32_t sbase = smem_u32(smem);
    const int tid = threadIdx.x;
    const int wid = tid >> 5;
    const int lid = tid & 31;
    const int wr = wid >> 2;
    const int wc = wid & 3;

    FragCtx f;
    frag_setup(f, tid);

    const char* Ah = (const char*)(g_Sh + ((size_t)bh * Tdim + bt * 128) * Tdim);
    const char* Al = (const char*)(g_Sl + ((size_t)bh * Tdim + bt * 128) * Tdim);
    const char* Bh = (const char*)(g_VTh + ((size_t)b * Ddim + bd * 128) * Tdim);
    const size_t rs = (size_t)Tdim * 2;

    size_t go[4];
#pragma unroll
    for (int r = 0; r < 4; r++) go[r] = (size_t)f.row[r] * rs + f.colb;

    float acc[4][4][4];
#pragma unroll
    for (int i = 0; i < 4; i++)
#pragma unroll
        for (int j = 0; j < 4; j++)
#pragma unroll
            for (int k = 0; k < 4; k++) acc[i][j][k] = 0.f;

    auto issueO = [&](int j, int st) {
        uint32_t s0 = sbase + st * STG_OUT;
        size_t kb = (size_t)j * 128;
#pragma unroll
        for (int r = 0; r < 4; r++) {
            cp16(s0 + f.sw[r],         Ah + go[r] + kb);
            cp16(s0 + 16384 + f.sw[r], Al + go[r] + kb);
            cp16(s0 + 32768 + f.sw[r], Bh + go[r] + kb);
        }
    };

    const int NCH = (bt + 1) * 2;  // causal K bound
    issueO(0, 0);
    asm volatile("cp.async.commit_group;" ::: "memory");
    issueO(1, 1);
    asm volatile("cp.async.commit_group;" ::: "memory");

    for (int i = 0; i < NCH; i++) {
        const int st = i % 3;
        asm volatile("cp.async.wait_group 1;" ::: "memory");
        __syncthreads();
        if (i + 2 < NCH) issueO(i + 2, (i + 2) % 3);
        asm volatile("cp.async.commit_group;" ::: "memory");
        const uint32_t s0 = sbase + st * STG_OUT;
#pragma unroll
        for (int ks = 0; ks < 4; ks++) {
            const uint32_t kx = ks * 32;
            uint32_t ah[4][4], bh2[2][4];
#pragma unroll
            for (int mi = 0; mi < 4; mi++)
                ldm_x4(ah[mi], s0 + (f.a_off[mi] ^ kx));
#pragma unroll
            for (int nb = 0; nb < 2; nb++)
                ldm_x4(bh2[nb], s0 + 32768 + (f.b_off[nb] ^ kx));
#pragma unroll
            for (int mi = 0; mi < 4; mi++) {
                mma16816(acc[mi][0], ah[mi], bh2[0][0], bh2[0][1]);
                mma16816(acc[mi][1], ah[mi], bh2[0][2], bh2[0][3]);
                mma16816(acc[mi][2], ah[mi], bh2[1][0], bh2[1][1]);
                mma16816(acc[mi][3], ah[mi], bh2[1][2], bh2[1][3]);
            }
            uint32_t al[4][4];
#pragma unroll
            for (int mi = 0; mi < 4; mi++)
                ldm_x4(al[mi], s0 + 16384 + (f.a_off[mi] ^ kx));
#pragma unroll
            for (int mi = 0; mi < 4; mi++) {
                mma16816(acc[mi][0], al[mi], bh2[0][0], bh2[0][1]);
                mma16816(acc[mi][1], al[mi], bh2[0][2], bh2[0][3]);
                mma16816(acc[mi][2], al[mi], bh2[1][0], bh2[1][1]);
                mma16816(acc[mi][3], al[mi], bh2[1][2], bh2[1][3]);
            }
        }
    }

    const int g0 = lid >> 2;
    const int tg = lid & 3;
#pragma unroll
    for (int mi = 0; mi < 4; mi++) {
#pragma unroll
        for (int half = 0; half < 2; half++) {
            const int t = bt * 128 + wr * 64 + mi * 16 + g0 + half * 8;
            float* rowp = Out + ((size_t)bh * Tdim + t) * Ddim;
#pragma unroll
            for (int ni = 0; ni < 4; ni++) {
                const int d = bd * 128 + wc * 32 + ni * 8 + tg * 2;
                float2 o;
                o.x = acc[mi][ni][half * 2 + 0];
                o.y = acc[mi][ni][half * 2 + 1];
                *(float2*)(rowp + d) = o;
            }
        }
    }
}

// ---------------------------------------------------------------------------
extern "C" void kernel_launch(void* const* d_in, const int* in_sizes, int n_in,
                              void* d_out, int out_size) {
    const float* Q      = (const float*)d_in[0];
    const float* V      = (const float*)d_in[1];
    const float* traces = (const float*)d_in[2];
    const float* scale  = (const float*)d_in[3];
    float* out = (float*)d_out;

    const size_t OUT_ELEMS = (size_t)BHdim * Tdim * Ddim;
    const size_t SC_ELEMS  = (size_t)BHdim * Tdim * Tdim;

    float* scores;
    if ((size_t)out_size >= OUT_ELEMS + SC_ELEMS) {
        scores = out + OUT_ELEMS;
    } else {
        void* p = nullptr;
        cudaGetSymbolAddress(&p, g_S_fallback);
        scores = (float*)p;
    }

    static bool attr_set = false;
    if (!attr_set) {
        cudaFuncSetAttribute(scores_tc_kernel,
                             cudaFuncAttributeMaxDynamicSharedMemorySize,
                             SMEM_SC);
        cudaFuncSetAttribute(out_tc_kernel,
                             cudaFuncAttributeMaxDynamicSharedMemorySize,
                             SMEM_OUT);
        attr_set = true;
    }

    const size_t np = (size_t)BHdim * Tdim * (Ndim / 2);
    rope_kernel<<<(unsigned)((np + 255) / 256), 256>>>(Q);
    gate_kernel<<<BHdim * Tdim, 32>>>(traces);
    dim3 gv(Tdim / 32, Ddim / 32, Bdim);
    vt_kernel<<<gv, dim3(32, 8)>>>(V);

    dim3 g1(Tdim / 128, Tdim / 128, BHdim);
    scores_tc_kernel<<<g1, 256, SMEM_SC>>>(scores, scale);

    dim3 g2(Ddim / 128, Tdim / 128, BHdim);
    out_tc_kernel<<<g2, 256, SMEM_OUT>>>(out);
}

// round 10
// speedup vs baseline: 7.5905x; 1.5957x over previous
#include <cuda_runtime.h>
#include <cuda_fp16.h>
#include <math.h>
#include <stdint.h>

#define Bdim 2
#define NHdim 4
#define Tdim 1024
#define Ndim 8192
#define Ddim 256
#define BHdim (Bdim * NHdim)

// Scratch (no cudaMalloc allowed)
static __device__ __half g_Qh[67108864];  // [BH, T, N] rope(Q) fp16, 128 MB
static __device__ __half g_Sh[8388608];   // [BH, T, T] scores hi fp16
static __device__ __half g_Sl[8388608];   // [BH, T, T] scores lo fp16
static __device__ __half g_VTh[Bdim * Ddim * Tdim];  // [B, D, T] V^T fp16
static __device__ float g_gate[BHdim * Tdim];
static __device__ float g_S_fallback[8388608];

// ---------------------------------------------------------------------------
// PTX helpers (baseline sm_80+ ISA: cp.async, ldmatrix, mma.sync)
// ---------------------------------------------------------------------------
__device__ __forceinline__ uint32_t smem_u32(const void* p) {
    uint32_t a;
    asm("{ .reg .u64 t; cvta.to.shared.u64 t, %1; cvt.u32.u64 %0, t; }"
        : "=r"(a) : "l"(p));
    return a;
}
__device__ __forceinline__ void cp16(uint32_t s, const void* g) {
    asm volatile("cp.async.cg.shared.global [%0], [%1], 16;" :: "r"(s), "l"(g)
                 : "memory");
}
__device__ __forceinline__ void ldm_x4(uint32_t* r, uint32_t addr) {
    asm volatile(
        "ldmatrix.sync.aligned.m8n8.x4.shared.b16 {%0,%1,%2,%3}, [%4];"
        : "=r"(r[0]), "=r"(r[1]), "=r"(r[2]), "=r"(r[3]) : "r"(addr));
}
__device__ __forceinline__ void mma16816(float* c, const uint32_t* a,
                                         uint32_t b0, uint32_t b1) {
    asm volatile(
        "mma.sync.aligned.m16n8k16.row.col.f32.f16.f16.f32 "
        "{%0,%1,%2,%3}, {%4,%5,%6,%7}, {%8,%9}, {%0,%1,%2,%3};"
        : "+f"(c[0]), "+f"(c[1]), "+f"(c[2]), "+f"(c[3])
        : "r"(a[0]), "r"(a[1]), "r"(a[2]), "r"(a[3]), "r"(b0), "r"(b1));
}
__device__ __forceinline__ uint32_t swz(uint32_t off) {
    return off ^ ((off >> 3) & 0x70);  // SW128
}

// ---------------------------------------------------------------------------
// RoPE -> fp16 (hi only). float4: each thread handles 2 rotation pairs.
// ---------------------------------------------------------------------------
__global__ void rope_kernel(const float* __restrict__ Q) {
    size_t idx = (size_t)blockIdx.x * blockDim.x + threadIdx.x;
    const size_t NQ = (size_t)BHdim * Tdim * (Ndim / 4);
    if (idx >= NQ) return;
    int p2 = (int)(idx % (Ndim / 4));       // quad index -> pairs 2*p2, 2*p2+1
    int t = (int)((idx / (Ndim / 4)) % Tdim);
    float4 v = ((const float4*)Q)[idx];
    const float tf = (float)t;
    const float k = -16.0f * 2.0f / (float)Ndim;

    float fr0 = exp2f(k * (float)(2 * p2)) * 0.15915494309189535f;
    float ph0 = tf * fr0;
    ph0 = (ph0 - floorf(ph0)) * 6.283185307179586f;
    float s0, c0;
    __sincosf(ph0, &s0, &c0);

    float fr1 = exp2f(k * (float)(2 * p2 + 1)) * 0.15915494309189535f;
    float ph1 = tf * fr1;
    ph1 = (ph1 - floorf(ph1)) * 6.283185307179586f;
    float s1, c1;
    __sincosf(ph1, &s1, &c1);

    __half2 h0, h1;
    h0.x = __float2half(v.x * c0 - v.y * s0);
    h0.y = __float2half(v.y * c0 + v.x * s0);
    h1.x = __float2half(v.z * c1 - v.w * s1);
    h1.y = __float2half(v.w * c1 + v.z * s1);
    ((__half2*)g_Qh)[idx * 2 + 0] = h0;
    ((__half2*)g_Qh)[idx * 2 + 1] = h1;
}

// ---------------------------------------------------------------------------
// Gate
// ---------------------------------------------------------------------------
__global__ void gate_kernel(const float* __restrict__ traces) {
    int row = blockIdx.x;
    const float* pr = traces + (size_t)row * Ddim;
    float sum = 0.f;
    for (int i = threadIdx.x; i < Ddim; i += 32) sum += pr[i];
#pragma unroll
    for (int o = 16; o; o >>= 1) sum += __shfl_xor_sync(0xffffffffu, sum, o);
    if (threadIdx.x == 0) {
        float m = sum * (1.0f / (float)Ddim);
        float sig = 1.0f / (1.0f + expf(-m));
        g_gate[row] = 0.5f + 0.5f * sig;
    }
}

// ---------------------------------------------------------------------------
// V transpose -> fp16 hi: VT[b][d][s]
// ---------------------------------------------------------------------------
__global__ void vt_kernel(const float* __restrict__ V) {
    __shared__ float tile[32][33];
    const int b = blockIdx.z;
    const int s0 = blockIdx.x * 32, d0 = blockIdx.y * 32;
#pragma unroll
    for (int j = 0; j < 4; j++)
        tile[threadIdx.y + 8 * j][threadIdx.x] =
            V[(size_t)b * Tdim * Ddim + (size_t)(s0 + threadIdx.y + 8 * j) * Ddim +
              d0 + threadIdx.x];
    __syncthreads();
#pragma unroll
    for (int j = 0; j < 4; j++) {
        int d = d0 + threadIdx.y + 8 * j;
        int s = s0 + threadIdx.x;
        float v = tile[threadIdx.x][threadIdx.y + 8 * j];
        g_VTh[(size_t)b * Ddim * Tdim + (size_t)d * Tdim + s] = __float2half(v);
    }
}

// ---------------------------------------------------------------------------
// Common fragment/load geometry: 128x128 tile, 8 warps 2x4, warp 64x32.
// ---------------------------------------------------------------------------
struct FragCtx {
    uint32_t a_off[4];
    uint32_t b_off[2];
    uint32_t sw[4];
    int row[4];
    int colb;
};

__device__ __forceinline__ void frag_setup(FragCtx& f, int tid) {
    const int lid = tid & 31;
    const int wid = tid >> 5;
    const int wr = wid >> 2;
    const int wc = wid & 3;
    const int a_row = wr * 64 + (lid & 15);
    const int a_kb = (lid >> 4) * 16;
#pragma unroll
    for (int mi = 0; mi < 4; mi++)
        f.a_off[mi] = swz((a_row + mi * 16) * 128 + a_kb);
    const int b_row = wc * 32 + (lid & 7) + ((lid >> 4) << 3);
    const int b_kb = ((lid >> 3) & 1) * 16;
#pragma unroll
    for (int nb = 0; nb < 2; nb++)
        f.b_off[nb] = swz((b_row + nb * 16) * 128 + b_kb);
    const int rbase = tid >> 3;
    f.colb = (tid & 7) * 16;
#pragma unroll
    for (int r = 0; r < 4; r++) {
        f.row[r] = rbase + 32 * r;
        f.sw[r] = swz(f.row[r] * 128 + f.colb);
    }
}

// ---------------------------------------------------------------------------
// GEMM1: scores = tril(QR QR^T, -1) * (1+stdp) * gate.  Single fp16 product.
// Stage = Ah(16K)+Bh(16K) = 32KB; 3 stages = 96KB -> 2 CTAs/SM.
// cp.async issue interleaved into the ks loop (no front burst).
// ---------------------------------------------------------------------------
#define STG_SC 32768
#define SMEM_SC (3 * STG_SC)

__global__ __launch_bounds__(256, 2) void scores_tc_kernel(
    float* __restrict__ Sc, const float* __restrict__ stdp_scale) {
    extern __shared__ char smem[];
    const int bh = blockIdx.z;
    const int bt = blockIdx.y;
    const int bs = blockIdx.x;
    float* Sbase = Sc + (size_t)bh * Tdim * Tdim;
    __half* Shb = g_Sh + (size_t)bh * Tdim * Tdim;
    __half* Slb = g_Sl + (size_t)bh * Tdim * Tdim;

    if (bs > bt) {  // strictly-upper tile: zeros
        const int r0 = bt * 128, c0 = bs * 128;
        float4 z = make_float4(0.f, 0.f, 0.f, 0.f);
        for (int i = threadIdx.x; i < 128 * 32; i += 256) {
            int r = i >> 5, c = (i & 31) << 2;
            *(float4*)(Sbase + (size_t)(r0 + r) * Tdim + c0 + c) = z;
        }
        for (int i = threadIdx.x; i < 128 * 16; i += 256) {
            int r = i >> 4, c = (i & 15) << 3;
            size_t o = (size_t)(r0 + r) * Tdim + c0 + c;
            *(uint4*)(Shb + o) = make_uint4(0, 0, 0, 0);
            *(uint4*)(Slb + o) = make_uint4(0, 0, 0, 0);
        }
        return;
    }

    const uint32_t sbase = smem_u32(smem);
    const int tid = threadIdx.x;
    const int wid = tid >> 5;
    const int lid = tid & 31;
    const int wr = wid >> 2;
    const int wc = wid & 3;

    FragCtx f;
    frag_setup(f, tid);

    const size_t rsQ = (size_t)Ndim * 2;
    const char* Ab = (const char*)(g_Qh + ((size_t)bh * Tdim + bt * 128) * Ndim);
    const char* Bb = (const char*)(g_Qh + ((size_t)bh * Tdim + bs * 128) * Ndim);
    const char* pA[4];
    const char* pB[4];
#pragma unroll
    for (int r = 0; r < 4; r++) {
        pA[r] = Ab + (size_t)f.row[r] * rsQ + f.colb;
        pB[r] = Bb + (size_t)f.row[r] * rsQ + f.colb;
    }

    float acc[4][4][4];
#pragma unroll
    for (int i = 0; i < 4; i++)
#pragma unroll
        for (int j = 0; j < 4; j++)
#pragma unroll
            for (int k = 0; k < 4; k++) acc[i][j][k] = 0.f;

    const int NCH = 128;
    // Prologue: chunks 0,1 as bursts.
#pragma unroll
    for (int c = 0; c < 2; c++) {
        uint32_t s0 = sbase + c * STG_SC;
        size_t kb = (size_t)c * 128;
#pragma unroll
        for (int r = 0; r < 4; r++) {
            cp16(s0 + f.sw[r],         pA[r] + kb);
            cp16(s0 + 16384 + f.sw[r], pB[r] + kb);
        }
        asm volatile("cp.async.commit_group;" ::: "memory");
    }

    for (int i = 0; i < NCH; i++) {
        const int st = i % 3;
        asm volatile("cp.async.wait_group 1;" ::: "memory");
        __syncthreads();  // chunk i visible; all warps done with chunk i-1
        const uint32_t s0 = sbase + st * STG_SC;
        const bool pf = (i + 2 < NCH);
        const uint32_t sp = sbase + ((i + 2) % 3) * STG_SC;
        const size_t kb = (size_t)(i + 2) * 128;
#pragma unroll
        for (int ks = 0; ks < 4; ks++) {
            if (pf) {  // interleave 2 of 8 cp.async per ks step
                cp16(sp + f.sw[ks],         pA[ks] + kb);
                cp16(sp + 16384 + f.sw[ks], pB[ks] + kb);
            }
            const uint32_t kx = ks * 32;
            uint32_t ah[4][4], bh2[2][4];
#pragma unroll
            for (int mi = 0; mi < 4; mi++)
                ldm_x4(ah[mi], s0 + (f.a_off[mi] ^ kx));
#pragma unroll
            for (int nb = 0; nb < 2; nb++)
                ldm_x4(bh2[nb], s0 + 16384 + (f.b_off[nb] ^ kx));
#pragma unroll
            for (int mi = 0; mi < 4; mi++) {
                mma16816(acc[mi][0], ah[mi], bh2[0][0], bh2[0][1]);
                mma16816(acc[mi][1], ah[mi], bh2[0][2], bh2[0][3]);
                mma16816(acc[mi][2], ah[mi], bh2[1][0], bh2[1][1]);
                mma16816(acc[mi][3], ah[mi], bh2[1][2], bh2[1][3]);
            }
        }
        asm volatile("cp.async.commit_group;" ::: "memory");
    }

    // Epilogue: mask/stdp/gate; store fp32 + fp16 hi/lo split.
    const float ssc = stdp_scale[0] * 0.01f;
    const int g0 = lid >> 2;
    const int tg = lid & 3;
#pragma unroll
    for (int mi = 0; mi < 4; mi++) {
#pragma unroll
        for (int half = 0; half < 2; half++) {
            const int t = bt * 128 + wr * 64 + mi * 16 + g0 + half * 8;
            const float g = g_gate[bh * Tdim + t];
            const float bco = g * ssc * __expf(-0.05f * (float)t);
            float* rowp = Sbase + (size_t)t * Tdim;
            __half* hrow = Shb + (size_t)t * Tdim;
            __half* lrow = Slb + (size_t)t * Tdim;
#pragma unroll
            for (int ni = 0; ni < 4; ni++) {
                const int s = bs * 128 + wc * 32 + ni * 8 + tg * 2;
                const float e0 = __expf(0.05f * (float)s);
                float v0 = acc[mi][ni][half * 2 + 0];
                float v1 = acc[mi][ni][half * 2 + 1];
                float2 o;
                o.x = (t > s)     ? v0 * fmaf(bco, e0, g) : 0.f;
                o.y = (t > s + 1) ? v1 * fmaf(bco, e0 * 1.0512710963760241f, g)
                                  : 0.f;
                *(float2*)(rowp + s) = o;
                __half2 h, l;
                h.x = __float2half(o.x);
                h.y = __float2half(o.y);
                l.x = __float2half(o.x - __half2float(h.x));
                l.y = __float2half(o.y - __half2float(h.y));
                *(__half2*)(hrow + s) = h;
                *(__half2*)(lrow + s) = l;
            }
        }
    }
}

// ---------------------------------------------------------------------------
// GEMM2: Out = S @ Vh  (exact-S via Sh+Sl, V hi only).
// Stage = Sh(16K)+Sl(16K)+VTh(16K) = 48KB; 3 stages = 144KB.
// ---------------------------------------------------------------------------
#define STG_OUT 49152
#define SMEM_OUT (3 * STG_OUT)

__global__ __launch_bounds__(256) void out_tc_kernel(float* __restrict__ Out) {
    extern __shared__ char smem[];
    const int bh = blockIdx.z;
    const int b = bh / NHdim;
    const int bt = blockIdx.y;
    const int bd = blockIdx.x;

    const uint32_t sbase = smem_u32(smem);
    const int tid = threadIdx.x;
    const int wid = tid >> 5;
    const int lid = tid & 31;
    const int wr = wid >> 2;
    const int wc = wid & 3;

    FragCtx f;
    frag_setup(f, tid);

    const size_t rs = (size_t)Tdim * 2;
    const char* Ahb = (const char*)(g_Sh + ((size_t)bh * Tdim + bt * 128) * Tdim);
    const char* Alb = (const char*)(g_Sl + ((size_t)bh * Tdim + bt * 128) * Tdim);
    const char* Bhb = (const char*)(g_VTh + ((size_t)b * Ddim + bd * 128) * Tdim);
    const char* pAh[4];
    const char* pAl[4];
    const char* pBh[4];
#pragma unroll
    for (int r = 0; r < 4; r++) {
        pAh[r] = Ahb + (size_t)f.row[r] * rs + f.colb;
        pAl[r] = Alb + (size_t)f.row[r] * rs + f.colb;
        pBh[r] = Bhb + (size_t)f.row[r] * rs + f.colb;
    }

    float acc[4][4][4];
#pragma unroll
    for (int i = 0; i < 4; i++)
#pragma unroll
        for (int j = 0; j < 4; j++)
#pragma unroll
            for (int k = 0; k < 4; k++) acc[i][j][k] = 0.f;

    const int NCH = (bt + 1) * 2;  // causal K bound
#pragma unroll
    for (int c = 0; c < 2; c++) {
        uint32_t s0 = sbase + c * STG_OUT;
        size_t kb = (size_t)c * 128;
#pragma unroll
        for (int r = 0; r < 4; r++) {
            cp16(s0 + f.sw[r],         pAh[r] + kb);
            cp16(s0 + 16384 + f.sw[r], pAl[r] + kb);
            cp16(s0 + 32768 + f.sw[r], pBh[r] + kb);
        }
        asm volatile("cp.async.commit_group;" ::: "memory");
    }

    for (int i = 0; i < NCH; i++) {
        const int st = i % 3;
        asm volatile("cp.async.wait_group 1;" ::: "memory");
        __syncthreads();
        const uint32_t s0 = sbase + st * STG_OUT;
        const bool pf = (i + 2 < NCH);
        const uint32_t sp = sbase + ((i + 2) % 3) * STG_OUT;
        const size_t kb = (size_t)(i + 2) * 128;
#pragma unroll
        for (int ks = 0; ks < 4; ks++) {
            if (pf) {  // interleave 3 of 12 cp.async per ks step
                cp16(sp + f.sw[ks],         pAh[ks] + kb);
                cp16(sp + 16384 + f.sw[ks], pAl[ks] + kb);
                cp16(sp + 32768 + f.sw[ks], pBh[ks] + kb);
            }
            const uint32_t kx = ks * 32;
            uint32_t ah[4][4], bh2[2][4];
#pragma unroll
            for (int mi = 0; mi < 4; mi++)
                ldm_x4(ah[mi], s0 + (f.a_off[mi] ^ kx));
#pragma unroll
            for (int nb = 0; nb < 2; nb++)
                ldm_x4(bh2[nb], s0 + 32768 + (f.b_off[nb] ^ kx));
#pragma unroll
            for (int mi = 0; mi < 4; mi++) {
                mma16816(acc[mi][0], ah[mi], bh2[0][0], bh2[0][1]);
                mma16816(acc[mi][1], ah[mi], bh2[0][2], bh2[0][3]);
                mma16816(acc[mi][2], ah[mi], bh2[1][0], bh2[1][1]);
                mma16816(acc[mi][3], ah[mi], bh2[1][2], bh2[1][3]);
            }
            uint32_t al[4][4];
#pragma unroll
            for (int mi = 0; mi < 4; mi++)
                ldm_x4(al[mi], s0 + 16384 + (f.a_off[mi] ^ kx));
#pragma unroll
            for (int mi = 0; mi < 4; mi++) {
                mma16816(acc[mi][0], al[mi], bh2[0][0], bh2[0][1]);
                mma16816(acc[mi][1], al[mi], bh2[0][2], bh2[0][3]);
                mma16816(acc[mi][2], al[mi], bh2[1][0], bh2[1][1]);
                mma16816(acc[mi][3], al[mi], bh2[1][2], bh2[1][3]);
            }
        }
        asm volatile("cp.async.commit_group;" ::: "memory");
    }

    const int g0 = lid >> 2;
    const int tg = lid & 3;
#pragma unroll
    for (int mi = 0; mi < 4; mi++) {
#pragma unroll
        for (int half = 0; half < 2; half++) {
            const int t = bt * 128 + wr * 64 + mi * 16 + g0 + half * 8;
            float* rowp = Out + ((size_t)bh * Tdim + t) * Ddim;
#pragma unroll
            for (int ni = 0; ni < 4; ni++) {
                const int d = bd * 128 + wc * 32 + ni * 8 + tg * 2;
                float2 o;
                o.x = acc[mi][ni][half * 2 + 0];
                o.y = acc[mi][ni][half * 2 + 1];
                *(float2*)(rowp + d) = o;
            }
        }
    }
}

// ---------------------------------------------------------------------------
extern "C" void kernel_launch(void* const* d_in, const int* in_sizes, int n_in,
                              void* d_out, int out_size) {
    const float* Q      = (const float*)d_in[0];
    const float* V      = (const float*)d_in[1];
    const float* traces = (const float*)d_in[2];
    const float* scale  = (const float*)d_in[3];
    float* out = (float*)d_out;

    const size_t OUT_ELEMS = (size_t)BHdim * Tdim * Ddim;
    const size_t SC_ELEMS  = (size_t)BHdim * Tdim * Tdim;

    float* scores;
    if ((size_t)out_size >= OUT_ELEMS + SC_ELEMS) {
        scores = out + OUT_ELEMS;
    } else {
        void* p = nullptr;
        cudaGetSymbolAddress(&p, g_S_fallback);
        scores = (float*)p;
    }

    static bool attr_set = false;
    if (!attr_set) {
        cudaFuncSetAttribute(scores_tc_kernel,
                             cudaFuncAttributeMaxDynamicSharedMemorySize,
                             SMEM_SC);
        cudaFuncSetAttribute(out_tc_kernel,
                             cudaFuncAttributeMaxDynamicSharedMemorySize,
                             SMEM_OUT);
        attr_set = true;
    }

    const size_t nq = (size_t)BHdim * Tdim * (Ndim / 4);
    rope_kernel<<<(unsigned)((nq + 255) / 256), 256>>>(Q);
    gate_kernel<<<BHdim * Tdim, 32>>>(traces);
    dim3 gv(Tdim / 32, Ddim / 32, Bdim);
    vt_kernel<<<gv, dim3(32, 8)>>>(V);

    dim3 g1(Tdim / 128, Tdim / 128, BHdim);
    scores_tc_kernel<<<g1, 256, SMEM_SC>>>(scores, scale);

    dim3 g2(Ddim / 128, Tdim / 128, BHdim);
    out_tc_kernel<<<g2, 256, SMEM_OUT>>>(out);
}

// round 11
// speedup vs baseline: 8.0813x; 1.0647x over previous
#include <cuda_runtime.h>
#include <cuda_fp16.h>
#include <math.h>
#include <stdint.h>

#define Bdim 2
#define NHdim 4
#define Tdim 1024
#define Ndim 8192
#define Ddim 256
#define BHdim (Bdim * NHdim)

// Scratch (no cudaMalloc allowed)
static __device__ __half g_Qh[67108864];  // [BH, T, N] rope(Q) fp16, 128 MB
static __device__ __half g_Sh[8388608];   // [BH, T, T] scores fp16
static __device__ __half g_VTh[Bdim * Ddim * Tdim];  // [B, D, T] V^T fp16
static __device__ float g_gate[BHdim * Tdim];
static __device__ float g_S_fallback[8388608];

// ---------------------------------------------------------------------------
// PTX helpers (baseline sm_80+ ISA: cp.async, ldmatrix, mma.sync)
// ---------------------------------------------------------------------------
__device__ __forceinline__ uint32_t smem_u32(const void* p) {
    uint32_t a;
    asm("{ .reg .u64 t; cvta.to.shared.u64 t, %1; cvt.u32.u64 %0, t; }"
        : "=r"(a) : "l"(p));
    return a;
}
__device__ __forceinline__ void cp16(uint32_t s, const void* g) {
    asm volatile("cp.async.cg.shared.global [%0], [%1], 16;" :: "r"(s), "l"(g)
                 : "memory");
}
__device__ __forceinline__ void ldm_x4(uint32_t* r, uint32_t addr) {
    asm volatile(
        "ldmatrix.sync.aligned.m8n8.x4.shared.b16 {%0,%1,%2,%3}, [%4];"
        : "=r"(r[0]), "=r"(r[1]), "=r"(r[2]), "=r"(r[3]) : "r"(addr));
}
__device__ __forceinline__ void mma16816(float* c, const uint32_t* a,
                                         uint32_t b0, uint32_t b1) {
    asm volatile(
        "mma.sync.aligned.m16n8k16.row.col.f32.f16.f16.f32 "
        "{%0,%1,%2,%3}, {%4,%5,%6,%7}, {%8,%9}, {%0,%1,%2,%3};"
        : "+f"(c[0]), "+f"(c[1]), "+f"(c[2]), "+f"(c[3])
        : "r"(a[0]), "r"(a[1]), "r"(a[2]), "r"(a[3]), "r"(b0), "r"(b1));
}
__device__ __forceinline__ uint32_t swz(uint32_t off) {
    return off ^ ((off >> 3) & 0x70);  // SW128
}

// ---------------------------------------------------------------------------
// RoPE -> fp16 (hi only). float4: each thread handles 2 rotation pairs.
// ---------------------------------------------------------------------------
__global__ void rope_kernel(const float* __restrict__ Q) {
    size_t idx = (size_t)blockIdx.x * blockDim.x + threadIdx.x;
    const size_t NQ = (size_t)BHdim * Tdim * (Ndim / 4);
    if (idx >= NQ) return;
    int p2 = (int)(idx % (Ndim / 4));
    int t = (int)((idx / (Ndim / 4)) % Tdim);
    float4 v = ((const float4*)Q)[idx];
    const float tf = (float)t;
    const float k = -16.0f * 2.0f / (float)Ndim;

    float fr0 = exp2f(k * (float)(2 * p2)) * 0.15915494309189535f;
    float ph0 = tf * fr0;
    ph0 = (ph0 - floorf(ph0)) * 6.283185307179586f;
    float s0, c0;
    __sincosf(ph0, &s0, &c0);

    float fr1 = exp2f(k * (float)(2 * p2 + 1)) * 0.15915494309189535f;
    float ph1 = tf * fr1;
    ph1 = (ph1 - floorf(ph1)) * 6.283185307179586f;
    float s1, c1;
    __sincosf(ph1, &s1, &c1);

    __half2 h0, h1;
    h0.x = __float2half(v.x * c0 - v.y * s0);
    h0.y = __float2half(v.y * c0 + v.x * s0);
    h1.x = __float2half(v.z * c1 - v.w * s1);
    h1.y = __float2half(v.w * c1 + v.z * s1);
    ((__half2*)g_Qh)[idx * 2 + 0] = h0;
    ((__half2*)g_Qh)[idx * 2 + 1] = h1;
}

// ---------------------------------------------------------------------------
// Gate
// ---------------------------------------------------------------------------
__global__ void gate_kernel(const float* __restrict__ traces) {
    int row = blockIdx.x;
    const float* pr = traces + (size_t)row * Ddim;
    float sum = 0.f;
    for (int i = threadIdx.x; i < Ddim; i += 32) sum += pr[i];
#pragma unroll
    for (int o = 16; o; o >>= 1) sum += __shfl_xor_sync(0xffffffffu, sum, o);
    if (threadIdx.x == 0) {
        float m = sum * (1.0f / (float)Ddim);
        float sig = 1.0f / (1.0f + expf(-m));
        g_gate[row] = 0.5f + 0.5f * sig;
    }
}

// ---------------------------------------------------------------------------
// V transpose -> fp16: VT[b][d][s]
// ---------------------------------------------------------------------------
__global__ void vt_kernel(const float* __restrict__ V) {
    __shared__ float tile[32][33];
    const int b = blockIdx.z;
    const int s0 = blockIdx.x * 32, d0 = blockIdx.y * 32;
#pragma unroll
    for (int j = 0; j < 4; j++)
        tile[threadIdx.y + 8 * j][threadIdx.x] =
            V[(size_t)b * Tdim * Ddim + (size_t)(s0 + threadIdx.y + 8 * j) * Ddim +
              d0 + threadIdx.x];
    __syncthreads();
#pragma unroll
    for (int j = 0; j < 4; j++) {
        int d = d0 + threadIdx.y + 8 * j;
        int s = s0 + threadIdx.x;
        float v = tile[threadIdx.x][threadIdx.y + 8 * j];
        g_VTh[(size_t)b * Ddim * Tdim + (size_t)d * Tdim + s] = __float2half(v);
    }
}

// ---------------------------------------------------------------------------
// Common fragment/load geometry: 128x128 tile, 8 warps 2x4, warp 64x32.
// ---------------------------------------------------------------------------
struct FragCtx {
    uint32_t a_off[4];
    uint32_t b_off[2];
    uint32_t sw[4];
    int row[4];
    int colb;
};

__device__ __forceinline__ void frag_setup(FragCtx& f, int tid) {
    const int lid = tid & 31;
    const int wid = tid >> 5;
    const int wr = wid >> 2;
    const int wc = wid & 3;
    const int a_row = wr * 64 + (lid & 15);
    const int a_kb = (lid >> 4) * 16;
#pragma unroll
    for (int mi = 0; mi < 4; mi++)
        f.a_off[mi] = swz((a_row + mi * 16) * 128 + a_kb);
    const int b_row = wc * 32 + (lid & 7) + ((lid >> 4) << 3);
    const int b_kb = ((lid >> 3) & 1) * 16;
#pragma unroll
    for (int nb = 0; nb < 2; nb++)
        f.b_off[nb] = swz((b_row + nb * 16) * 128 + b_kb);
    const int rbase = tid >> 3;
    f.colb = (tid & 7) * 16;
#pragma unroll
    for (int r = 0; r < 4; r++) {
        f.row[r] = rbase + 32 * r;
        f.sw[r] = swz(f.row[r] * 128 + f.colb);
    }
}

// One ks compute step: B first, then alternate A-load / 4xMMA with 2 buffers.
__device__ __forceinline__ void ks_step(const FragCtx& f, uint32_t s0,
                                        uint32_t bsm, uint32_t kx,
                                        float acc[4][4][4]) {
    uint32_t b0[4], b1[4];
    ldm_x4(b0, bsm + (f.b_off[0] ^ kx));
    ldm_x4(b1, bsm + (f.b_off[1] ^ kx));
    uint32_t a0[4], a1[4];
    ldm_x4(a0, s0 + (f.a_off[0] ^ kx));
    ldm_x4(a1, s0 + (f.a_off[1] ^ kx));
    mma16816(acc[0][0], a0, b0[0], b0[1]);
    mma16816(acc[0][1], a0, b0[2], b0[3]);
    mma16816(acc[0][2], a0, b1[0], b1[1]);
    mma16816(acc[0][3], a0, b1[2], b1[3]);
    ldm_x4(a0, s0 + (f.a_off[2] ^ kx));
    mma16816(acc[1][0], a1, b0[0], b0[1]);
    mma16816(acc[1][1], a1, b0[2], b0[3]);
    mma16816(acc[1][2], a1, b1[0], b1[1]);
    mma16816(acc[1][3], a1, b1[2], b1[3]);
    ldm_x4(a1, s0 + (f.a_off[3] ^ kx));
    mma16816(acc[2][0], a0, b0[0], b0[1]);
    mma16816(acc[2][1], a0, b0[2], b0[3]);
    mma16816(acc[2][2], a0, b1[0], b1[1]);
    mma16816(acc[2][3], a0, b1[2], b1[3]);
    mma16816(acc[3][0], a1, b0[0], b0[1]);
    mma16816(acc[3][1], a1, b0[2], b0[3]);
    mma16816(acc[3][2], a1, b1[0], b1[1]);
    mma16816(acc[3][3], a1, b1[2], b1[3]);
}

// ---------------------------------------------------------------------------
// GEMM1: scores = tril(QR QR^T, -1) * (1+stdp) * gate.  Single fp16 product.
// Stage = Ah(16K)+Bh(16K) = 32KB; 3 stages = 96KB -> 2 CTAs/SM.
// ---------------------------------------------------------------------------
#define STG_SC 32768
#define SMEM_SC (3 * STG_SC)

__global__ __launch_bounds__(256, 2) void scores_tc_kernel(
    float* __restrict__ Sc, const float* __restrict__ stdp_scale) {
    extern __shared__ char smem[];
    const int bh = blockIdx.z;
    const int bt = blockIdx.y;
    const int bs = blockIdx.x;
    float* Sbase = Sc + (size_t)bh * Tdim * Tdim;
    __half* Shb = g_Sh + (size_t)bh * Tdim * Tdim;

    if (bs > bt) {  // strictly-upper tile: zeros
        const int r0 = bt * 128, c0 = bs * 128;
        float4 z = make_float4(0.f, 0.f, 0.f, 0.f);
        for (int i = threadIdx.x; i < 128 * 32; i += 256) {
            int r = i >> 5, c = (i & 31) << 2;
            *(float4*)(Sbase + (size_t)(r0 + r) * Tdim + c0 + c) = z;
        }
        for (int i = threadIdx.x; i < 128 * 16; i += 256) {
            int r = i >> 4, c = (i & 15) << 3;
            *(uint4*)(Shb + (size_t)(r0 + r) * Tdim + c0 + c) =
                make_uint4(0, 0, 0, 0);
        }
        return;
    }

    const uint32_t sbase = smem_u32(smem);
    const int tid = threadIdx.x;
    const int wid = tid >> 5;
    const int lid = tid & 31;
    const int wr = wid >> 2;
    const int wc = wid & 3;

    FragCtx f;
    frag_setup(f, tid);

    const size_t rsQ = (size_t)Ndim * 2;
    const char* Ab = (const char*)(g_Qh + ((size_t)bh * Tdim + bt * 128) * Ndim);
    const char* Bb = (const char*)(g_Qh + ((size_t)bh * Tdim + bs * 128) * Ndim);
    const char* pA[4];
    const char* pB[4];
#pragma unroll
    for (int r = 0; r < 4; r++) {
        pA[r] = Ab + (size_t)f.row[r] * rsQ + f.colb;
        pB[r] = Bb + (size_t)f.row[r] * rsQ + f.colb;
    }

    float acc[4][4][4];
#pragma unroll
    for (int i = 0; i < 4; i++)
#pragma unroll
        for (int j = 0; j < 4; j++)
#pragma unroll
            for (int k = 0; k < 4; k++) acc[i][j][k] = 0.f;

    const int NCH = 128;
#pragma unroll
    for (int c = 0; c < 2; c++) {
        uint32_t s0 = sbase + c * STG_SC;
        size_t kb = (size_t)c * 128;
#pragma unroll
        for (int r = 0; r < 4; r++) {
            cp16(s0 + f.sw[r],         pA[r] + kb);
            cp16(s0 + 16384 + f.sw[r], pB[r] + kb);
        }
        asm volatile("cp.async.commit_group;" ::: "memory");
    }

    int st = 0, stp = 2;  // current stage, prefetch stage
    for (int i = 0; i < NCH; i++) {
        asm volatile("cp.async.wait_group 1;" ::: "memory");
        __syncthreads();
        const uint32_t s0 = sbase + st * STG_SC;
        const bool pf = (i + 2 < NCH);
        const uint32_t sp = sbase + stp * STG_SC;
        const size_t kb = (size_t)(i + 2) * 128;
#pragma unroll
        for (int ks = 0; ks < 4; ks++) {
            if (pf) {
                cp16(sp + f.sw[ks],         pA[ks] + kb);
                cp16(sp + 16384 + f.sw[ks], pB[ks] + kb);
            }
            ks_step(f, s0, s0 + 16384, ks * 32, acc);
        }
        asm volatile("cp.async.commit_group;" ::: "memory");
        st = (st == 2) ? 0 : st + 1;
        stp = (stp == 2) ? 0 : stp + 1;
    }

    // Epilogue: mask/stdp/gate; store fp32 + fp16.
    const float ssc = stdp_scale[0] * 0.01f;
    const int g0 = lid >> 2;
    const int tg = lid & 3;
#pragma unroll
    for (int mi = 0; mi < 4; mi++) {
#pragma unroll
        for (int half = 0; half < 2; half++) {
            const int t = bt * 128 + wr * 64 + mi * 16 + g0 + half * 8;
            const float g = g_gate[bh * Tdim + t];
            const float bco = g * ssc * __expf(-0.05f * (float)t);
            float* rowp = Sbase + (size_t)t * Tdim;
            __half* hrow = Shb + (size_t)t * Tdim;
#pragma unroll
            for (int ni = 0; ni < 4; ni++) {
                const int s = bs * 128 + wc * 32 + ni * 8 + tg * 2;
                const float e0 = __expf(0.05f * (float)s);
                float v0 = acc[mi][ni][half * 2 + 0];
                float v1 = acc[mi][ni][half * 2 + 1];
                float2 o;
                o.x = (t > s)     ? v0 * fmaf(bco, e0, g) : 0.f;
                o.y = (t > s + 1) ? v1 * fmaf(bco, e0 * 1.0512710963760241f, g)
                                  : 0.f;
                *(float2*)(rowp + s) = o;
                __half2 h;
                h.x = __float2half(o.x);
                h.y = __float2half(o.y);
                *(__half2*)(hrow + s) = h;
            }
        }
    }
}

// ---------------------------------------------------------------------------
// GEMM2: Out = Sh @ VTh (single fp16 product).
// Stage = Sh(16K)+VTh(16K) = 32KB; 3 stages = 96KB -> 2 CTAs/SM.
// ---------------------------------------------------------------------------
#define STG_OUT 32768
#define SMEM_OUT (3 * STG_OUT)

__global__ __launch_bounds__(256, 2) void out_tc_kernel(float* __restrict__ Out) {
    extern __shared__ char smem[];
    const int bh = blockIdx.z;
    const int b = bh / NHdim;
    const int bt = blockIdx.y;
    const int bd = blockIdx.x;

    const uint32_t sbase = smem_u32(smem);
    const int tid = threadIdx.x;
    const int wid = tid >> 5;
    const int lid = tid & 31;
    const int wr = wid >> 2;
    const int wc = wid & 3;

    FragCtx f;
    frag_setup(f, tid);

    const size_t rs = (size_t)Tdim * 2;
    const char* Ahb = (const char*)(g_Sh + ((size_t)bh * Tdim + bt * 128) * Tdim);
    const char* Bhb = (const char*)(g_VTh + ((size_t)b * Ddim + bd * 128) * Tdim);
    const char* pA[4];
    const char* pB[4];
#pragma unroll
    for (int r = 0; r < 4; r++) {
        pA[r] = Ahb + (size_t)f.row[r] * rs + f.colb;
        pB[r] = Bhb + (size_t)f.row[r] * rs + f.colb;
    }

    float acc[4][4][4];
#pragma unroll
    for (int i = 0; i < 4; i++)
#pragma unroll
        for (int j = 0; j < 4; j++)
#pragma unroll
            for (int k = 0; k < 4; k++) acc[i][j][k] = 0.f;

    const int NCH = (bt + 1) * 2;  // causal K bound
#pragma unroll
    for (int c = 0; c < 2; c++) {
        uint32_t s0 = sbase + c * STG_OUT;
        size_t kb = (size_t)c * 128;
#pragma unroll
        for (int r = 0; r < 4; r++) {
            cp16(s0 + f.sw[r],         pA[r] + kb);
            cp16(s0 + 16384 + f.sw[r], pB[r] + kb);
        }
        asm volatile("cp.async.commit_group;" ::: "memory");
    }

    int st = 0, stp = 2;
    for (int i = 0; i < NCH; i++) {
        asm volatile("cp.async.wait_group 1;" ::: "memory");
        __syncthreads();
        const uint32_t s0 = sbase + st * STG_OUT;
        const bool pf = (i + 2 < NCH);
        const uint32_t sp = sbase + stp * STG_OUT;
        const size_t kb = (size_t)(i + 2) * 128;
#pragma unroll
        for (int ks = 0; ks < 4; ks++) {
            if (pf) {
                cp16(sp + f.sw[ks],         pA[ks] + kb);
                cp16(sp + 16384 + f.sw[ks], pB[ks] + kb);
            }
            ks_step(f, s0, s0 + 16384, ks * 32, acc);
        }
        asm volatile("cp.async.commit_group;" ::: "memory");
        st = (st == 2) ? 0 : st + 1;
        stp = (stp == 2) ? 0 : stp + 1;
    }

    const int g0 = lid >> 2;
    const int tg = lid & 3;
#pragma unroll
    for (int mi = 0; mi < 4; mi++) {
#pragma unroll
        for (int half = 0; half < 2; half++) {
            const int t = bt * 128 + wr * 64 + mi * 16 + g0 + half * 8;
            float* rowp = Out + ((size_t)bh * Tdim + t) * Ddim;
#pragma unroll
            for (int ni = 0; ni < 4; ni++) {
                const int d = bd * 128 + wc * 32 + ni * 8 + tg * 2;
                float2 o;
                o.x = acc[mi][ni][half * 2 + 0];
                o.y = acc[mi][ni][half * 2 + 1];
                *(float2*)(rowp + d) = o;
            }
        }
    }
}

// ---------------------------------------------------------------------------
extern "C" void kernel_launch(void* const* d_in, const int* in_sizes, int n_in,
                              void* d_out, int out_size) {
    const float* Q      = (const float*)d_in[0];
    const float* V      = (const float*)d_in[1];
    const float* traces = (const float*)d_in[2];
    const float* scale  = (const float*)d_in[3];
    float* out = (float*)d_out;

    const size_t OUT_ELEMS = (size_t)BHdim * Tdim * Ddim;
    const size_t SC_ELEMS  = (size_t)BHdim * Tdim * Tdim;

    float* scores;
    if ((size_t)out_size >= OUT_ELEMS + SC_ELEMS) {
        scores = out + OUT_ELEMS;
    } else {
        void* p = nullptr;
        cudaGetSymbolAddress(&p, g_S_fallback);
        scores = (float*)p;
    }

    static bool attr_set = false;
    if (!attr_set) {
        cudaFuncSetAttribute(scores_tc_kernel,
                             cudaFuncAttributeMaxDynamicSharedMemorySize,
                             SMEM_SC);
        cudaFuncSetAttribute(out_tc_kernel,
                             cudaFuncAttributeMaxDynamicSharedMemorySize,
                             SMEM_OUT);
        attr_set = true;
    }

    const size_t nq = (size_t)BHdim * Tdim * (Ndim / 4);
    rope_kernel<<<(unsigned)((nq + 255) / 256), 256>>>(Q);
    gate_kernel<<<BHdim * Tdim, 32>>>(traces);
    dim3 gv(Tdim / 32, Ddim / 32, Bdim);
    vt_kernel<<<gv, dim3(32, 8)>>>(V);

    dim3 g1(Tdim / 128, Tdim / 128, BHdim);
    scores_tc_kernel<<<g1, 256, SMEM_SC>>>(scores, scale);

    dim3 g2(Ddim / 128, Tdim / 128, BHdim);
    out_tc_kernel<<<g2, 256, SMEM_OUT>>>(out);
}

// round 12
// speedup vs baseline: 8.3372x; 1.0317x over previous
#include <cuda_runtime.h>
#include <cuda_fp16.h>
#include <math.h>
#include <stdint.h>

#define Bdim 2
#define NHdim 4
#define Tdim 1024
#define Ndim 8192
#define Ddim 256
#define BHdim (Bdim * NHdim)

// Scratch (no cudaMalloc allowed)
static __device__ __half g_Qh[67108864];  // [BH, T, N] rope(Q) fp16, 128 MB
static __device__ __half g_Sh[8388608];   // [BH, T, T] scores fp16
static __device__ __half g_VTh[Bdim * Ddim * Tdim];  // [B, D, T] V^T fp16
static __device__ float g_gate[BHdim * Tdim];
static __device__ float g_S_fallback[8388608];

// ---------------------------------------------------------------------------
// PTX helpers
// ---------------------------------------------------------------------------
__device__ __forceinline__ uint32_t smem_u32(const void* p) {
    uint32_t a;
    asm("{ .reg .u64 t; cvta.to.shared.u64 t, %1; cvt.u32.u64 %0, t; }"
        : "=r"(a) : "l"(p));
    return a;
}
__device__ __forceinline__ void cp16(uint32_t s, const void* g) {
    asm volatile("cp.async.cg.shared.global [%0], [%1], 16;" :: "r"(s), "l"(g)
                 : "memory");
}
__device__ __forceinline__ void ldm_x4(uint32_t* r, uint32_t addr) {
    asm volatile(
        "ldmatrix.sync.aligned.m8n8.x4.shared.b16 {%0,%1,%2,%3}, [%4];"
        : "=r"(r[0]), "=r"(r[1]), "=r"(r[2]), "=r"(r[3]) : "r"(addr));
}
__device__ __forceinline__ void mma16816(float* c, const uint32_t* a,
                                         uint32_t b0, uint32_t b1) {
    asm volatile(
        "mma.sync.aligned.m16n8k16.row.col.f32.f16.f16.f32 "
        "{%0,%1,%2,%3}, {%4,%5,%6,%7}, {%8,%9}, {%0,%1,%2,%3};"
        : "+f"(c[0]), "+f"(c[1]), "+f"(c[2]), "+f"(c[3])
        : "r"(a[0]), "r"(a[1]), "r"(a[2]), "r"(a[3]), "r"(b0), "r"(b1));
}
__device__ __forceinline__ uint32_t swz(uint32_t off) {
    return off ^ ((off >> 3) & 0x70);  // SW128
}

// ---------------------------------------------------------------------------
// RoPE -> fp16
// ---------------------------------------------------------------------------
__global__ void rope_kernel(const float* __restrict__ Q) {
    size_t idx = (size_t)blockIdx.x * blockDim.x + threadIdx.x;
    const size_t NQ = (size_t)BHdim * Tdim * (Ndim / 4);
    if (idx >= NQ) return;
    int p2 = (int)(idx % (Ndim / 4));
    int t = (int)((idx / (Ndim / 4)) % Tdim);
    float4 v = ((const float4*)Q)[idx];
    const float tf = (float)t;
    const float k = -16.0f * 2.0f / (float)Ndim;

    float fr0 = exp2f(k * (float)(2 * p2)) * 0.15915494309189535f;
    float ph0 = tf * fr0;
    ph0 = (ph0 - floorf(ph0)) * 6.283185307179586f;
    float s0, c0;
    __sincosf(ph0, &s0, &c0);

    float fr1 = exp2f(k * (float)(2 * p2 + 1)) * 0.15915494309189535f;
    float ph1 = tf * fr1;
    ph1 = (ph1 - floorf(ph1)) * 6.283185307179586f;
    float s1, c1;
    __sincosf(ph1, &s1, &c1);

    __half2 h0, h1;
    h0.x = __float2half(v.x * c0 - v.y * s0);
    h0.y = __float2half(v.y * c0 + v.x * s0);
    h1.x = __float2half(v.z * c1 - v.w * s1);
    h1.y = __float2half(v.w * c1 + v.z * s1);
    ((__half2*)g_Qh)[idx * 2 + 0] = h0;
    ((__half2*)g_Qh)[idx * 2 + 1] = h1;
}

// ---------------------------------------------------------------------------
// Gate
// ---------------------------------------------------------------------------
__global__ void gate_kernel(const float* __restrict__ traces) {
    int row = blockIdx.x;
    const float* pr = traces + (size_t)row * Ddim;
    float sum = 0.f;
    for (int i = threadIdx.x; i < Ddim; i += 32) sum += pr[i];
#pragma unroll
    for (int o = 16; o; o >>= 1) sum += __shfl_xor_sync(0xffffffffu, sum, o);
    if (threadIdx.x == 0) {
        float m = sum * (1.0f / (float)Ddim);
        float sig = 1.0f / (1.0f + expf(-m));
        g_gate[row] = 0.5f + 0.5f * sig;
    }
}

// ---------------------------------------------------------------------------
// V transpose -> fp16: VT[b][d][s]
// ---------------------------------------------------------------------------
__global__ void vt_kernel(const float* __restrict__ V) {
    __shared__ float tile[32][33];
    const int b = blockIdx.z;
    const int s0 = blockIdx.x * 32, d0 = blockIdx.y * 32;
#pragma unroll
    for (int j = 0; j < 4; j++)
        tile[threadIdx.y + 8 * j][threadIdx.x] =
            V[(size_t)b * Tdim * Ddim + (size_t)(s0 + threadIdx.y + 8 * j) * Ddim +
              d0 + threadIdx.x];
    __syncthreads();
#pragma unroll
    for (int j = 0; j < 4; j++) {
        int d = d0 + threadIdx.y + 8 * j;
        int s = s0 + threadIdx.x;
        float v = tile[threadIdx.x][threadIdx.y + 8 * j];
        g_VTh[(size_t)b * Ddim * Tdim + (size_t)d * Tdim + s] = __float2half(v);
    }
}

// ===========================================================================
// SCORES: 128x128 tile, 4 warps (2x2), warp tile 64x64, 2 CTAs/SM.
// Stage = A(16K)+B(16K) = 32KB; 3 stages = 96KB.
// ===========================================================================
#define STG_SC 32768
#define SMEM_SC (3 * STG_SC)

struct Frag4 {
    uint32_t a_off[4];   // 4 m16 tiles (64 rows)
    uint32_t b_off[4];   // 4 n16 tiles (64 cols)
    uint32_t sw[8];      // 8 load lines per thread
    uint32_t gof[8];     // global offsets (row*rsQ + colb), rsQ = 16384
};

__device__ __forceinline__ void frag4_setup(Frag4& f, int tid, uint32_t rstride) {
    const int lid = tid & 31;
    const int wid = tid >> 5;
    const int wr = wid >> 1;  // 0-1: rows wr*64
    const int wc = wid & 1;   // 0-1: cols wc*64
    const int a_row = wr * 64 + (lid & 15);
    const int a_kb = (lid >> 4) * 16;
#pragma unroll
    for (int mi = 0; mi < 4; mi++)
        f.a_off[mi] = swz((a_row + mi * 16) * 128 + a_kb);
    const int b_row = wc * 64 + (lid & 7) + ((lid >> 4) << 3);
    const int b_kb = ((lid >> 3) & 1) * 16;
#pragma unroll
    for (int nb = 0; nb < 4; nb++)
        f.b_off[nb] = swz((b_row + nb * 16) * 128 + b_kb);
    const int rbase = tid >> 3;          // 0..15
    const int colb = (tid & 7) * 16;
#pragma unroll
    for (int r = 0; r < 8; r++) {
        int row = rbase + 16 * r;
        f.sw[r] = swz(row * 128 + colb);
        f.gof[r] = (uint32_t)row * rstride + colb;
    }
}

// One ks step for 64x64 warp tile: 4 B ldm, 4 A ldm (2-buffer), 32 MMA.
__device__ __forceinline__ void ks4_step(const Frag4& f, uint32_t asm_,
                                         uint32_t bsm, uint32_t kx,
                                         float acc[4][8][4]) {
    uint32_t b[4][4];
#pragma unroll
    for (int nb = 0; nb < 4; nb++) ldm_x4(b[nb], bsm + (f.b_off[nb] ^ kx));
    uint32_t a0[4], a1[4];
    ldm_x4(a0, asm_ + (f.a_off[0] ^ kx));
    ldm_x4(a1, asm_ + (f.a_off[1] ^ kx));
#pragma unroll
    for (int nb = 0; nb < 4; nb++) {
        mma16816(acc[0][2 * nb + 0], a0, b[nb][0], b[nb][1]);
        mma16816(acc[0][2 * nb + 1], a0, b[nb][2], b[nb][3]);
    }
    ldm_x4(a0, asm_ + (f.a_off[2] ^ kx));
#pragma unroll
    for (int nb = 0; nb < 4; nb++) {
        mma16816(acc[1][2 * nb + 0], a1, b[nb][0], b[nb][1]);
        mma16816(acc[1][2 * nb + 1], a1, b[nb][2], b[nb][3]);
    }
    ldm_x4(a1, asm_ + (f.a_off[3] ^ kx));
#pragma unroll
    for (int nb = 0; nb < 4; nb++) {
        mma16816(acc[2][2 * nb + 0], a0, b[nb][0], b[nb][1]);
        mma16816(acc[2][2 * nb + 1], a0, b[nb][2], b[nb][3]);
    }
#pragma unroll
    for (int nb = 0; nb < 4; nb++) {
        mma16816(acc[3][2 * nb + 0], a1, b[nb][0], b[nb][1]);
        mma16816(acc[3][2 * nb + 1], a1, b[nb][2], b[nb][3]);
    }
}

__global__ __launch_bounds__(128, 2) void scores_tc_kernel(
    float* __restrict__ Sc, const float* __restrict__ stdp_scale) {
    extern __shared__ char smem[];
    const int bh = blockIdx.z;
    const int bt = blockIdx.y;
    const int bs = blockIdx.x;
    float* Sbase = Sc + (size_t)bh * Tdim * Tdim;
    __half* Shb = g_Sh + (size_t)bh * Tdim * Tdim;

    if (bs > bt) {  // strictly-upper tile: zeros
        const int r0 = bt * 128, c0 = bs * 128;
        float4 z = make_float4(0.f, 0.f, 0.f, 0.f);
        for (int i = threadIdx.x; i < 128 * 32; i += 128) {
            int r = i >> 5, c = (i & 31) << 2;
            *(float4*)(Sbase + (size_t)(r0 + r) * Tdim + c0 + c) = z;
        }
        for (int i = threadIdx.x; i < 128 * 16; i += 128) {
            int r = i >> 4, c = (i & 15) << 3;
            *(uint4*)(Shb + (size_t)(r0 + r) * Tdim + c0 + c) =
                make_uint4(0, 0, 0, 0);
        }
        return;
    }

    const uint32_t sbase = smem_u32(smem);
    const int tid = threadIdx.x;
    const int wid = tid >> 5;
    const int lid = tid & 31;
    const int wr = wid >> 1;
    const int wc = wid & 1;

    Frag4 f;
    frag4_setup(f, tid, (uint32_t)Ndim * 2);

    const char* Ab = (const char*)(g_Qh + ((size_t)bh * Tdim + bt * 128) * Ndim);
    const char* Bb = (const char*)(g_Qh + ((size_t)bh * Tdim + bs * 128) * Ndim);

    float acc[4][8][4];
#pragma unroll
    for (int i = 0; i < 4; i++)
#pragma unroll
        for (int j = 0; j < 8; j++)
#pragma unroll
            for (int k = 0; k < 4; k++) acc[i][j][k] = 0.f;

    const int NCH = 128;
    // Prologue: chunks 0,1 full bursts (8 A lines + 8 B lines per thread).
#pragma unroll
    for (int c = 0; c < 2; c++) {
        uint32_t s0 = sbase + c * STG_SC;
        size_t kb = (size_t)c * 128;
#pragma unroll
        for (int r = 0; r < 8; r++) {
            cp16(s0 + f.sw[r],         Ab + f.gof[r] + kb);
            cp16(s0 + 16384 + f.sw[r], Bb + f.gof[r] + kb);
        }
        asm volatile("cp.async.commit_group;" ::: "memory");
    }

    int st = 0, stp = 2;
    for (int i = 0; i < NCH; i++) {
        asm volatile("cp.async.wait_group 1;" ::: "memory");
        __syncthreads();
        const uint32_t s0 = sbase + st * STG_SC;
        const bool pf = (i + 2 < NCH);
        const uint32_t sp = sbase + stp * STG_SC;
        const size_t kb = (size_t)(i + 2) * 128;
#pragma unroll
        for (int ks = 0; ks < 4; ks++) {
            if (pf) {  // 4 of 16 cp.async per ks step
                cp16(sp + f.sw[2 * ks],             Ab + f.gof[2 * ks] + kb);
                cp16(sp + f.sw[2 * ks + 1],         Ab + f.gof[2 * ks + 1] + kb);
                cp16(sp + 16384 + f.sw[2 * ks],     Bb + f.gof[2 * ks] + kb);
                cp16(sp + 16384 + f.sw[2 * ks + 1], Bb + f.gof[2 * ks + 1] + kb);
            }
            ks4_step(f, s0, s0 + 16384, ks * 32, acc);
        }
        asm volatile("cp.async.commit_group;" ::: "memory");
        st = (st == 2) ? 0 : st + 1;
        stp = (stp == 2) ? 0 : stp + 1;
    }

    // Epilogue: mask/stdp/gate; store fp32 + fp16.
    const float ssc = stdp_scale[0] * 0.01f;
    const int g0 = lid >> 2;
    const int tg = lid & 3;
#pragma unroll
    for (int mi = 0; mi < 4; mi++) {
#pragma unroll
        for (int half = 0; half < 2; half++) {
            const int t = bt * 128 + wr * 64 + mi * 16 + g0 + half * 8;
            const float g = g_gate[bh * Tdim + t];
            const float bco = g * ssc * __expf(-0.05f * (float)t);
            float* rowp = Sbase + (size_t)t * Tdim;
            __half* hrow = Shb + (size_t)t * Tdim;
#pragma unroll
            for (int ni = 0; ni < 8; ni++) {
                const int s = bs * 128 + wc * 64 + ni * 8 + tg * 2;
                const float e0 = __expf(0.05f * (float)s);
                float v0 = acc[mi][ni][half * 2 + 0];
                float v1 = acc[mi][ni][half * 2 + 1];
                float2 o;
                o.x = (t > s)     ? v0 * fmaf(bco, e0, g) : 0.f;
                o.y = (t > s + 1) ? v1 * fmaf(bco, e0 * 1.0512710963760241f, g)
                                  : 0.f;
                *(float2*)(rowp + s) = o;
                __half2 h;
                h.x = __float2half(o.x);
                h.y = __float2half(o.y);
                *(__half2*)(hrow + s) = h;
            }
        }
    }
}

// ===========================================================================
// GEMM2 (unchanged r11 geometry): 8 warps 2x4, warp 64x32, single product.
// ===========================================================================
struct FragCtx {
    uint32_t a_off[4];
    uint32_t b_off[2];
    uint32_t sw[4];
    int row[4];
    int colb;
};

__device__ __forceinline__ void frag_setup(FragCtx& f, int tid) {
    const int lid = tid & 31;
    const int wid = tid >> 5;
    const int wr = wid >> 2;
    const int wc = wid & 3;
    const int a_row = wr * 64 + (lid & 15);
    const int a_kb = (lid >> 4) * 16;
#pragma unroll
    for (int mi = 0; mi < 4; mi++)
        f.a_off[mi] = swz((a_row + mi * 16) * 128 + a_kb);
    const int b_row = wc * 32 + (lid & 7) + ((lid >> 4) << 3);
    const int b_kb = ((lid >> 3) & 1) * 16;
#pragma unroll
    for (int nb = 0; nb < 2; nb++)
        f.b_off[nb] = swz((b_row + nb * 16) * 128 + b_kb);
    const int rbase = tid >> 3;
    f.colb = (tid & 7) * 16;
#pragma unroll
    for (int r = 0; r < 4; r++) {
        f.row[r] = rbase + 32 * r;
        f.sw[r] = swz(f.row[r] * 128 + f.colb);
    }
}

__device__ __forceinline__ void ks_step(const FragCtx& f, uint32_t s0,
                                        uint32_t bsm, uint32_t kx,
                                        float acc[4][4][4]) {
    uint32_t b0[4], b1[4];
    ldm_x4(b0, bsm + (f.b_off[0] ^ kx));
    ldm_x4(b1, bsm + (f.b_off[1] ^ kx));
    uint32_t a0[4], a1[4];
    ldm_x4(a0, s0 + (f.a_off[0] ^ kx));
    ldm_x4(a1, s0 + (f.a_off[1] ^ kx));
    mma16816(acc[0][0], a0, b0[0], b0[1]);
    mma16816(acc[0][1], a0, b0[2], b0[3]);
    mma16816(acc[0][2], a0, b1[0], b1[1]);
    mma16816(acc[0][3], a0, b1[2], b1[3]);
    ldm_x4(a0, s0 + (f.a_off[2] ^ kx));
    mma16816(acc[1][0], a1, b0[0], b0[1]);
    mma16816(acc[1][1], a1, b0[2], b0[3]);
    mma16816(acc[1][2], a1, b1[0], b1[1]);
    mma16816(acc[1][3], a1, b1[2], b1[3]);
    ldm_x4(a1, s0 + (f.a_off[3] ^ kx));
    mma16816(acc[2][0], a0, b0[0], b0[1]);
    mma16816(acc[2][1], a0, b0[2], b0[3]);
    mma16816(acc[2][2], a0, b1[0], b1[1]);
    mma16816(acc[2][3], a0, b1[2], b1[3]);
    mma16816(acc[3][0], a1, b0[0], b0[1]);
    mma16816(acc[3][1], a1, b0[2], b0[3]);
    mma16816(acc[3][2], a1, b1[0], b1[1]);
    mma16816(acc[3][3], a1, b1[2], b1[3]);
}

#define STG_OUT 32768
#define SMEM_OUT (3 * STG_OUT)

__global__ __launch_bounds__(256, 2) void out_tc_kernel(float* __restrict__ Out) {
    extern __shared__ char smem[];
    const int bh = blockIdx.z;
    const int b = bh / NHdim;
    const int bt = blockIdx.y;
    const int bd = blockIdx.x;

    const uint32_t sbase = smem_u32(smem);
    const int tid = threadIdx.x;
    const int wid = tid >> 5;
    const int lid = tid & 31;
    const int wr = wid >> 2;
    const int wc = wid & 3;

    FragCtx f;
    frag_setup(f, tid);

    const size_t rs = (size_t)Tdim * 2;
    const char* Ahb = (const char*)(g_Sh + ((size_t)bh * Tdim + bt * 128) * Tdim);
    const char* Bhb = (const char*)(g_VTh + ((size_t)b * Ddim + bd * 128) * Tdim);
    const char* pA[4];
    const char* pB[4];
#pragma unroll
    for (int r = 0; r < 4; r++) {
        pA[r] = Ahb + (size_t)f.row[r] * rs + f.colb;
        pB[r] = Bhb + (size_t)f.row[r] * rs + f.colb;
    }

    float acc[4][4][4];
#pragma unroll
    for (int i = 0; i < 4; i++)
#pragma unroll
        for (int j = 0; j < 4; j++)
#pragma unroll
            for (int k = 0; k < 4; k++) acc[i][j][k] = 0.f;

    const int NCH = (bt + 1) * 2;
#pragma unroll
    for (int c = 0; c < 2; c++) {
        uint32_t s0 = sbase + c * STG_OUT;
        size_t kb = (size_t)c * 128;
#pragma unroll
        for (int r = 0; r < 4; r++) {
            cp16(s0 + f.sw[r],         pA[r] + kb);
            cp16(s0 + 16384 + f.sw[r], pB[r] + kb);
        }
        asm volatile("cp.async.commit_group;" ::: "memory");
    }

    int st = 0, stp = 2;
    for (int i = 0; i < NCH; i++) {
        asm volatile("cp.async.wait_group 1;" ::: "memory");
        __syncthreads();
        const uint32_t s0 = sbase + st * STG_OUT;
        const bool pf = (i + 2 < NCH);
        const uint32_t sp = sbase + stp * STG_OUT;
        const size_t kb = (size_t)(i + 2) * 128;
#pragma unroll
        for (int ks = 0; ks < 4; ks++) {
            if (pf) {
                cp16(sp + f.sw[ks],         pA[ks] + kb);
                cp16(sp + 16384 + f.sw[ks], pB[ks] + kb);
            }
            ks_step(f, s0, s0 + 16384, ks * 32, acc);
        }
        asm volatile("cp.async.commit_group;" ::: "memory");
        st = (st == 2) ? 0 : st + 1;
        stp = (stp == 2) ? 0 : stp + 1;
    }

    const int g0 = lid >> 2;
    const int tg = lid & 3;
#pragma unroll
    for (int mi = 0; mi < 4; mi++) {
#pragma unroll
        for (int half = 0; half < 2; half++) {
            const int t = bt * 128 + wr * 64 + mi * 16 + g0 + half * 8;
            float* rowp = Out + ((size_t)bh * Tdim + t) * Ddim;
#pragma unroll
            for (int ni = 0; ni < 4; ni++) {
                const int d = bd * 128 + wc * 32 + ni * 8 + tg * 2;
                float2 o;
                o.x = acc[mi][ni][half * 2 + 0];
                o.y = acc[mi][ni][half * 2 + 1];
                *(float2*)(rowp + d) = o;
            }
        }
    }
}

// ---------------------------------------------------------------------------
extern "C" void kernel_launch(void* const* d_in, const int* in_sizes, int n_in,
                              void* d_out, int out_size) {
    const float* Q      = (const float*)d_in[0];
    const float* V      = (const float*)d_in[1];
    const float* traces = (const float*)d_in[2];
    const float* scale  = (const float*)d_in[3];
    float* out = (float*)d_out;

    const size_t OUT_ELEMS = (size_t)BHdim * Tdim * Ddim;
    const size_t SC_ELEMS  = (size_t)BHdim * Tdim * Tdim;

    float* scores;
    if ((size_t)out_size >= OUT_ELEMS + SC_ELEMS) {
        scores = out + OUT_ELEMS;
    } else {
        void* p = nullptr;
        cudaGetSymbolAddress(&p, g_S_fallback);
        scores = (float*)p;
    }

    static bool attr_set = false;
    if (!attr_set) {
        cudaFuncSetAttribute(scores_tc_kernel,
                             cudaFuncAttributeMaxDynamicSharedMemorySize,
                             SMEM_SC);
        cudaFuncSetAttribute(out_tc_kernel,
                             cudaFuncAttributeMaxDynamicSharedMemorySize,
                             SMEM_OUT);
        attr_set = true;
    }

    const size_t nq = (size_t)BHdim * Tdim * (Ndim / 4);
    rope_kernel<<<(unsigned)((nq + 255) / 256), 256>>>(Q);
    gate_kernel<<<BHdim * Tdim, 32>>>(traces);
    dim3 gv(Tdim / 32, Ddim / 32, Bdim);
    vt_kernel<<<gv, dim3(32, 8)>>>(V);

    dim3 g1(Tdim / 128, Tdim / 128, BHdim);
    scores_tc_kernel<<<g1, 128, SMEM_SC>>>(scores, scale);

    dim3 g2(Ddim / 128, Tdim / 128, BHdim);
    out_tc_kernel<<<g2, 256, SMEM_OUT>>>(out);
}

// round 13
// speedup vs baseline: 8.3382x; 1.0001x over previous
#include <cuda_runtime.h>
#include <cuda_fp16.h>
#include <math.h>
#include <stdint.h>

#define Bdim 2
#define NHdim 4
#define Tdim 1024
#define Ndim 8192
#define Ddim 256
#define BHdim (Bdim * NHdim)

// Scratch (no cudaMalloc allowed)
static __device__ __half g_Qh[67108864];  // [BH, T, N] rope(Q) fp16, 128 MB
static __device__ __half g_Sh[8388608];   // [BH, T, T] scores fp16
static __device__ __half g_VTh[Bdim * Ddim * Tdim];  // [B, D, T] V^T fp16
static __device__ float g_gate[BHdim * Tdim];
static __device__ float g_S_fallback[8388608];

// ---------------------------------------------------------------------------
// PTX helpers
// ---------------------------------------------------------------------------
__device__ __forceinline__ uint32_t smem_u32(const void* p) {
    uint32_t a;
    asm("{ .reg .u64 t; cvta.to.shared.u64 t, %1; cvt.u32.u64 %0, t; }"
        : "=r"(a) : "l"(p));
    return a;
}
__device__ __forceinline__ void cp16(uint32_t s, const void* g) {
    asm volatile("cp.async.cg.shared.global [%0], [%1], 16;" :: "r"(s), "l"(g)
                 : "memory");
}
__device__ __forceinline__ void ldm_x4(uint32_t* r, uint32_t addr) {
    asm volatile(
        "ldmatrix.sync.aligned.m8n8.x4.shared.b16 {%0,%1,%2,%3}, [%4];"
        : "=r"(r[0]), "=r"(r[1]), "=r"(r[2]), "=r"(r[3]) : "r"(addr));
}
__device__ __forceinline__ void mma16816(float* c, const uint32_t* a,
                                         uint32_t b0, uint32_t b1) {
    asm volatile(
        "mma.sync.aligned.m16n8k16.row.col.f32.f16.f16.f32 "
        "{%0,%1,%2,%3}, {%4,%5,%6,%7}, {%8,%9}, {%0,%1,%2,%3};"
        : "+f"(c[0]), "+f"(c[1]), "+f"(c[2]), "+f"(c[3])
        : "r"(a[0]), "r"(a[1]), "r"(a[2]), "r"(a[3]), "r"(b0), "r"(b1));
}
__device__ __forceinline__ uint32_t swz(uint32_t off) {
    return off ^ ((off >> 3) & 0x70);  // SW128
}

// ---------------------------------------------------------------------------
// RoPE -> fp16
// ---------------------------------------------------------------------------
__global__ void rope_kernel(const float* __restrict__ Q) {
    size_t idx = (size_t)blockIdx.x * blockDim.x + threadIdx.x;
    const size_t NQ = (size_t)BHdim * Tdim * (Ndim / 4);
    if (idx >= NQ) return;
    int p2 = (int)(idx % (Ndim / 4));
    int t = (int)((idx / (Ndim / 4)) % Tdim);
    float4 v = ((const float4*)Q)[idx];
    const float tf = (float)t;
    const float k = -16.0f * 2.0f / (float)Ndim;

    float fr0 = exp2f(k * (float)(2 * p2)) * 0.15915494309189535f;
    float ph0 = tf * fr0;
    ph0 = (ph0 - floorf(ph0)) * 6.283185307179586f;
    float s0, c0;
    __sincosf(ph0, &s0, &c0);

    float fr1 = exp2f(k * (float)(2 * p2 + 1)) * 0.15915494309189535f;
    float ph1 = tf * fr1;
    ph1 = (ph1 - floorf(ph1)) * 6.283185307179586f;
    float s1, c1;
    __sincosf(ph1, &s1, &c1);

    __half2 h0, h1;
    h0.x = __float2half(v.x * c0 - v.y * s0);
    h0.y = __float2half(v.y * c0 + v.x * s0);
    h1.x = __float2half(v.z * c1 - v.w * s1);
    h1.y = __float2half(v.w * c1 + v.z * s1);
    ((__half2*)g_Qh)[idx * 2 + 0] = h0;
    ((__half2*)g_Qh)[idx * 2 + 1] = h1;
}

// ---------------------------------------------------------------------------
// Gate
// ---------------------------------------------------------------------------
__global__ void gate_kernel(const float* __restrict__ traces) {
    int row = blockIdx.x;
    const float* pr = traces + (size_t)row * Ddim;
    float sum = 0.f;
    for (int i = threadIdx.x; i < Ddim; i += 32) sum += pr[i];
#pragma unroll
    for (int o = 16; o; o >>= 1) sum += __shfl_xor_sync(0xffffffffu, sum, o);
    if (threadIdx.x == 0) {
        float m = sum * (1.0f / (float)Ddim);
        float sig = 1.0f / (1.0f + expf(-m));
        g_gate[row] = 0.5f + 0.5f * sig;
    }
}

// ---------------------------------------------------------------------------
// V transpose -> fp16: VT[b][d][s]
// ---------------------------------------------------------------------------
__global__ void vt_kernel(const float* __restrict__ V) {
    __shared__ float tile[32][33];
    const int b = blockIdx.z;
    const int s0 = blockIdx.x * 32, d0 = blockIdx.y * 32;
#pragma unroll
    for (int j = 0; j < 4; j++)
        tile[threadIdx.y + 8 * j][threadIdx.x] =
            V[(size_t)b * Tdim * Ddim + (size_t)(s0 + threadIdx.y + 8 * j) * Ddim +
              d0 + threadIdx.x];
    __syncthreads();
#pragma unroll
    for (int j = 0; j < 4; j++) {
        int d = d0 + threadIdx.y + 8 * j;
        int s = s0 + threadIdx.x;
        float v = tile[threadIdx.x][threadIdx.y + 8 * j];
        g_VTh[(size_t)b * Ddim * Tdim + (size_t)d * Tdim + s] = __float2half(v);
    }
}

// ---------------------------------------------------------------------------
// Zero-fill kernel for strictly-upper tiles (bt < bs).
// 224 tiles total (28 per bh). Decode idx -> (bt < bs) pair.
// ---------------------------------------------------------------------------
__global__ void zero_upper_kernel(float* __restrict__ Sc) {
    const int bh = blockIdx.x & 7;
    int j = blockIdx.x >> 3;  // 0..27 upper pair index
    int c = (int)((sqrtf(8.f * (float)j + 1.f) + 1.f) * 0.5f);
    while (c * (c - 1) / 2 > j) c--;
    while ((c + 1) * c / 2 <= j) c++;
    const int bs = c;                    // 1..7
    const int bt = j - c * (c - 1) / 2;  // 0..bs-1
    float* Sbase = Sc + (size_t)bh * Tdim * Tdim;
    __half* Shb = g_Sh + (size_t)bh * Tdim * Tdim;
    const int r0 = bt * 128, c0 = bs * 128;
    float4 z = make_float4(0.f, 0.f, 0.f, 0.f);
    for (int i = threadIdx.x; i < 128 * 32; i += 256) {
        int r = i >> 5, cc = (i & 31) << 2;
        *(float4*)(Sbase + (size_t)(r0 + r) * Tdim + c0 + cc) = z;
    }
    for (int i = threadIdx.x; i < 128 * 16; i += 256) {
        int r = i >> 4, cc = (i & 15) << 3;
        *(uint4*)(Shb + (size_t)(r0 + r) * Tdim + c0 + cc) = make_uint4(0, 0, 0, 0);
    }
}

// ===========================================================================
// SCORES: 1D grid over 288 lower tiles. 128x128 tile, 4 warps (2x2),
// warp tile 64x64, 2 CTAs/SM. Stage = A(16K)+B(16K); 3 stages = 96KB.
// ===========================================================================
#define STG_SC 32768
#define SMEM_SC (3 * STG_SC)

struct Frag4 {
    uint32_t a_off[4];
    uint32_t b_off[4];
    uint32_t sw[8];
    uint32_t gof[8];
};

__device__ __forceinline__ void frag4_setup(Frag4& f, int tid, uint32_t rstride) {
    const int lid = tid & 31;
    const int wid = tid >> 5;
    const int wr = wid >> 1;
    const int wc = wid & 1;
    const int a_row = wr * 64 + (lid & 15);
    const int a_kb = (lid >> 4) * 16;
#pragma unroll
    for (int mi = 0; mi < 4; mi++)
        f.a_off[mi] = swz((a_row + mi * 16) * 128 + a_kb);
    const int b_row = wc * 64 + (lid & 7) + ((lid >> 4) << 3);
    const int b_kb = ((lid >> 3) & 1) * 16;
#pragma unroll
    for (int nb = 0; nb < 4; nb++)
        f.b_off[nb] = swz((b_row + nb * 16) * 128 + b_kb);
    const int rbase = tid >> 3;
    const int colb = (tid & 7) * 16;
#pragma unroll
    for (int r = 0; r < 8; r++) {
        int row = rbase + 16 * r;
        f.sw[r] = swz(row * 128 + colb);
        f.gof[r] = (uint32_t)row * rstride + colb;
    }
}

__device__ __forceinline__ void ks4_step(const Frag4& f, uint32_t asm_,
                                         uint32_t bsm, uint32_t kx,
                                         float acc[4][8][4]) {
    uint32_t b[4][4];
#pragma unroll
    for (int nb = 0; nb < 4; nb++) ldm_x4(b[nb], bsm + (f.b_off[nb] ^ kx));
    uint32_t a0[4], a1[4];
    ldm_x4(a0, asm_ + (f.a_off[0] ^ kx));
    ldm_x4(a1, asm_ + (f.a_off[1] ^ kx));
#pragma unroll
    for (int nb = 0; nb < 4; nb++) {
        mma16816(acc[0][2 * nb + 0], a0, b[nb][0], b[nb][1]);
        mma16816(acc[0][2 * nb + 1], a0, b[nb][2], b[nb][3]);
    }
    ldm_x4(a0, asm_ + (f.a_off[2] ^ kx));
#pragma unroll
    for (int nb = 0; nb < 4; nb++) {
        mma16816(acc[1][2 * nb + 0], a1, b[nb][0], b[nb][1]);
        mma16816(acc[1][2 * nb + 1], a1, b[nb][2], b[nb][3]);
    }
    ldm_x4(a1, asm_ + (f.a_off[3] ^ kx));
#pragma unroll
    for (int nb = 0; nb < 4; nb++) {
        mma16816(acc[2][2 * nb + 0], a0, b[nb][0], b[nb][1]);
        mma16816(acc[2][2 * nb + 1], a0, b[nb][2], b[nb][3]);
    }
#pragma unroll
    for (int nb = 0; nb < 4; nb++) {
        mma16816(acc[3][2 * nb + 0], a1, b[nb][0], b[nb][1]);
        mma16816(acc[3][2 * nb + 1], a1, b[nb][2], b[nb][3]);
    }
}

__global__ __launch_bounds__(128, 2) void scores_tc_kernel(
    float* __restrict__ Sc, const float* __restrict__ stdp_scale) {
    extern __shared__ char smem[];
    // Decode 1D heavy-tile index: idx = bh + 8 * k, k in [0,36) lower-tri.
    const int bh = blockIdx.x & 7;
    int kidx = blockIdx.x >> 3;  // 0..35
    int bt = (int)((sqrtf(8.f * (float)kidx + 1.f) - 1.f) * 0.5f);
    while (bt * (bt + 1) / 2 > kidx) bt--;
    while ((bt + 1) * (bt + 2) / 2 <= kidx) bt++;
    const int bs = kidx - bt * (bt + 1) / 2;  // 0..bt

    float* Sbase = Sc + (size_t)bh * Tdim * Tdim;
    __half* Shb = g_Sh + (size_t)bh * Tdim * Tdim;

    const uint32_t sbase = smem_u32(smem);
    const int tid = threadIdx.x;
    const int wid = tid >> 5;
    const int lid = tid & 31;
    const int wr = wid >> 1;
    const int wc = wid & 1;

    Frag4 f;
    frag4_setup(f, tid, (uint32_t)Ndim * 2);

    const char* Ab = (const char*)(g_Qh + ((size_t)bh * Tdim + bt * 128) * Ndim);
    const char* Bb = (const char*)(g_Qh + ((size_t)bh * Tdim + bs * 128) * Ndim);

    float acc[4][8][4];
#pragma unroll
    for (int i = 0; i < 4; i++)
#pragma unroll
        for (int j = 0; j < 8; j++)
#pragma unroll
            for (int k = 0; k < 4; k++) acc[i][j][k] = 0.f;

    const int NCH = 128;
#pragma unroll
    for (int c = 0; c < 2; c++) {
        uint32_t s0 = sbase + c * STG_SC;
        size_t kb = (size_t)c * 128;
#pragma unroll
        for (int r = 0; r < 8; r++) {
            cp16(s0 + f.sw[r],         Ab + f.gof[r] + kb);
            cp16(s0 + 16384 + f.sw[r], Bb + f.gof[r] + kb);
        }
        asm volatile("cp.async.commit_group;" ::: "memory");
    }

    int st = 0, stp = 2;
    for (int i = 0; i < NCH; i++) {
        asm volatile("cp.async.wait_group 1;" ::: "memory");
        __syncthreads();
        const uint32_t s0 = sbase + st * STG_SC;
        const bool pf = (i + 2 < NCH);
        const uint32_t sp = sbase + stp * STG_SC;
        const size_t kb = (size_t)(i + 2) * 128;
#pragma unroll
        for (int ks = 0; ks < 4; ks++) {
            if (pf) {
                cp16(sp + f.sw[2 * ks],             Ab + f.gof[2 * ks] + kb);
                cp16(sp + f.sw[2 * ks + 1],         Ab + f.gof[2 * ks + 1] + kb);
                cp16(sp + 16384 + f.sw[2 * ks],     Bb + f.gof[2 * ks] + kb);
                cp16(sp + 16384 + f.sw[2 * ks + 1], Bb + f.gof[2 * ks + 1] + kb);
            }
            ks4_step(f, s0, s0 + 16384, ks * 32, acc);
        }
        asm volatile("cp.async.commit_group;" ::: "memory");
        st = (st == 2) ? 0 : st + 1;
        stp = (stp == 2) ? 0 : stp + 1;
    }

    // Epilogue: mask/stdp/gate; store fp32 + fp16.
    const float ssc = stdp_scale[0] * 0.01f;
    const int g0 = lid >> 2;
    const int tg = lid & 3;
#pragma unroll
    for (int mi = 0; mi < 4; mi++) {
#pragma unroll
        for (int half = 0; half < 2; half++) {
            const int t = bt * 128 + wr * 64 + mi * 16 + g0 + half * 8;
            const float g = g_gate[bh * Tdim + t];
            const float bco = g * ssc * __expf(-0.05f * (float)t);
            float* rowp = Sbase + (size_t)t * Tdim;
            __half* hrow = Shb + (size_t)t * Tdim;
#pragma unroll
            for (int ni = 0; ni < 8; ni++) {
                const int s = bs * 128 + wc * 64 + ni * 8 + tg * 2;
                const float e0 = __expf(0.05f * (float)s);
                float v0 = acc[mi][ni][half * 2 + 0];
                float v1 = acc[mi][ni][half * 2 + 1];
                float2 o;
                o.x = (t > s)     ? v0 * fmaf(bco, e0, g) : 0.f;
                o.y = (t > s + 1) ? v1 * fmaf(bco, e0 * 1.0512710963760241f, g)
                                  : 0.f;
                *(float2*)(rowp + s) = o;
                __half2 h;
                h.x = __float2half(o.x);
                h.y = __float2half(o.y);
                *(__half2*)(hrow + s) = h;
            }
        }
    }
}

// ===========================================================================
// GEMM2: 8 warps 2x4, warp 64x32, single product.
// ===========================================================================
struct FragCtx {
    uint32_t a_off[4];
    uint32_t b_off[2];
    uint32_t sw[4];
    int row[4];
    int colb;
};

__device__ __forceinline__ void frag_setup(FragCtx& f, int tid) {
    const int lid = tid & 31;
    const int wid = tid >> 5;
    const int wr = wid >> 2;
    const int wc = wid & 3;
    const int a_row = wr * 64 + (lid & 15);
    const int a_kb = (lid >> 4) * 16;
#pragma unroll
    for (int mi = 0; mi < 4; mi++)
        f.a_off[mi] = swz((a_row + mi * 16) * 128 + a_kb);
    const int b_row = wc * 32 + (lid & 7) + ((lid >> 4) << 3);
    const int b_kb = ((lid >> 3) & 1) * 16;
#pragma unroll
    for (int nb = 0; nb < 2; nb++)
        f.b_off[nb] = swz((b_row + nb * 16) * 128 + b_kb);
    const int rbase = tid >> 3;
    f.colb = (tid & 7) * 16;
#pragma unroll
    for (int r = 0; r < 4; r++) {
        f.row[r] = rbase + 32 * r;
        f.sw[r] = swz(f.row[r] * 128 + f.colb);
    }
}

__device__ __forceinline__ void ks_step(const FragCtx& f, uint32_t s0,
                                        uint32_t bsm, uint32_t kx,
                                        float acc[4][4][4]) {
    uint32_t b0[4], b1[4];
    ldm_x4(b0, bsm + (f.b_off[0] ^ kx));
    ldm_x4(b1, bsm + (f.b_off[1] ^ kx));
    uint32_t a0[4], a1[4];
    ldm_x4(a0, s0 + (f.a_off[0] ^ kx));
    ldm_x4(a1, s0 + (f.a_off[1] ^ kx));
    mma16816(acc[0][0], a0, b0[0], b0[1]);
    mma16816(acc[0][1], a0, b0[2], b0[3]);
    mma16816(acc[0][2], a0, b1[0], b1[1]);
    mma16816(acc[0][3], a0, b1[2], b1[3]);
    ldm_x4(a0, s0 + (f.a_off[2] ^ kx));
    mma16816(acc[1][0], a1, b0[0], b0[1]);
    mma16816(acc[1][1], a1, b0[2], b0[3]);
    mma16816(acc[1][2], a1, b1[0], b1[1]);
    mma16816(acc[1][3], a1, b1[2], b1[3]);
    ldm_x4(a1, s0 + (f.a_off[3] ^ kx));
    mma16816(acc[2][0], a0, b0[0], b0[1]);
    mma16816(acc[2][1], a0, b0[2], b0[3]);
    mma16816(acc[2][2], a0, b1[0], b1[1]);
    mma16816(acc[2][3], a0, b1[2], b1[3]);
    mma16816(acc[3][0], a1, b0[0], b0[1]);
    mma16816(acc[3][1], a1, b0[2], b0[3]);
    mma16816(acc[3][2], a1, b1[0], b1[1]);
    mma16816(acc[3][3], a1, b1[2], b1[3]);
}

#define STG_OUT 32768
#define SMEM_OUT (3 * STG_OUT)

__global__ __launch_bounds__(256, 2) void out_tc_kernel(float* __restrict__ Out) {
    extern __shared__ char smem[];
    const int bh = blockIdx.z;
    const int b = bh / NHdim;
    const int bt = blockIdx.y;
    const int bd = blockIdx.x;

    const uint32_t sbase = smem_u32(smem);
    const int tid = threadIdx.x;
    const int wid = tid >> 5;
    const int lid = tid & 31;
    const int wr = wid >> 2;
    const int wc = wid & 3;

    FragCtx f;
    frag_setup(f, tid);

    const size_t rs = (size_t)Tdim * 2;
    const char* Ahb = (const char*)(g_Sh + ((size_t)bh * Tdim + bt * 128) * Tdim);
    const char* Bhb = (const char*)(g_VTh + ((size_t)b * Ddim + bd * 128) * Tdim);
    const char* pA[4];
    const char* pB[4];
#pragma unroll
    for (int r = 0; r < 4; r++) {
        pA[r] = Ahb + (size_t)f.row[r] * rs + f.colb;
        pB[r] = Bhb + (size_t)f.row[r] * rs + f.colb;
    }

    float acc[4][4][4];
#pragma unroll
    for (int i = 0; i < 4; i++)
#pragma unroll
        for (int j = 0; j < 4; j++)
#pragma unroll
            for (int k = 0; k < 4; k++) acc[i][j][k] = 0.f;

    const int NCH = (bt + 1) * 2;
#pragma unroll
    for (int c = 0; c < 2; c++) {
        uint32_t s0 = sbase + c * STG_OUT;
        size_t kb = (size_t)c * 128;
#pragma unroll
        for (int r = 0; r < 4; r++) {
            cp16(s0 + f.sw[r],         pA[r] + kb);
            cp16(s0 + 16384 + f.sw[r], pB[r] + kb);
        }
        asm volatile("cp.async.commit_group;" ::: "memory");
    }

    int st = 0, stp = 2;
    for (int i = 0; i < NCH; i++) {
        asm volatile("cp.async.wait_group 1;" ::: "memory");
        __syncthreads();
        const uint32_t s0 = sbase + st * STG_OUT;
        const bool pf = (i + 2 < NCH);
        const uint32_t sp = sbase + stp * STG_OUT;
        const size_t kb = (size_t)(i + 2) * 128;
#pragma unroll
        for (int ks = 0; ks < 4; ks++) {
            if (pf) {
                cp16(sp + f.sw[ks],         pA[ks] + kb);
                cp16(sp + 16384 + f.sw[ks], pB[ks] + kb);
            }
            ks_step(f, s0, s0 + 16384, ks * 32, acc);
        }
        asm volatile("cp.async.commit_group;" ::: "memory");
        st = (st == 2) ? 0 : st + 1;
        stp = (stp == 2) ? 0 : stp + 1;
    }

    const int g0 = lid >> 2;
    const int tg = lid & 3;
#pragma unroll
    for (int mi = 0; mi < 4; mi++) {
#pragma unroll
        for (int half = 0; half < 2; half++) {
            const int t = bt * 128 + wr * 64 + mi * 16 + g0 + half * 8;
            float* rowp = Out + ((size_t)bh * Tdim + t) * Ddim;
#pragma unroll
            for (int ni = 0; ni < 4; ni++) {
                const int d = bd * 128 + wc * 32 + ni * 8 + tg * 2;
                float2 o;
                o.x = acc[mi][ni][half * 2 + 0];
                o.y = acc[mi][ni][half * 2 + 1];
                *(float2*)(rowp + d) = o;
            }
        }
    }
}

// ---------------------------------------------------------------------------
extern "C" void kernel_launch(void* const* d_in, const int* in_sizes, int n_in,
                              void* d_out, int out_size) {
    const float* Q      = (const float*)d_in[0];
    const float* V      = (const float*)d_in[1];
    const float* traces = (const float*)d_in[2];
    const float* scale  = (const float*)d_in[3];
    float* out = (float*)d_out;

    const size_t OUT_ELEMS = (size_t)BHdim * Tdim * Ddim;
    const size_t SC_ELEMS  = (size_t)BHdim * Tdim * Tdim;

    float* scores;
    if ((size_t)out_size >= OUT_ELEMS + SC_ELEMS) {
        scores = out + OUT_ELEMS;
    } else {
        void* p = nullptr;
        cudaGetSymbolAddress(&p, g_S_fallback);
        scores = (float*)p;
    }

    static bool attr_set = false;
    if (!attr_set) {
        cudaFuncSetAttribute(scores_tc_kernel,
                             cudaFuncAttributeMaxDynamicSharedMemorySize,
                             SMEM_SC);
        cudaFuncSetAttribute(out_tc_kernel,
                             cudaFuncAttributeMaxDynamicSharedMemorySize,
                             SMEM_OUT);
        attr_set = true;
    }

    // Zero-fill upper tiles first (independent, ~5us).
    zero_upper_kernel<<<28 * BHdim, 256>>>(scores);

    const size_t nq = (size_t)BHdim * Tdim * (Ndim / 4);
    rope_kernel<<<(unsigned)((nq + 255) / 256), 256>>>(Q);
    gate_kernel<<<BHdim * Tdim, 32>>>(traces);
    dim3 gv(Tdim / 32, Ddim / 32, Bdim);
    vt_kernel<<<gv, dim3(32, 8)>>>(V);

    // 288 heavy lower tiles, one wave at 2 CTAs/SM.
    scores_tc_kernel<<<36 * BHdim, 128, SMEM_SC>>>(scores, scale);

    dim3 g2(Ddim / 128, Tdim / 128, BHdim);
    out_tc_kernel<<<g2, 256, SMEM_OUT>>>(out);
}

// round 14
// speedup vs baseline: 8.5886x; 1.0300x over previous
#include <cuda_runtime.h>
#include <cuda_fp16.h>
#include <math.h>
#include <stdint.h>

#define Bdim 2
#define NHdim 4
#define Tdim 1024
#define Ndim 8192
#define Ddim 256
#define BHdim (Bdim * NHdim)

// Scratch (no cudaMalloc allowed)
static __device__ __half g_Qh[67108864];  // [BH, T, N] rope(Q) fp16, 128 MB
static __device__ __half g_Sh[8388608];   // [BH, T, T] scores fp16
static __device__ __half g_VTh[Bdim * Ddim * Tdim];  // [B, D, T] V^T fp16
static __device__ float g_gate[BHdim * Tdim];
static __device__ float g_S_fallback[8388608];

// ---------------------------------------------------------------------------
// PTX helpers
// ---------------------------------------------------------------------------
__device__ __forceinline__ uint32_t smem_u32(const void* p) {
    uint32_t a;
    asm("{ .reg .u64 t; cvta.to.shared.u64 t, %1; cvt.u32.u64 %0, t; }"
        : "=r"(a) : "l"(p));
    return a;
}
__device__ __forceinline__ void cp16(uint32_t s, const void* g) {
    asm volatile("cp.async.cg.shared.global [%0], [%1], 16;" :: "r"(s), "l"(g)
                 : "memory");
}
__device__ __forceinline__ void ldm_x4(uint32_t* r, uint32_t addr) {
    asm volatile(
        "ldmatrix.sync.aligned.m8n8.x4.shared.b16 {%0,%1,%2,%3}, [%4];"
        : "=r"(r[0]), "=r"(r[1]), "=r"(r[2]), "=r"(r[3]) : "r"(addr));
}
__device__ __forceinline__ void mma16816(float* c, const uint32_t* a,
                                         uint32_t b0, uint32_t b1) {
    asm volatile(
        "mma.sync.aligned.m16n8k16.row.col.f32.f16.f16.f32 "
        "{%0,%1,%2,%3}, {%4,%5,%6,%7}, {%8,%9}, {%0,%1,%2,%3};"
        : "+f"(c[0]), "+f"(c[1]), "+f"(c[2]), "+f"(c[3])
        : "r"(a[0]), "r"(a[1]), "r"(a[2]), "r"(a[3]), "r"(b0), "r"(b1));
}
__device__ __forceinline__ uint32_t swz(uint32_t off) {
    return off ^ ((off >> 3) & 0x70);  // SW128
}
__device__ __forceinline__ void mbar_init(uint32_t a, uint32_t cnt) {
    asm volatile("mbarrier.init.shared.b64 [%0], %1;" :: "r"(a), "r"(cnt)
                 : "memory");
}
__device__ __forceinline__ void mbar_wait(uint32_t a, uint32_t parity) {
    asm volatile(
        "{\n\t.reg .pred P;\n"
        "WL_%=:\n\t"
        "mbarrier.try_wait.parity.acquire.cta.shared::cta.b64 P, [%0], %1, 0x989680;\n\t"
        "@!P bra WL_%=;\n\t}"
        :: "r"(a), "r"(parity) : "memory");
}
__device__ __forceinline__ void mbar_arrive(uint32_t a) {
    asm volatile("mbarrier.arrive.shared.b64 _, [%0];" :: "r"(a) : "memory");
}
__device__ __forceinline__ void cp_arrive(uint32_t a) {
    asm volatile("cp.async.mbarrier.arrive.noinc.shared.b64 [%0];" :: "r"(a)
                 : "memory");
}

// ---------------------------------------------------------------------------
// RoPE -> fp16
// ---------------------------------------------------------------------------
__global__ void rope_kernel(const float* __restrict__ Q) {
    size_t idx = (size_t)blockIdx.x * blockDim.x + threadIdx.x;
    const size_t NQ = (size_t)BHdim * Tdim * (Ndim / 4);
    if (idx >= NQ) return;
    int p2 = (int)(idx % (Ndim / 4));
    int t = (int)((idx / (Ndim / 4)) % Tdim);
    float4 v = ((const float4*)Q)[idx];
    const float tf = (float)t;
    const float k = -16.0f * 2.0f / (float)Ndim;

    float fr0 = exp2f(k * (float)(2 * p2)) * 0.15915494309189535f;
    float ph0 = tf * fr0;
    ph0 = (ph0 - floorf(ph0)) * 6.283185307179586f;
    float s0, c0;
    __sincosf(ph0, &s0, &c0);

    float fr1 = exp2f(k * (float)(2 * p2 + 1)) * 0.15915494309189535f;
    float ph1 = tf * fr1;
    ph1 = (ph1 - floorf(ph1)) * 6.283185307179586f;
    float s1, c1;
    __sincosf(ph1, &s1, &c1);

    __half2 h0, h1;
    h0.x = __float2half(v.x * c0 - v.y * s0);
    h0.y = __float2half(v.y * c0 + v.x * s0);
    h1.x = __float2half(v.z * c1 - v.w * s1);
    h1.y = __float2half(v.w * c1 + v.z * s1);
    ((__half2*)g_Qh)[idx * 2 + 0] = h0;
    ((__half2*)g_Qh)[idx * 2 + 1] = h1;
}

// ---------------------------------------------------------------------------
// Gate
// ---------------------------------------------------------------------------
__global__ void gate_kernel(const float* __restrict__ traces) {
    int row = blockIdx.x;
    const float* pr = traces + (size_t)row * Ddim;
    float sum = 0.f;
    for (int i = threadIdx.x; i < Ddim; i += 32) sum += pr[i];
#pragma unroll
    for (int o = 16; o; o >>= 1) sum += __shfl_xor_sync(0xffffffffu, sum, o);
    if (threadIdx.x == 0) {
        float m = sum * (1.0f / (float)Ddim);
        float sig = 1.0f / (1.0f + expf(-m));
        g_gate[row] = 0.5f + 0.5f * sig;
    }
}

// ---------------------------------------------------------------------------
// V transpose -> fp16: VT[b][d][s]
// ---------------------------------------------------------------------------
__global__ void vt_kernel(const float* __restrict__ V) {
    __shared__ float tile[32][33];
    const int b = blockIdx.z;
    const int s0 = blockIdx.x * 32, d0 = blockIdx.y * 32;
#pragma unroll
    for (int j = 0; j < 4; j++)
        tile[threadIdx.y + 8 * j][threadIdx.x] =
            V[(size_t)b * Tdim * Ddim + (size_t)(s0 + threadIdx.y + 8 * j) * Ddim +
              d0 + threadIdx.x];
    __syncthreads();
#pragma unroll
    for (int j = 0; j < 4; j++) {
        int d = d0 + threadIdx.y + 8 * j;
        int s = s0 + threadIdx.x;
        float v = tile[threadIdx.x][threadIdx.y + 8 * j];
        g_VTh[(size_t)b * Ddim * Tdim + (size_t)d * Tdim + s] = __float2half(v);
    }
}

// ---------------------------------------------------------------------------
// Zero-fill kernel for strictly-upper tiles (bt < bs).
// ---------------------------------------------------------------------------
__global__ void zero_upper_kernel(float* __restrict__ Sc) {
    const int bh = blockIdx.x & 7;
    int j = blockIdx.x >> 3;
    int c = (int)((sqrtf(8.f * (float)j + 1.f) + 1.f) * 0.5f);
    while (c * (c - 1) / 2 > j) c--;
    while ((c + 1) * c / 2 <= j) c++;
    const int bs = c;
    const int bt = j - c * (c - 1) / 2;
    float* Sbase = Sc + (size_t)bh * Tdim * Tdim;
    __half* Shb = g_Sh + (size_t)bh * Tdim * Tdim;
    const int r0 = bt * 128, c0 = bs * 128;
    float4 z = make_float4(0.f, 0.f, 0.f, 0.f);
    for (int i = threadIdx.x; i < 128 * 32; i += 256) {
        int r = i >> 5, cc = (i & 31) << 2;
        *(float4*)(Sbase + (size_t)(r0 + r) * Tdim + c0 + cc) = z;
    }
    for (int i = threadIdx.x; i < 128 * 16; i += 256) {
        int r = i >> 4, cc = (i & 15) << 3;
        *(uint4*)(Shb + (size_t)(r0 + r) * Tdim + c0 + cc) = make_uint4(0, 0, 0, 0);
    }
}

// ===========================================================================
// SCORES: 1D grid over 288 lower tiles. 128x128 tile, 4 warps 2x2,
// warp tile 64x64, 2 CTAs/SM. 3 stages + per-stage mbarrier pipeline
// (full: 128 cp-arrives; empty: 4 warp-arrives). No __syncthreads in loop.
// ===========================================================================
#define STG_SC 32768
#define MB_OFF (3 * STG_SC)
#define SMEM_SC (3 * STG_SC + 64)

struct Frag4 {
    uint32_t a_off[4];
    uint32_t b_off[4];
    uint32_t sw[8];
    uint32_t gof[8];
};

__device__ __forceinline__ void frag4_setup(Frag4& f, int tid, uint32_t rstride) {
    const int lid = tid & 31;
    const int wid = tid >> 5;
    const int wr = wid >> 1;
    const int wc = wid & 1;
    const int a_row = wr * 64 + (lid & 15);
    const int a_kb = (lid >> 4) * 16;
#pragma unroll
    for (int mi = 0; mi < 4; mi++)
        f.a_off[mi] = swz((a_row + mi * 16) * 128 + a_kb);
    const int b_row = wc * 64 + (lid & 7) + ((lid >> 4) << 3);
    const int b_kb = ((lid >> 3) & 1) * 16;
#pragma unroll
    for (int nb = 0; nb < 4; nb++)
        f.b_off[nb] = swz((b_row + nb * 16) * 128 + b_kb);
    const int rbase = tid >> 3;
    const int colb = (tid & 7) * 16;
#pragma unroll
    for (int r = 0; r < 8; r++) {
        int row = rbase + 16 * r;
        f.sw[r] = swz(row * 128 + colb);
        f.gof[r] = (uint32_t)row * rstride + colb;
    }
}

__device__ __forceinline__ void ks4_step(const Frag4& f, uint32_t asm_,
                                         uint32_t bsm, uint32_t kx,
                                         float acc[4][8][4]) {
    uint32_t b[4][4];
#pragma unroll
    for (int nb = 0; nb < 4; nb++) ldm_x4(b[nb], bsm + (f.b_off[nb] ^ kx));
    uint32_t a0[4], a1[4];
    ldm_x4(a0, asm_ + (f.a_off[0] ^ kx));
    ldm_x4(a1, asm_ + (f.a_off[1] ^ kx));
#pragma unroll
    for (int nb = 0; nb < 4; nb++) {
        mma16816(acc[0][2 * nb + 0], a0, b[nb][0], b[nb][1]);
        mma16816(acc[0][2 * nb + 1], a0, b[nb][2], b[nb][3]);
    }
    ldm_x4(a0, asm_ + (f.a_off[2] ^ kx));
#pragma unroll
    for (int nb = 0; nb < 4; nb++) {
        mma16816(acc[1][2 * nb + 0], a1, b[nb][0], b[nb][1]);
        mma16816(acc[1][2 * nb + 1], a1, b[nb][2], b[nb][3]);
    }
    ldm_x4(a1, asm_ + (f.a_off[3] ^ kx));
#pragma unroll
    for (int nb = 0; nb < 4; nb++) {
        mma16816(acc[2][2 * nb + 0], a0, b[nb][0], b[nb][1]);
        mma16816(acc[2][2 * nb + 1], a0, b[nb][2], b[nb][3]);
    }
#pragma unroll
    for (int nb = 0; nb < 4; nb++) {
        mma16816(acc[3][2 * nb + 0], a1, b[nb][0], b[nb][1]);
        mma16816(acc[3][2 * nb + 1], a1, b[nb][2], b[nb][3]);
    }
}

__global__ __launch_bounds__(128, 2) void scores_tc_kernel(
    float* __restrict__ Sc, const float* __restrict__ stdp_scale) {
    extern __shared__ char smem[];
    const int bh = blockIdx.x & 7;
    int kidx = blockIdx.x >> 3;
    int bt = (int)((sqrtf(8.f * (float)kidx + 1.f) - 1.f) * 0.5f);
    while (bt * (bt + 1) / 2 > kidx) bt--;
    while ((bt + 1) * (bt + 2) / 2 <= kidx) bt++;
    const int bs = kidx - bt * (bt + 1) / 2;

    float* Sbase = Sc + (size_t)bh * Tdim * Tdim;
    __half* Shb = g_Sh + (size_t)bh * Tdim * Tdim;

    const uint32_t sbase = smem_u32(smem);
    const int tid = threadIdx.x;
    const int wid = tid >> 5;
    const int lid = tid & 31;
    const int wr = wid >> 1;
    const int wc = wid & 1;

    // Barriers: FULL(s) = sbase+MB_OFF+s*8 (count 128, cp arrives);
    //           EMPTY(s) = sbase+MB_OFF+24+s*8 (count 4, warp arrives).
    const uint32_t MB = sbase + MB_OFF;
    if (tid == 0) {
#pragma unroll
        for (int s = 0; s < 3; s++) {
            mbar_init(MB + s * 8, 128);
            mbar_init(MB + 24 + s * 8, 4);
        }
    }
    __syncthreads();

    Frag4 f;
    frag4_setup(f, tid, (uint32_t)Ndim * 2);

    const char* Ab = (const char*)(g_Qh + ((size_t)bh * Tdim + bt * 128) * Ndim);
    const char* Bb = (const char*)(g_Qh + ((size_t)bh * Tdim + bs * 128) * Ndim);

    float acc[4][8][4];
#pragma unroll
    for (int i = 0; i < 4; i++)
#pragma unroll
        for (int j = 0; j < 8; j++)
#pragma unroll
            for (int k = 0; k < 4; k++) acc[i][j][k] = 0.f;

    const int NCH = 128;
    // Prologue: chunks 0,1 into stages 0,1.
#pragma unroll
    for (int c = 0; c < 2; c++) {
        uint32_t s0 = sbase + c * STG_SC;
        size_t kb = (size_t)c * 128;
#pragma unroll
        for (int r = 0; r < 8; r++) {
            cp16(s0 + f.sw[r],         Ab + f.gof[r] + kb);
            cp16(s0 + 16384 + f.sw[r], Bb + f.gof[r] + kb);
        }
        cp_arrive(MB + c * 8);
    }

    int s = 0, m = 0;  // c = 3*m + s
    for (int c = 0; c < NCH; c++) {
        mbar_wait(MB + s * 8, m & 1);  // full[s], parity (c/3)&1
        const uint32_t s0 = sbase + s * STG_SC;
        ks4_step(f, s0, s0 + 16384, 0, acc);

        const int p = c + 2;
        if (p < NCH) {
            int sp = s + 2;
            if (sp >= 3) sp -= 3;
            const int pdiv = m + (s >= 1 ? 1 : 0);  // p/3
            if (p >= 3) mbar_wait(MB + 24 + sp * 8, (pdiv - 1) & 1);
            const uint32_t spb = sbase + sp * STG_SC;
            const size_t kb = (size_t)p * 128;
            // ks1 + 6 lines
            cp16(spb + f.sw[0],         Ab + f.gof[0] + kb);
            cp16(spb + f.sw[1],         Ab + f.gof[1] + kb);
            cp16(spb + f.sw[2],         Ab + f.gof[2] + kb);
            cp16(spb + 16384 + f.sw[0], Bb + f.gof[0] + kb);
            cp16(spb + 16384 + f.sw[1], Bb + f.gof[1] + kb);
            cp16(spb + 16384 + f.sw[2], Bb + f.gof[2] + kb);
            ks4_step(f, s0, s0 + 16384, 32, acc);
            // ks2 + 6 lines
            cp16(spb + f.sw[3],         Ab + f.gof[3] + kb);
            cp16(spb + f.sw[4],         Ab + f.gof[4] + kb);
            cp16(spb + f.sw[5],         Ab + f.gof[5] + kb);
            cp16(spb + 16384 + f.sw[3], Bb + f.gof[3] + kb);
            cp16(spb + 16384 + f.sw[4], Bb + f.gof[4] + kb);
            cp16(spb + 16384 + f.sw[5], Bb + f.gof[5] + kb);
            ks4_step(f, s0, s0 + 16384, 64, acc);
            // ks3 + 4 lines + full arrive
            cp16(spb + f.sw[6],         Ab + f.gof[6] + kb);
            cp16(spb + f.sw[7],         Ab + f.gof[7] + kb);
            cp16(spb + 16384 + f.sw[6], Bb + f.gof[6] + kb);
            cp16(spb + 16384 + f.sw[7], Bb + f.gof[7] + kb);
            cp_arrive(MB + sp * 8);
            ks4_step(f, s0, s0 + 16384, 96, acc);
        } else {
            ks4_step(f, s0, s0 + 16384, 32, acc);
            ks4_step(f, s0, s0 + 16384, 64, acc);
            ks4_step(f, s0, s0 + 16384, 96, acc);
        }
        __syncwarp();
        if (lid == 0) mbar_arrive(MB + 24 + s * 8);  // empty[s]
        if (++s == 3) { s = 0; m++; }
    }

    // Epilogue: mask/stdp/gate; store fp32 + fp16.
    const float ssc = stdp_scale[0] * 0.01f;
    const int g0 = lid >> 2;
    const int tg = lid & 3;
#pragma unroll
    for (int mi = 0; mi < 4; mi++) {
#pragma unroll
        for (int half = 0; half < 2; half++) {
            const int t = bt * 128 + wr * 64 + mi * 16 + g0 + half * 8;
            const float g = g_gate[bh * Tdim + t];
            const float bco = g * ssc * __expf(-0.05f * (float)t);
            float* rowp = Sbase + (size_t)t * Tdim;
            __half* hrow = Shb + (size_t)t * Tdim;
#pragma unroll
            for (int ni = 0; ni < 8; ni++) {
                const int ss = bs * 128 + wc * 64 + ni * 8 + tg * 2;
                const float e0 = __expf(0.05f * (float)ss);
                float v0 = acc[mi][ni][half * 2 + 0];
                float v1 = acc[mi][ni][half * 2 + 1];
                float2 o;
                o.x = (t > ss)     ? v0 * fmaf(bco, e0, g) : 0.f;
                o.y = (t > ss + 1) ? v1 * fmaf(bco, e0 * 1.0512710963760241f, g)
                                   : 0.f;
                *(float2*)(rowp + ss) = o;
                __half2 h;
                h.x = __float2half(o.x);
                h.y = __float2half(o.y);
                *(__half2*)(hrow + ss) = h;
            }
        }
    }
}

// ===========================================================================
// GEMM2: 8 warps 2x4, warp 64x32, single product (unchanged).
// ===========================================================================
struct FragCtx {
    uint32_t a_off[4];
    uint32_t b_off[2];
    uint32_t sw[4];
    int row[4];
    int colb;
};

__device__ __forceinline__ void frag_setup(FragCtx& f, int tid) {
    const int lid = tid & 31;
    const int wid = tid >> 5;
    const int wr = wid >> 2;
    const int wc = wid & 3;
    const int a_row = wr * 64 + (lid & 15);
    const int a_kb = (lid >> 4) * 16;
#pragma unroll
    for (int mi = 0; mi < 4; mi++)
        f.a_off[mi] = swz((a_row + mi * 16) * 128 + a_kb);
    const int b_row = wc * 32 + (lid & 7) + ((lid >> 4) << 3);
    const int b_kb = ((lid >> 3) & 1) * 16;
#pragma unroll
    for (int nb = 0; nb < 2; nb++)
        f.b_off[nb] = swz((b_row + nb * 16) * 128 + b_kb);
    const int rbase = tid >> 3;
    f.colb = (tid & 7) * 16;
#pragma unroll
    for (int r = 0; r < 4; r++) {
        f.row[r] = rbase + 32 * r;
        f.sw[r] = swz(f.row[r] * 128 + f.colb);
    }
}

__device__ __forceinline__ void ks_step(const FragCtx& f, uint32_t s0,
                                        uint32_t bsm, uint32_t kx,
                                        float acc[4][4][4]) {
    uint32_t b0[4], b1[4];
    ldm_x4(b0, bsm + (f.b_off[0] ^ kx));
    ldm_x4(b1, bsm + (f.b_off[1] ^ kx));
    uint32_t a0[4], a1[4];
    ldm_x4(a0, s0 + (f.a_off[0] ^ kx));
    ldm_x4(a1, s0 + (f.a_off[1] ^ kx));
    mma16816(acc[0][0], a0, b0[0], b0[1]);
    mma16816(acc[0][1], a0, b0[2], b0[3]);
    mma16816(acc[0][2], a0, b1[0], b1[1]);
    mma16816(acc[0][3], a0, b1[2], b1[3]);
    ldm_x4(a0, s0 + (f.a_off[2] ^ kx));
    mma16816(acc[1][0], a1, b0[0], b0[1]);
    mma16816(acc[1][1], a1, b0[2], b0[3]);
    mma16816(acc[1][2], a1, b1[0], b1[1]);
    mma16816(acc[1][3], a1, b1[2], b1[3]);
    ldm_x4(a1, s0 + (f.a_off[3] ^ kx));
    mma16816(acc[2][0], a0, b0[0], b0[1]);
    mma16816(acc[2][1], a0, b0[2], b0[3]);
    mma16816(acc[2][2], a0, b1[0], b1[1]);
    mma16816(acc[2][3], a0, b1[2], b1[3]);
    mma16816(acc[3][0], a1, b0[0], b0[1]);
    mma16816(acc[3][1], a1, b0[2], b0[3]);
    mma16816(acc[3][2], a1, b1[0], b1[1]);
    mma16816(acc[3][3], a1, b1[2], b1[3]);
}

#define STG_OUT 32768
#define SMEM_OUT (3 * STG_OUT)

__global__ __launch_bounds__(256, 2) void out_tc_kernel(float* __restrict__ Out) {
    extern __shared__ char smem[];
    const int bh = blockIdx.z;
    const int b = bh / NHdim;
    const int bt = blockIdx.y;
    const int bd = blockIdx.x;

    const uint32_t sbase = smem_u32(smem);
    const int tid = threadIdx.x;
    const int wid = tid >> 5;
    const int lid = tid & 31;
    const int wr = wid >> 2;
    const int wc = wid & 3;

    FragCtx f;
    frag_setup(f, tid);

    const size_t rs = (size_t)Tdim * 2;
    const char* Ahb = (const char*)(g_Sh + ((size_t)bh * Tdim + bt * 128) * Tdim);
    const char* Bhb = (const char*)(g_VTh + ((size_t)b * Ddim + bd * 128) * Tdim);
    const char* pA[4];
    const char* pB[4];
#pragma unroll
    for (int r = 0; r < 4; r++) {
        pA[r] = Ahb + (size_t)f.row[r] * rs + f.colb;
        pB[r] = Bhb + (size_t)f.row[r] * rs + f.colb;
    }

    float acc[4][4][4];
#pragma unroll
    for (int i = 0; i < 4; i++)
#pragma unroll
        for (int j = 0; j < 4; j++)
#pragma unroll
            for (int k = 0; k < 4; k++) acc[i][j][k] = 0.f;

    const int NCH = (bt + 1) * 2;
#pragma unroll
    for (int c = 0; c < 2; c++) {
        uint32_t s0 = sbase + c * STG_OUT;
        size_t kb = (size_t)c * 128;
#pragma unroll
        for (int r = 0; r < 4; r++) {
            cp16(s0 + f.sw[r],         pA[r] + kb);
            cp16(s0 + 16384 + f.sw[r], pB[r] + kb);
        }
        asm volatile("cp.async.commit_group;" ::: "memory");
    }

    int st = 0, stp = 2;
    for (int i = 0; i < NCH; i++) {
        asm volatile("cp.async.wait_group 1;" ::: "memory");
        __syncthreads();
        const uint32_t s0 = sbase + st * STG_OUT;
        const bool pf = (i + 2 < NCH);
        const uint32_t sp = sbase + stp * STG_OUT;
        const size_t kb = (size_t)(i + 2) * 128;
#pragma unroll
        for (int ks = 0; ks < 4; ks++) {
            if (pf) {
                cp16(sp + f.sw[ks],         pA[ks] + kb);
                cp16(sp + 16384 + f.sw[ks], pB[ks] + kb);
            }
            ks_step(f, s0, s0 + 16384, ks * 32, acc);
        }
        asm volatile("cp.async.commit_group;" ::: "memory");
        st = (st == 2) ? 0 : st + 1;
        stp = (stp == 2) ? 0 : stp + 1;
    }

    const int g0 = lid >> 2;
    const int tg = lid & 3;
#pragma unroll
    for (int mi = 0; mi < 4; mi++) {
#pragma unroll
        for (int half = 0; half < 2; half++) {
            const int t = bt * 128 + wr * 64 + mi * 16 + g0 + half * 8;
            float* rowp = Out + ((size_t)bh * Tdim + t) * Ddim;
#pragma unroll
            for (int ni = 0; ni < 4; ni++) {
                const int d = bd * 128 + wc * 32 + ni * 8 + tg * 2;
                float2 o;
                o.x = acc[mi][ni][half * 2 + 0];
                o.y = acc[mi][ni][half * 2 + 1];
                *(float2*)(rowp + d) = o;
            }
        }
    }
}

// ---------------------------------------------------------------------------
extern "C" void kernel_launch(void* const* d_in, const int* in_sizes, int n_in,
                              void* d_out, int out_size) {
    const float* Q      = (const float*)d_in[0];
    const float* V      = (const float*)d_in[1];
    const float* traces = (const float*)d_in[2];
    const float* scale  = (const float*)d_in[3];
    float* out = (float*)d_out;

    const size_t OUT_ELEMS = (size_t)BHdim * Tdim * Ddim;
    const size_t SC_ELEMS  = (size_t)BHdim * Tdim * Tdim;

    float* scores;
    if ((size_t)out_size >= OUT_ELEMS + SC_ELEMS) {
        scores = out + OUT_ELEMS;
    } else {
        void* p = nullptr;
        cudaGetSymbolAddress(&p, g_S_fallback);
        scores = (float*)p;
    }

    static bool attr_set = false;
    if (!attr_set) {
        cudaFuncSetAttribute(scores_tc_kernel,
                             cudaFuncAttributeMaxDynamicSharedMemorySize,
                             SMEM_SC);
        cudaFuncSetAttribute(out_tc_kernel,
                             cudaFuncAttributeMaxDynamicSharedMemorySize,
                             SMEM_OUT);
        attr_set = true;
    }

    zero_upper_kernel<<<28 * BHdim, 256>>>(scores);

    const size_t nq = (size_t)BHdim * Tdim * (Ndim / 4);
    rope_kernel<<<(unsigned)((nq + 255) / 256), 256>>>(Q);
    gate_kernel<<<BHdim * Tdim, 32>>>(traces);
    dim3 gv(Tdim / 32, Ddim / 32, Bdim);
    vt_kernel<<<gv, dim3(32, 8)>>>(V);

    scores_tc_kernel<<<36 * BHdim, 128, SMEM_SC>>>(scores, scale);

    dim3 g2(Ddim / 128, Tdim / 128, BHdim);
    out_tc_kernel<<<g2, 256, SMEM_OUT>>>(out);
}